// round 2
// baseline (speedup 1.0000x reference)
#include <cuda_runtime.h>
#include <cuda_bf16.h>
#include <math.h>
#include <stdint.h>

// ---------------- problem constants ----------------
// B=32, N=64, T=50, WD=200, H=S=128, C=8
#define BN   2048            // B*N
#define TSEQ 50
#define WD   200
#define NSEQ 64              // tag sequence length (N)
#define BB   32              // tag batch (B)

// ---------------- device scratch ----------------
__device__ float g_xp0[(size_t)TSEQ * BN * 512];   // sentence inproj fwd [t][p][512]
__device__ float g_xp1[(size_t)TSEQ * BN * 512];   // sentence inproj bwd [t][p][512]
__device__ float g_hbuf[2][2 * BN * 128];          // double-buffered h [buf][dir][p][128]
__device__ float g_cst[2 * BN * 128];              // c state [dir][p][128]
__device__ float g_hsum[2 * BN * 128];             // sum_t h  [dir][p][128]
__device__ float g_sentpres[(size_t)BN * 256];     // [p][256]
__device__ float g_txp0[(size_t)NSEQ * BB * 512];  // tag inproj fwd [n][b][512]
__device__ float g_txp1[(size_t)NSEQ * BB * 512];
__device__ float g_thbuf[2][2 * BB * 128];
__device__ float g_tcst[2 * BB * 128];
__device__ float g_tag_out[(size_t)BN * 256];      // [p][256] tanh'ed
__device__ float g_q[(size_t)BN * 256];
__device__ float g_k[(size_t)BN * 256];
__device__ float g_sentFt[(size_t)BN * 15];
__device__ float g_roleFt[(size_t)BN * 15];
__device__ float g_agg[(size_t)BN * 256];

// ---------------- math helpers ----------------
__device__ __forceinline__ float sigf(float x) {
    return 1.0f / (1.0f + expf(-x));
}

// ============================================================
// Generic dual-half GEMM:  C[m][h*NB+g] = A[m][:K] . B_h[g][:K] + bias_h[g]
// BM=BN=128, BK=8, 256 threads, 8x8 micro-tile.
// MODE: 0 sent-inproj (A=param docs, out g_xp)        M=102400 K=200 NB=512
//       1 tag-inproj  (A=g_sentpres, out g_txp)       M=2048   K=256 NB=512
//       2 spp-sent    (A=g_sentpres, out g_q/g_k)     M=2048   K=256 NB=256
//       3 spp-role    (A=g_tag_out,  out g_q/g_k)     M=2048   K=256 NB=256
//       4 gcn-out     (A=g_agg, out=param, relu)      M=2048   K=256 NB=256 (grid.y=2)
// ============================================================
template <int MODE>
__global__ void __launch_bounds__(256) gemm_dual(
    const float* __restrict__ Aparam, int M, int K, int NB,
    const float* __restrict__ B0, const float* __restrict__ B1,
    const float* __restrict__ bias0, const float* __restrict__ bias1,
    float* __restrict__ outParam)
{
    __shared__ float As[8][128];
    __shared__ float Bs[8][128];

    const float* A;
    if (MODE == 0) A = Aparam;
    else if (MODE == 1 || MODE == 2) A = g_sentpres;
    else if (MODE == 3) A = g_tag_out;
    else A = g_agg;

    int hsel = (blockIdx.y * 128) / NB;
    int g0 = blockIdx.y * 128 - hsel * NB;
    int m0 = blockIdx.x * 128;

    const float* B = hsel ? B1 : B0;
    const float* bias = hsel ? bias1 : bias0;

    float* out;
    if (MODE == 0) out = hsel ? g_xp1 : g_xp0;
    else if (MODE == 1) out = hsel ? g_txp1 : g_txp0;
    else if (MODE == 2 || MODE == 3) out = hsel ? g_k : g_q;
    else out = outParam;

    int tid = threadIdx.x;
    int tx = tid & 15;        // 0..15 -> output cols tx*8..
    int ty = tid >> 4;        // 0..15 -> output rows ty*8..
    int lr = tid >> 1;        // load row 0..127
    int lc4 = tid & 1;        // load col-quad 0..1

    float acc[8][8];
#pragma unroll
    for (int i = 0; i < 8; i++)
#pragma unroll
        for (int j = 0; j < 8; j++) acc[i][j] = 0.0f;

    int KT = K / 8;
    for (int kt = 0; kt < KT; kt++) {
        float4 av = *(const float4*)(A + (size_t)(m0 + lr) * K + kt * 8 + lc4 * 4);
        float4 bv = *(const float4*)(B + (size_t)(g0 + lr) * K + kt * 8 + lc4 * 4);
        As[lc4 * 4 + 0][lr] = av.x; As[lc4 * 4 + 1][lr] = av.y;
        As[lc4 * 4 + 2][lr] = av.z; As[lc4 * 4 + 3][lr] = av.w;
        Bs[lc4 * 4 + 0][lr] = bv.x; Bs[lc4 * 4 + 1][lr] = bv.y;
        Bs[lc4 * 4 + 2][lr] = bv.z; Bs[lc4 * 4 + 3][lr] = bv.w;
        __syncthreads();
#pragma unroll
        for (int kk = 0; kk < 8; kk++) {
            float4 a0 = *(const float4*)&As[kk][ty * 8];
            float4 a1 = *(const float4*)&As[kk][ty * 8 + 4];
            float4 b0 = *(const float4*)&Bs[kk][tx * 8];
            float4 b1 = *(const float4*)&Bs[kk][tx * 8 + 4];
            float a[8] = {a0.x, a0.y, a0.z, a0.w, a1.x, a1.y, a1.z, a1.w};
            float b[8] = {b0.x, b0.y, b0.z, b0.w, b1.x, b1.y, b1.z, b1.w};
#pragma unroll
            for (int i = 0; i < 8; i++)
#pragma unroll
                for (int j = 0; j < 8; j++) acc[i][j] += a[i] * b[j];
        }
        __syncthreads();
    }

#pragma unroll
    for (int i = 0; i < 8; i++) {
        int m = m0 + ty * 8 + i;
        size_t rowbase;
        if (MODE == 0) {
            int p = m / 50; int t = m - p * 50;
            rowbase = ((size_t)t * BN + p) * 512;
        } else if (MODE == 1) {
            int b = m >> 6; int n = m & 63;
            rowbase = ((size_t)n * BB + b) * 512;
        } else {
            rowbase = (size_t)m * 256;
        }
#pragma unroll
        for (int j = 0; j < 8; j++) {
            int g = g0 + tx * 8 + j;
            float v = acc[i][j] + bias[g];
            if (MODE == 4) v = fmaxf(v, 0.0f);
            out[rowbase + g] = v;
        }
    }
}

// ============================================================
// Fused LSTM step: gates = xp[t] + h_in @ W_hh^T, then state update.
// Block covers 32 rows (p) x 32 hidden cols (j) across all 4 gates.
// grid = (M/32, 4, 2dirs), 256 threads.
// SENT=true : M=2048, T=50, accumulates g_hsum.
// SENT=false: M=32,   T=64, writes tanh(h) into g_tag_out at the
//             forward (n=s) / time-reversed (n=T-1-s) position.
// ============================================================
template <int M, bool SENT>
__global__ void __launch_bounds__(256) lstm_step(
    const float* __restrict__ W0, const float* __restrict__ W1, int s)
{
    const int T = SENT ? TSEQ : NSEQ;
    int dir = blockIdx.z;
    int j0 = blockIdx.y * 32;
    int p0 = blockIdx.x * 32;
    int t = (dir == 0) ? s : (T - 1 - s);
    const float* W = (dir == 0) ? W0 : W1;
    const float* xp = SENT ? ((dir == 0) ? g_xp0 : g_xp1)
                           : ((dir == 0) ? g_txp0 : g_txp1);
    const float* hIn = (SENT ? g_hbuf[s & 1] : g_thbuf[s & 1]) + (size_t)dir * M * 128;
    float* hOut = (SENT ? g_hbuf[(s + 1) & 1] : g_thbuf[(s + 1) & 1]) + (size_t)dir * M * 128;
    float* cD = (SENT ? g_cst : g_tcst) + (size_t)dir * M * 128;

    __shared__ float hs[32][128];
    __shared__ float Ws[128][33];

    int tid = threadIdx.x;
    int jj = tid & 31;        // hidden-col lane
    int pg = tid >> 5;        // 0..7, each owns 4 p's
    float acc[4][4];          // [pp][gate]
#pragma unroll
    for (int a = 0; a < 4; a++)
#pragma unroll
        for (int b = 0; b < 4; b++) acc[a][b] = 0.0f;

    if (s > 0) {
        for (int i = tid; i < 32 * 32; i += 256) {
            int r = i >> 5, c4 = i & 31;
            *(float4*)&hs[r][c4 * 4] =
                *(const float4*)(hIn + (size_t)(p0 + r) * 128 + c4 * 4);
        }
        for (int kc = 0; kc < 4; kc++) {
            __syncthreads();
            int k0 = kc * 32;
            for (int i = tid; i < 128 * 32; i += 256) {
                int r = i >> 5, cc = i & 31;
                int grow = (r >> 5) * 128 + j0 + (r & 31);   // gate*128 + j
                Ws[r][cc] = W[(size_t)grow * 128 + k0 + cc];
            }
            __syncthreads();
#pragma unroll 8
            for (int kk = 0; kk < 32; kk++) {
                float a0 = hs[pg * 4 + 0][k0 + kk];
                float a1 = hs[pg * 4 + 1][k0 + kk];
                float a2 = hs[pg * 4 + 2][k0 + kk];
                float a3 = hs[pg * 4 + 3][k0 + kk];
                float w0 = Ws[jj][kk];
                float w1 = Ws[32 + jj][kk];
                float w2 = Ws[64 + jj][kk];
                float w3 = Ws[96 + jj][kk];
                acc[0][0] += a0 * w0; acc[0][1] += a0 * w1; acc[0][2] += a0 * w2; acc[0][3] += a0 * w3;
                acc[1][0] += a1 * w0; acc[1][1] += a1 * w1; acc[1][2] += a1 * w2; acc[1][3] += a1 * w3;
                acc[2][0] += a2 * w0; acc[2][1] += a2 * w1; acc[2][2] += a2 * w2; acc[2][3] += a2 * w3;
                acc[3][0] += a3 * w0; acc[3][1] += a3 * w1; acc[3][2] += a3 * w2; acc[3][3] += a3 * w3;
            }
        }
    }

    size_t xbase = (size_t)t * M * 512;
    int j = j0 + jj;
#pragma unroll
    for (int pp = 0; pp < 4; pp++) {
        int p = p0 + pg * 4 + pp;
        size_t xrow = xbase + (size_t)p * 512;
        float iv = acc[pp][0] + xp[xrow + j];
        float fv = acc[pp][1] + xp[xrow + 128 + j];
        float gv = acc[pp][2] + xp[xrow + 256 + j];
        float ov = acc[pp][3] + xp[xrow + 384 + j];
        size_t hidx = (size_t)p * 128 + j;
        float cold = (s == 0) ? 0.0f : cD[hidx];
        float cn = sigf(fv) * cold + sigf(iv) * tanhf(gv);
        float hn = sigf(ov) * tanhf(cn);
        cD[hidx] = cn;
        hOut[hidx] = hn;
        if (SENT) {
            float* hp = g_hsum + (size_t)dir * M * 128 + hidx;
            *hp = (s == 0) ? hn : (*hp + hn);
        } else {
            // p is the batch index b here; n = t
            g_tag_out[((size_t)p * NSEQ + t) * 256 + dir * 128 + j] = tanhf(hn);
        }
    }
}

// ---------------- sentpres = tanh(mean_t h) ----------------
__global__ void sentpres_kernel() {
    int i = blockIdx.x * 256 + threadIdx.x;     // 2048*256 total
    int p = i >> 8;
    int j = i & 255;
    int dir = j >> 7;
    int jj = j & 127;
    float v = g_hsum[((size_t)dir * BN + p) * 128 + jj] * (1.0f / 50.0f);
    g_sentpres[i] = tanhf(v);
}

// ---------------- SPP: att = q k^T / 16, pyramid max pool -> 15 ----------------
__global__ void __launch_bounds__(256) spp_kernel(int which) {
    int b = blockIdx.x;               // 32 batches
    int tid = threadIdx.x;
    __shared__ float qs[64][33];
    __shared__ float ks[64][33];
    __shared__ float segs[64][8];

    float acc[16];
#pragma unroll
    for (int i = 0; i < 16; i++) acc[i] = 0.0f;
    int n = tid >> 2;
    int mBase = (tid & 3) * 16;

    for (int d0 = 0; d0 < 256; d0 += 32) {
        __syncthreads();
        for (int idx = tid; idx < 64 * 32; idx += 256) {
            int r = idx >> 5, cc = idx & 31;
            size_t gi = ((size_t)(b * 64 + r)) * 256 + d0 + cc;
            qs[r][cc] = g_q[gi];
            ks[r][cc] = g_k[gi];
        }
        __syncthreads();
#pragma unroll 4
        for (int dd = 0; dd < 32; dd++) {
            float qv = qs[n][dd];
#pragma unroll
            for (int mm = 0; mm < 16; mm++)
                acc[mm] += qv * ks[mBase + mm][dd];
        }
    }
    // two 8-wide segment maxes (scale by 1/sqrt(256) = 1/16)
    float s8a = -3.4e38f, s8b = -3.4e38f;
#pragma unroll
    for (int mm = 0; mm < 8; mm++)  s8a = fmaxf(s8a, acc[mm]);
#pragma unroll
    for (int mm = 8; mm < 16; mm++) s8b = fmaxf(s8b, acc[mm]);
    segs[n][(tid & 3) * 2 + 0] = s8a * 0.0625f;
    segs[n][(tid & 3) * 2 + 1] = s8b * 0.0625f;
    __syncthreads();

    if (tid < 64) {
        float e[8];
#pragma unroll
        for (int i = 0; i < 8; i++) e[i] = segs[tid][i];
        float q4[4], h2[2];
#pragma unroll
        for (int i = 0; i < 4; i++) q4[i] = fmaxf(e[2 * i], e[2 * i + 1]);
        h2[0] = fmaxf(q4[0], q4[1]);
        h2[1] = fmaxf(q4[2], q4[3]);
        float a1 = fmaxf(h2[0], h2[1]);
        float* o = (which ? g_roleFt : g_sentFt) + (size_t)(b * 64 + tid) * 15;
        o[0] = a1;
        o[1] = h2[0]; o[2] = h2[1];
#pragma unroll
        for (int i = 0; i < 4; i++) o[3 + i] = q4[i];
#pragma unroll
        for (int i = 0; i < 8; i++) o[7 + i] = e[i];
    }
}

// ---------------- GCN pre: cosine adjacency + aggregate -> g_agg ----------------
__global__ void __launch_bounds__(256) gcn_pre() {
    int b = blockIdx.x;
    int tid = threadIdx.x;
    __shared__ float cosm[64][65];
    __shared__ float xs[64][33];
    __shared__ float inv[64];

    if (tid < 64) {
        const float* xr = g_tag_out + (size_t)(b * 64 + tid) * 256;
        float s = 0.0f;
        for (int d = 0; d < 256; d++) { float v = xr[d]; s += v * v; }
        inv[tid] = 1.0f / (sqrtf(s) + 1e-8f);
    }

    float acc[16];
#pragma unroll
    for (int i = 0; i < 16; i++) acc[i] = 0.0f;
    int n = tid >> 2;
    int mBase = (tid & 3) * 16;

    for (int d0 = 0; d0 < 256; d0 += 32) {
        __syncthreads();
        for (int idx = tid; idx < 64 * 32; idx += 256) {
            int r = idx >> 5, cc = idx & 31;
            xs[r][cc] = g_tag_out[((size_t)(b * 64 + r)) * 256 + d0 + cc];
        }
        __syncthreads();
#pragma unroll 4
        for (int dd = 0; dd < 32; dd++) {
            float xv = xs[n][dd];
#pragma unroll
            for (int mm = 0; mm < 16; mm++)
                acc[mm] += xv * xs[mBase + mm][dd];
        }
    }
#pragma unroll
    for (int mm = 0; mm < 16; mm++)
        cosm[n][mBase + mm] = acc[mm] * inv[n] * inv[mBase + mm];

    int ddBase = (tid & 3) * 8;
    for (int d0 = 0; d0 < 256; d0 += 32) {
        __syncthreads();   // also covers cosm stores on first iteration
        for (int idx = tid; idx < 64 * 32; idx += 256) {
            int r = idx >> 5, cc = idx & 31;
            xs[r][cc] = g_tag_out[((size_t)(b * 64 + r)) * 256 + d0 + cc];
        }
        __syncthreads();
        float r8[8];
#pragma unroll
        for (int i = 0; i < 8; i++) r8[i] = 0.0f;
        for (int m = 0; m < 64; m++) {
            float cv = cosm[n][m];
#pragma unroll
            for (int i = 0; i < 8; i++) r8[i] += cv * xs[m][ddBase + i];
        }
#pragma unroll
        for (int i = 0; i < 8; i++) {
            float v = (r8[i] + 2.0f * xs[n][ddBase + i]) * (1.0f / 66.0f);
            g_agg[(size_t)(b * 64 + n) * 256 + d0 + ddBase + i] = v;
        }
    }
}

// ---------------- classifier + log_softmax ----------------
__global__ void __launch_bounds__(256) cls_kernel(
    const float* __restrict__ W, const float* __restrict__ bias,
    float* __restrict__ out)
{
    __shared__ float Wsh[8][288];     // 286 used
    __shared__ float bsh[8];
    __shared__ float ftile[256][33];

    int tid = threadIdx.x;
    for (int i = tid; i < 8 * 286; i += 256) Wsh[i / 286][i % 286] = W[i];
    if (tid < 8) bsh[tid] = bias[tid];
    __syncthreads();

    int p0 = blockIdx.x * 256;
    int p = p0 + tid;
    float z[8];
#pragma unroll
    for (int c = 0; c < 8; c++) z[c] = bsh[c];

    for (int d0 = 0; d0 < 256; d0 += 32) {
        __syncthreads();
        for (int idx = tid; idx < 256 * 32; idx += 256) {
            int r = idx >> 5, cc = idx & 31;
            ftile[r][cc] = g_tag_out[(size_t)(p0 + r) * 256 + d0 + cc];
        }
        __syncthreads();
#pragma unroll 4
        for (int dd = 0; dd < 32; dd++) {
            float f = ftile[tid][dd];
#pragma unroll
            for (int c = 0; c < 8; c++) z[c] += f * Wsh[c][d0 + dd];
        }
    }
#pragma unroll
    for (int d = 0; d < 15; d++) {
        float f = g_sentFt[(size_t)p * 15 + d];
#pragma unroll
        for (int c = 0; c < 8; c++) z[c] += f * Wsh[c][256 + d];
    }
#pragma unroll
    for (int d = 0; d < 15; d++) {
        float f = g_roleFt[(size_t)p * 15 + d];
#pragma unroll
        for (int c = 0; c < 8; c++) z[c] += f * Wsh[c][271 + d];
    }
    float m = z[0];
#pragma unroll
    for (int c = 1; c < 8; c++) m = fmaxf(m, z[c]);
    float se = 0.0f;
#pragma unroll
    for (int c = 0; c < 8; c++) se += expf(z[c] - m);
    float lse = m + logf(se);
#pragma unroll
    for (int c = 0; c < 8; c++) out[(size_t)p * 8 + c] = z[c] - lse;
}

// ============================================================
extern "C" void kernel_launch(void* const* d_in, const int* in_sizes, int n_in,
                              void* d_out, int out_size)
{
    (void)in_sizes; (void)n_in; (void)out_size;
    const float* documents = (const float*)d_in[0];
    const float* sw_ih_f = (const float*)d_in[1];
    const float* sw_hh_f = (const float*)d_in[2];
    const float* sb_f    = (const float*)d_in[3];
    const float* sw_ih_b = (const float*)d_in[4];
    const float* sw_hh_b = (const float*)d_in[5];
    const float* sb_b    = (const float*)d_in[6];
    const float* sf_Wq   = (const float*)d_in[7];
    const float* sf_bq   = (const float*)d_in[8];
    const float* sf_Wk   = (const float*)d_in[9];
    const float* sf_bk   = (const float*)d_in[10];
    const float* rf_Wq   = (const float*)d_in[11];
    const float* rf_bq   = (const float*)d_in[12];
    const float* rf_Wk   = (const float*)d_in[13];
    const float* rf_bk   = (const float*)d_in[14];
    const float* tw_ih_f = (const float*)d_in[15];
    const float* tw_hh_f = (const float*)d_in[16];
    const float* tb_f    = (const float*)d_in[17];
    const float* tw_ih_b = (const float*)d_in[18];
    const float* tw_hh_b = (const float*)d_in[19];
    const float* tb_b    = (const float*)d_in[20];
    const float* sage_W  = (const float*)d_in[21];
    const float* sage_b  = (const float*)d_in[22];
    const float* cls_W   = (const float*)d_in[23];
    const float* cls_b   = (const float*)d_in[24];
    float* out = (float*)d_out;

    // 1) sentence BiLSTM input projection (both dirs): 102400 x 1024 x 200
    gemm_dual<0><<<dim3(800, 8), 256>>>(documents, 102400, 200, 512,
                                        sw_ih_f, sw_ih_b, sb_f, sb_b, nullptr);
    // 2) sentence recurrence, 50 steps
    for (int s = 0; s < TSEQ; s++)
        lstm_step<BN, true><<<dim3(64, 4, 2), 256>>>(sw_hh_f, sw_hh_b, s);
    // 3) sentpres = tanh(mean)
    sentpres_kernel<<<2048, 256>>>();
    // 4) tag BiLSTM input projection: 2048 x 1024 x 256
    gemm_dual<1><<<dim3(16, 8), 256>>>(nullptr, 2048, 256, 512,
                                       tw_ih_f, tw_ih_b, tb_f, tb_b, nullptr);
    // 5) tag recurrence, 64 steps (writes tanh(h) into g_tag_out)
    for (int s = 0; s < NSEQ; s++)
        lstm_step<BB, false><<<dim3(1, 4, 2), 256>>>(tw_hh_f, tw_hh_b, s);
    // 6) SPP on sentpres -> sentFt
    gemm_dual<2><<<dim3(16, 4), 256>>>(nullptr, 2048, 256, 256,
                                       sf_Wq, sf_Wk, sf_bq, sf_bk, nullptr);
    spp_kernel<<<32, 256>>>(0);
    // 7) SPP on tag_out -> roleFt
    gemm_dual<3><<<dim3(16, 4), 256>>>(nullptr, 2048, 256, 256,
                                       rf_Wq, rf_Wk, rf_bq, rf_bk, nullptr);
    spp_kernel<<<32, 256>>>(1);
    // 8) GCN: cosine aggregate, then relu(agg @ sage_W^T + b) -> d_out[16384:]
    gcn_pre<<<32, 256>>>();
    gemm_dual<4><<<dim3(16, 2), 256>>>(nullptr, 2048, 256, 256,
                                       sage_W, sage_W, sage_b, sage_b, out + 16384);
    // 9) classifier + log_softmax -> d_out[0:16384]
    cls_kernel<<<8, 256>>>(cls_W, cls_b, out);
}

// round 3
// speedup vs baseline: 1.0889x; 1.0889x over previous
#include <cuda_runtime.h>
#include <math.h>
#include <stdint.h>

typedef unsigned long long u64;

// ---------------- problem constants ----------------
#define BN   2048
#define TSEQ 50
#define NSEQ 64
#define BB   32

// ---------------- device scratch ----------------
__device__ float g_xp0[(size_t)TSEQ * BN * 512];
__device__ float g_xp1[(size_t)TSEQ * BN * 512];
__device__ float g_hbuf[2][2 * BN * 128];
__device__ float g_cst[2 * BN * 128];
__device__ float g_hsum[2 * BN * 128];
__device__ float g_sentpres[(size_t)BN * 256];
__device__ float g_txp0[(size_t)NSEQ * BB * 512];
__device__ float g_txp1[(size_t)NSEQ * BB * 512];
__device__ float g_thbuf[2][2 * BB * 128];
__device__ float g_tag_out[(size_t)BN * 256];
__device__ float g_q[(size_t)BN * 256];
__device__ float g_k[(size_t)BN * 256];
__device__ float g_sentFt[(size_t)BN * 15];
__device__ float g_roleFt[(size_t)BN * 15];
__device__ float g_agg[(size_t)BN * 256];
__device__ int g_tbar;
__device__ int g_tdone;

// ---------------- f32x2 helpers ----------------
__device__ __forceinline__ u64 pk2(float lo, float hi) {
    u64 r; asm("mov.b64 %0, {%1, %2};" : "=l"(r) : "f"(lo), "f"(hi)); return r;
}
__device__ __forceinline__ void up2(u64 v, float& lo, float& hi) {
    asm("mov.b64 {%0, %1}, %2;" : "=f"(lo), "=f"(hi) : "l"(v));
}
__device__ __forceinline__ void fma2(u64& d, u64 a, u64 b) {
    asm("fma.rn.f32x2 %0, %1, %2, %0;" : "+l"(d) : "l"(a), "l"(b));
}

// ---------------- fast math ----------------
__device__ __forceinline__ float sigf(float x) {
    x = fminf(fmaxf(x, -30.f), 30.f);
    return __fdividef(1.f, 1.f + __expf(-x));
}
__device__ __forceinline__ float tanhfast(float x) {
    x = fminf(fmaxf(x, -15.f), 15.f);
    return __fdividef(2.f, 1.f + __expf(-2.f * x)) - 1.f;
}

// ============================================================
// Dual-half GEMM with f32x2:  C[m][h*NB+g] = A[m][:K].B_h[g][:K] + bias_h[g]
// BM=BN=128, BK=8, 256 threads, 8 rows x 4 j-pairs per thread.
// MODE: 0 sent-inproj  M=102400 K=200 NB=512 -> g_xp{0,1}[t][p][g]
//       1 tag-inproj   M=2048   K=256 NB=512 -> g_txp{0,1}[n][b][g]
//       2 spp-sent     M=2048   K=256 NB=256 -> g_q/g_k
//       3 spp-role     M=2048   K=256 NB=256 -> g_q/g_k
//       4 gcn-out+relu M=2048   K=256 NB=256 -> outParam (grid.y=2)
// ============================================================
template <int MODE>
__global__ void __launch_bounds__(256) gemm_dual(
    const float* __restrict__ Aparam, int M, int K, int NB,
    const float* __restrict__ B0, const float* __restrict__ B1,
    const float* __restrict__ bias0, const float* __restrict__ bias1,
    float* __restrict__ outParam)
{
    __shared__ __align__(16) u64 As2[8][128];
    __shared__ __align__(16) float Bs[8][128];

    const float* A;
    if (MODE == 0) A = Aparam;
    else if (MODE == 1 || MODE == 2) A = g_sentpres;
    else if (MODE == 3) A = g_tag_out;
    else A = g_agg;

    int hsel = (blockIdx.y * 128) / NB;
    int g0 = blockIdx.y * 128 - hsel * NB;
    int m0 = blockIdx.x * 128;

    const float* B = hsel ? B1 : B0;
    const float* bias = hsel ? bias1 : bias0;

    float* out;
    if (MODE == 0) out = hsel ? g_xp1 : g_xp0;
    else if (MODE == 1) out = hsel ? g_txp1 : g_txp0;
    else if (MODE == 2 || MODE == 3) out = hsel ? g_k : g_q;
    else out = outParam;

    int tid = threadIdx.x;
    int tx = tid & 15;       // j-pair lane
    int ty = tid >> 4;       // row group
    int lr = tid >> 1;       // load row 0..127
    int lc4 = tid & 1;       // load quad 0..1

    u64 acc2[8][4];
#pragma unroll
    for (int i = 0; i < 8; i++)
#pragma unroll
        for (int j = 0; j < 4; j++) acc2[i][j] = 0ULL;

    int KT = K / 8;
    const float* aPtr = A + (size_t)(m0 + lr) * K + lc4 * 4;
    const float* bPtr = B + (size_t)(g0 + lr) * K + lc4 * 4;
    float4 av = *(const float4*)(aPtr);
    float4 bv = *(const float4*)(bPtr);

    for (int kt = 0; kt < KT; kt++) {
        As2[lc4 * 4 + 0][lr] = pk2(av.x, av.x);
        As2[lc4 * 4 + 1][lr] = pk2(av.y, av.y);
        As2[lc4 * 4 + 2][lr] = pk2(av.z, av.z);
        As2[lc4 * 4 + 3][lr] = pk2(av.w, av.w);
        Bs[lc4 * 4 + 0][lr] = bv.x; Bs[lc4 * 4 + 1][lr] = bv.y;
        Bs[lc4 * 4 + 2][lr] = bv.z; Bs[lc4 * 4 + 3][lr] = bv.w;
        __syncthreads();
        if (kt + 1 < KT) {
            av = *(const float4*)(aPtr + (kt + 1) * 8);
            bv = *(const float4*)(bPtr + (kt + 1) * 8);
        }
#pragma unroll
        for (int kk = 0; kk < 8; kk++) {
            u64 b2[4];
#pragma unroll
            for (int jq = 0; jq < 4; jq++)
                b2[jq] = *(const u64*)&Bs[kk][2 * (tx + 16 * jq)];
            u64 a2[8];
#pragma unroll
            for (int i = 0; i < 8; i++) a2[i] = As2[kk][ty * 8 + i];
#pragma unroll
            for (int i = 0; i < 8; i++)
#pragma unroll
                for (int jq = 0; jq < 4; jq++)
                    fma2(acc2[i][jq], a2[i], b2[jq]);
        }
        __syncthreads();
    }

#pragma unroll
    for (int i = 0; i < 8; i++) {
        int m = m0 + ty * 8 + i;
        size_t rowbase;
        if (MODE == 0) {
            int p = m / 50; int t = m - p * 50;
            rowbase = ((size_t)t * BN + p) * 512;
        } else if (MODE == 1) {
            int b = m >> 6; int n = m & 63;
            rowbase = ((size_t)n * BB + b) * 512;
        } else {
            rowbase = (size_t)m * 256;
        }
#pragma unroll
        for (int jq = 0; jq < 4; jq++) {
            int g = g0 + 2 * (tx + 16 * jq);
            float lo, hi;
            up2(acc2[i][jq], lo, hi);
            float2 bb = *(const float2*)(bias + g);
            float2 o;
            o.x = lo + bb.x;
            o.y = hi + bb.y;
            if (MODE == 4) { o.x = fmaxf(o.x, 0.f); o.y = fmaxf(o.y, 0.f); }
            *(float2*)(out + rowbase + g) = o;
        }
    }
}

// ============================================================
// Sentence LSTM step, f32x2 over even/odd k.
// Block: 64 p x 32 j x 4 gates, one dir. grid (32, 4, 2), 256 thr.
// Dynamic smem: hsf float[64][128] (32KB) + Wf u64[4][32][65] (65KB).
// ============================================================
__global__ void __launch_bounds__(256) lstm_sent(
    const float* __restrict__ W0, const float* __restrict__ W1, int s)
{
    extern __shared__ __align__(16) char sm[];
    float (*hsf)[128] = (float (*)[128])sm;                       // 64*128*4 = 32768
    u64 (*Wf)[32][65] = (u64 (*)[32][65])(sm + 64 * 128 * 4);     // 4*32*65*8 = 66560

    int dir = blockIdx.z;
    int j0 = blockIdx.y * 32;
    int p0 = blockIdx.x * 64;
    int t = dir ? (TSEQ - 1 - s) : s;
    const float* W = dir ? W1 : W0;
    const float* xp = dir ? g_xp1 : g_xp0;
    const float* hIn = g_hbuf[s & 1] + (size_t)dir * BN * 128;
    float* hOut = g_hbuf[(s + 1) & 1] + (size_t)dir * BN * 128;
    float* cD = g_cst + (size_t)dir * BN * 128;
    float* hsD = g_hsum + (size_t)dir * BN * 128;

    int tid = threadIdx.x;
    int jj = tid & 31;
    int pg = tid >> 5;      // 8 groups x 8 p

    u64 acc2[8][4];
#pragma unroll
    for (int a = 0; a < 8; a++)
#pragma unroll
        for (int b = 0; b < 4; b++) acc2[a][b] = 0ULL;

    if (s > 0) {
        // stage W slice as even/odd-k u64 pairs
        {
            int rowId = tid >> 1;
            int g = rowId >> 5, jr = rowId & 31;
            int half = tid & 1;
            const float* wrow = W + (size_t)(g * 128 + j0 + jr) * 128 + half * 64;
            u64* dst = &Wf[g][jr][half * 32];
#pragma unroll
            for (int q = 0; q < 16; q++) {
                float4 v = *(const float4*)(wrow + q * 4);
                dst[q * 2 + 0] = pk2(v.x, v.y);
                dst[q * 2 + 1] = pk2(v.z, v.w);
            }
        }
        // stage h
#pragma unroll
        for (int i = 0; i < 8; i++) {
            int idx = tid + i * 256;
            int r = idx >> 5, c4 = idx & 31;
            *(float4*)&hsf[r][c4 * 4] =
                *(const float4*)(hIn + (size_t)(p0 + r) * 128 + c4 * 4);
        }
        __syncthreads();

#pragma unroll 4
        for (int kp = 0; kp < 64; kp++) {
            u64 w0 = Wf[0][jj][kp];
            u64 w1 = Wf[1][jj][kp];
            u64 w2 = Wf[2][jj][kp];
            u64 w3 = Wf[3][jj][kp];
#pragma unroll
            for (int pp = 0; pp < 8; pp++) {
                u64 a2 = *(const u64*)&hsf[pg * 8 + pp][kp * 2];
                fma2(acc2[pp][0], a2, w0);
                fma2(acc2[pp][1], a2, w1);
                fma2(acc2[pp][2], a2, w2);
                fma2(acc2[pp][3], a2, w3);
            }
        }
    }

    size_t xbase = (size_t)t * BN * 512;
    int j = j0 + jj;
#pragma unroll
    for (int pp = 0; pp < 8; pp++) {
        int p = p0 + pg * 8 + pp;
        const float* xr = xp + xbase + (size_t)p * 512 + j;
        float lo, hi;
        up2(acc2[pp][0], lo, hi); float gi = lo + hi + xr[0];
        up2(acc2[pp][1], lo, hi); float gf = lo + hi + xr[128];
        up2(acc2[pp][2], lo, hi); float gg = lo + hi + xr[256];
        up2(acc2[pp][3], lo, hi); float go = lo + hi + xr[384];
        size_t hidx = (size_t)p * 128 + j;
        float cold = (s == 0) ? 0.0f : cD[hidx];
        float cn = sigf(gf) * cold + sigf(gi) * tanhfast(gg);
        float hn = sigf(go) * tanhfast(cn);
        cD[hidx] = cn;
        hOut[hidx] = hn;
        hsD[hidx] = (s == 0) ? hn : (hsD[hidx] + hn);
    }
}

// ============================================================
// Persistent tag BiLSTM: 8 co-resident blocks (2 dirs x 4 j-chunks),
// W cached in smem for all 64 steps, c in registers, global spin barrier.
// Dynamic smem: Wf u64[4][32][65] (65KB) + hsf float[32][128] (16KB).
// ============================================================
#define TAG_NBLK 8
__global__ void __launch_bounds__(256) tag_persistent(
    const float* __restrict__ W0, const float* __restrict__ W1)
{
    extern __shared__ __align__(16) char sm[];
    u64 (*Wf)[32][65] = (u64 (*)[32][65])sm;                      // 66560
    float (*hsf)[128] = (float (*)[128])(sm + 4 * 32 * 65 * 8);   // 16384

    int dir = blockIdx.x >> 2;
    int j0 = (blockIdx.x & 3) * 32;
    const float* W = dir ? W1 : W0;
    const float* xp = dir ? g_txp1 : g_txp0;
    int tid = threadIdx.x;
    int jj = tid & 31;
    int pg = tid >> 5;      // 8 groups x 4 b
    int j = j0 + jj;

    // stage W once
    {
        int rowId = tid >> 1;
        int g = rowId >> 5, jr = rowId & 31;
        int half = tid & 1;
        const float* wrow = W + (size_t)(g * 128 + j0 + jr) * 128 + half * 64;
        u64* dst = &Wf[g][jr][half * 32];
#pragma unroll
        for (int q = 0; q < 16; q++) {
            float4 v = *(const float4*)(wrow + q * 4);
            dst[q * 2 + 0] = pk2(v.x, v.y);
            dst[q * 2 + 1] = pk2(v.z, v.w);
        }
    }

    float creg[4] = {0.f, 0.f, 0.f, 0.f};

    for (int s = 0; s < NSEQ; s++) {
        int t = dir ? (NSEQ - 1 - s) : s;
        u64 acc2[4][4];
#pragma unroll
        for (int a = 0; a < 4; a++)
#pragma unroll
            for (int b = 0; b < 4; b++) acc2[a][b] = 0ULL;

        if (s > 0) {
            const float* hIn = g_thbuf[s & 1] + (size_t)dir * BB * 128;
#pragma unroll
            for (int i = 0; i < 4; i++) {
                int idx = tid + i * 256;
                int r = idx >> 5, c4 = idx & 31;
                *(float4*)&hsf[r][c4 * 4] =
                    *(const float4*)(hIn + (size_t)r * 128 + c4 * 4);
            }
            __syncthreads();
#pragma unroll 4
            for (int kp = 0; kp < 64; kp++) {
                u64 w0 = Wf[0][jj][kp];
                u64 w1 = Wf[1][jj][kp];
                u64 w2 = Wf[2][jj][kp];
                u64 w3 = Wf[3][jj][kp];
#pragma unroll
                for (int bb = 0; bb < 4; bb++) {
                    u64 a2 = *(const u64*)&hsf[pg * 4 + bb][kp * 2];
                    fma2(acc2[bb][0], a2, w0);
                    fma2(acc2[bb][1], a2, w1);
                    fma2(acc2[bb][2], a2, w2);
                    fma2(acc2[bb][3], a2, w3);
                }
            }
        }

        float* hOut = g_thbuf[(s + 1) & 1] + (size_t)dir * BB * 128;
#pragma unroll
        for (int bb = 0; bb < 4; bb++) {
            int b = pg * 4 + bb;
            const float* xr = xp + ((size_t)t * BB + b) * 512 + j;
            float lo, hi;
            up2(acc2[bb][0], lo, hi); float gi = lo + hi + xr[0];
            up2(acc2[bb][1], lo, hi); float gf = lo + hi + xr[128];
            up2(acc2[bb][2], lo, hi); float gg = lo + hi + xr[256];
            up2(acc2[bb][3], lo, hi); float go = lo + hi + xr[384];
            float cn = sigf(gf) * creg[bb] + sigf(gi) * tanhfast(gg);
            float hn = sigf(go) * tanhfast(cn);
            creg[bb] = cn;
            hOut[(size_t)b * 128 + j] = hn;
            g_tag_out[((size_t)b * NSEQ + t) * 256 + dir * 128 + j] = tanhfast(hn);
        }

        if (s < NSEQ - 1) {
            // grid barrier (CG-style): all h writes visible before next step reads
            __syncthreads();
            if (tid == 0) {
                __threadfence();
                atomicAdd(&g_tbar, 1);
                int target = TAG_NBLK * (s + 1);
                while (*(volatile int*)&g_tbar < target) { }
                __threadfence();
            }
            __syncthreads();
        }
    }

    // deterministic counter reset for the next graph replay
    __syncthreads();
    if (tid == 0) {
        int old = atomicAdd(&g_tdone, 1);
        if (old == TAG_NBLK - 1) {
            g_tbar = 0;
            __threadfence();
            g_tdone = 0;
        }
    }
}

// ---------------- sentpres = tanh(mean_t h) ----------------
__global__ void sentpres_kernel() {
    int i = blockIdx.x * 256 + threadIdx.x;
    int p = i >> 8;
    int j = i & 255;
    int dir = j >> 7;
    int jj = j & 127;
    float v = g_hsum[((size_t)dir * BN + p) * 128 + jj] * (1.0f / 50.0f);
    g_sentpres[i] = tanhfast(v);
}

// ---------------- SPP ----------------
__global__ void __launch_bounds__(256) spp_kernel(int which) {
    int b = blockIdx.x;
    int tid = threadIdx.x;
    __shared__ float qs[64][33];
    __shared__ float ks[64][33];
    __shared__ float segs[64][8];

    float acc[16];
#pragma unroll
    for (int i = 0; i < 16; i++) acc[i] = 0.0f;
    int n = tid >> 2;
    int mBase = (tid & 3) * 16;

    for (int d0 = 0; d0 < 256; d0 += 32) {
        __syncthreads();
        for (int idx = tid; idx < 64 * 32; idx += 256) {
            int r = idx >> 5, cc = idx & 31;
            size_t gi = ((size_t)(b * 64 + r)) * 256 + d0 + cc;
            qs[r][cc] = g_q[gi];
            ks[r][cc] = g_k[gi];
        }
        __syncthreads();
#pragma unroll 4
        for (int dd = 0; dd < 32; dd++) {
            float qv = qs[n][dd];
#pragma unroll
            for (int mm = 0; mm < 16; mm++)
                acc[mm] += qv * ks[mBase + mm][dd];
        }
    }
    float s8a = -3.4e38f, s8b = -3.4e38f;
#pragma unroll
    for (int mm = 0; mm < 8; mm++)  s8a = fmaxf(s8a, acc[mm]);
#pragma unroll
    for (int mm = 8; mm < 16; mm++) s8b = fmaxf(s8b, acc[mm]);
    segs[n][(tid & 3) * 2 + 0] = s8a * 0.0625f;
    segs[n][(tid & 3) * 2 + 1] = s8b * 0.0625f;
    __syncthreads();

    if (tid < 64) {
        float e[8];
#pragma unroll
        for (int i = 0; i < 8; i++) e[i] = segs[tid][i];
        float q4[4], h2[2];
#pragma unroll
        for (int i = 0; i < 4; i++) q4[i] = fmaxf(e[2 * i], e[2 * i + 1]);
        h2[0] = fmaxf(q4[0], q4[1]);
        h2[1] = fmaxf(q4[2], q4[3]);
        float a1 = fmaxf(h2[0], h2[1]);
        float* o = (which ? g_roleFt : g_sentFt) + (size_t)(b * 64 + tid) * 15;
        o[0] = a1;
        o[1] = h2[0]; o[2] = h2[1];
#pragma unroll
        for (int i = 0; i < 4; i++) o[3 + i] = q4[i];
#pragma unroll
        for (int i = 0; i < 8; i++) o[7 + i] = e[i];
    }
}

// ---------------- GCN pre ----------------
__global__ void __launch_bounds__(256) gcn_pre() {
    int b = blockIdx.x;
    int tid = threadIdx.x;
    __shared__ float cosm[64][65];
    __shared__ float xs[64][33];
    __shared__ float inv[64];

    if (tid < 64) {
        const float* xr = g_tag_out + (size_t)(b * 64 + tid) * 256;
        float s = 0.0f;
        for (int d = 0; d < 256; d++) { float v = xr[d]; s += v * v; }
        inv[tid] = 1.0f / (sqrtf(s) + 1e-8f);
    }

    float acc[16];
#pragma unroll
    for (int i = 0; i < 16; i++) acc[i] = 0.0f;
    int n = tid >> 2;
    int mBase = (tid & 3) * 16;

    for (int d0 = 0; d0 < 256; d0 += 32) {
        __syncthreads();
        for (int idx = tid; idx < 64 * 32; idx += 256) {
            int r = idx >> 5, cc = idx & 31;
            xs[r][cc] = g_tag_out[((size_t)(b * 64 + r)) * 256 + d0 + cc];
        }
        __syncthreads();
#pragma unroll 4
        for (int dd = 0; dd < 32; dd++) {
            float xv = xs[n][dd];
#pragma unroll
            for (int mm = 0; mm < 16; mm++)
                acc[mm] += xv * xs[mBase + mm][dd];
        }
    }
#pragma unroll
    for (int mm = 0; mm < 16; mm++)
        cosm[n][mBase + mm] = acc[mm] * inv[n] * inv[mBase + mm];

    int ddBase = (tid & 3) * 8;
    for (int d0 = 0; d0 < 256; d0 += 32) {
        __syncthreads();
        for (int idx = tid; idx < 64 * 32; idx += 256) {
            int r = idx >> 5, cc = idx & 31;
            xs[r][cc] = g_tag_out[((size_t)(b * 64 + r)) * 256 + d0 + cc];
        }
        __syncthreads();
        float r8[8];
#pragma unroll
        for (int i = 0; i < 8; i++) r8[i] = 0.0f;
        for (int m = 0; m < 64; m++) {
            float cv = cosm[n][m];
#pragma unroll
            for (int i = 0; i < 8; i++) r8[i] += cv * xs[m][ddBase + i];
        }
#pragma unroll
        for (int i = 0; i < 8; i++) {
            float v = (r8[i] + 2.0f * xs[n][ddBase + i]) * (1.0f / 66.0f);
            g_agg[(size_t)(b * 64 + n) * 256 + d0 + ddBase + i] = v;
        }
    }
}

// ---------------- classifier + log_softmax ----------------
__global__ void __launch_bounds__(256) cls_kernel(
    const float* __restrict__ W, const float* __restrict__ bias,
    float* __restrict__ out)
{
    __shared__ float Wsh[8][288];
    __shared__ float bsh[8];
    __shared__ float ftile[256][33];

    int tid = threadIdx.x;
    for (int i = tid; i < 8 * 286; i += 256) Wsh[i / 286][i % 286] = W[i];
    if (tid < 8) bsh[tid] = bias[tid];
    __syncthreads();

    int p0 = blockIdx.x * 256;
    int p = p0 + tid;
    float z[8];
#pragma unroll
    for (int c = 0; c < 8; c++) z[c] = bsh[c];

    for (int d0 = 0; d0 < 256; d0 += 32) {
        __syncthreads();
        for (int idx = tid; idx < 256 * 32; idx += 256) {
            int r = idx >> 5, cc = idx & 31;
            ftile[r][cc] = g_tag_out[(size_t)(p0 + r) * 256 + d0 + cc];
        }
        __syncthreads();
#pragma unroll 4
        for (int dd = 0; dd < 32; dd++) {
            float f = ftile[tid][dd];
#pragma unroll
            for (int c = 0; c < 8; c++) z[c] += f * Wsh[c][d0 + dd];
        }
    }
#pragma unroll
    for (int d = 0; d < 15; d++) {
        float f = g_sentFt[(size_t)p * 15 + d];
#pragma unroll
        for (int c = 0; c < 8; c++) z[c] += f * Wsh[c][256 + d];
    }
#pragma unroll
    for (int d = 0; d < 15; d++) {
        float f = g_roleFt[(size_t)p * 15 + d];
#pragma unroll
        for (int c = 0; c < 8; c++) z[c] += f * Wsh[c][271 + d];
    }
    float m = z[0];
#pragma unroll
    for (int c = 1; c < 8; c++) m = fmaxf(m, z[c]);
    float se = 0.0f;
#pragma unroll
    for (int c = 0; c < 8; c++) se += expf(z[c] - m);
    float lse = m + logf(se);
#pragma unroll
    for (int c = 0; c < 8; c++) out[(size_t)p * 8 + c] = z[c] - lse;
}

// ============================================================
extern "C" void kernel_launch(void* const* d_in, const int* in_sizes, int n_in,
                              void* d_out, int out_size)
{
    (void)in_sizes; (void)n_in; (void)out_size;
    const float* documents = (const float*)d_in[0];
    const float* sw_ih_f = (const float*)d_in[1];
    const float* sw_hh_f = (const float*)d_in[2];
    const float* sb_f    = (const float*)d_in[3];
    const float* sw_ih_b = (const float*)d_in[4];
    const float* sw_hh_b = (const float*)d_in[5];
    const float* sb_b    = (const float*)d_in[6];
    const float* sf_Wq   = (const float*)d_in[7];
    const float* sf_bq   = (const float*)d_in[8];
    const float* sf_Wk   = (const float*)d_in[9];
    const float* sf_bk   = (const float*)d_in[10];
    const float* rf_Wq   = (const float*)d_in[11];
    const float* rf_bq   = (const float*)d_in[12];
    const float* rf_Wk   = (const float*)d_in[13];
    const float* rf_bk   = (const float*)d_in[14];
    const float* tw_ih_f = (const float*)d_in[15];
    const float* tw_hh_f = (const float*)d_in[16];
    const float* tb_f    = (const float*)d_in[17];
    const float* tw_ih_b = (const float*)d_in[18];
    const float* tw_hh_b = (const float*)d_in[19];
    const float* tb_b    = (const float*)d_in[20];
    const float* sage_W  = (const float*)d_in[21];
    const float* sage_b  = (const float*)d_in[22];
    const float* cls_W   = (const float*)d_in[23];
    const float* cls_b   = (const float*)d_in[24];
    float* out = (float*)d_out;

    const int SENT_SMEM = 64 * 128 * 4 + 4 * 32 * 65 * 8;   // 99328
    const int TAG_SMEM  = 4 * 32 * 65 * 8 + 32 * 128 * 4;   // 82944
    cudaFuncSetAttribute(lstm_sent, cudaFuncAttributeMaxDynamicSharedMemorySize, SENT_SMEM);
    cudaFuncSetAttribute(tag_persistent, cudaFuncAttributeMaxDynamicSharedMemorySize, TAG_SMEM);

    // 1) sentence BiLSTM input projection (both dirs): 102400 x 1024 x 200
    gemm_dual<0><<<dim3(800, 8), 256>>>(documents, 102400, 200, 512,
                                        sw_ih_f, sw_ih_b, sb_f, sb_b, nullptr);
    // 2) sentence recurrence, 50 steps
    for (int s = 0; s < TSEQ; s++)
        lstm_sent<<<dim3(32, 4, 2), 256, SENT_SMEM>>>(sw_hh_f, sw_hh_b, s);
    // 3) sentpres = tanh(mean)
    sentpres_kernel<<<2048, 256>>>();
    // 4) tag BiLSTM input projection: 2048 x 1024 x 256
    gemm_dual<1><<<dim3(16, 8), 256>>>(nullptr, 2048, 256, 512,
                                       tw_ih_f, tw_ih_b, tb_f, tb_b, nullptr);
    // 5) tag recurrence: single persistent kernel, 64 steps inside
    tag_persistent<<<TAG_NBLK, 256, TAG_SMEM>>>(tw_hh_f, tw_hh_b);
    // 6) SPP on sentpres -> sentFt
    gemm_dual<2><<<dim3(16, 4), 256>>>(nullptr, 2048, 256, 256,
                                       sf_Wq, sf_Wk, sf_bq, sf_bk, nullptr);
    spp_kernel<<<32, 256>>>(0);
    // 7) SPP on tag_out -> roleFt
    gemm_dual<3><<<dim3(16, 4), 256>>>(nullptr, 2048, 256, 256,
                                       rf_Wq, rf_Wk, rf_bq, rf_bk, nullptr);
    spp_kernel<<<32, 256>>>(1);
    // 8) GCN
    gcn_pre<<<32, 256>>>();
    gemm_dual<4><<<dim3(16, 2), 256>>>(nullptr, 2048, 256, 256,
                                       sage_W, sage_W, sage_b, sage_b, out + 16384);
    // 9) classifier + log_softmax
    cls_kernel<<<8, 256>>>(cls_W, cls_b, out);
}

// round 4
// speedup vs baseline: 1.0973x; 1.0077x over previous
#include <cuda_runtime.h>
#include <math.h>
#include <stdint.h>

typedef unsigned long long u64;

// ---------------- problem constants ----------------
#define BN   2048
#define TSEQ 50
#define NSEQ 64
#define BB   32

// ---------------- device scratch ----------------
__device__ float g_xp0[(size_t)TSEQ * BN * 512];
__device__ float g_xp1[(size_t)TSEQ * BN * 512];
__device__ float g_hbuf[2][2 * BN * 128];
__device__ float g_cst[2 * BN * 128];
__device__ float g_hsum[2 * BN * 128];
__device__ float g_sentpres[(size_t)BN * 256];
__device__ float g_txp0[(size_t)NSEQ * BB * 512];
__device__ float g_txp1[(size_t)NSEQ * BB * 512];
__device__ float g_thbuf[2][2 * BB * 128];
__device__ float g_tag_out[(size_t)BN * 256];
__device__ float g_q[(size_t)BN * 256];
__device__ float g_k[(size_t)BN * 256];
__device__ float g_sentFt[(size_t)BN * 15];
__device__ float g_roleFt[(size_t)BN * 15];
__device__ float g_agg[(size_t)BN * 256];
__device__ int g_tbar;
__device__ int g_tdone;

// ---------------- f32x2 helpers ----------------
__device__ __forceinline__ u64 pk2(float lo, float hi) {
    u64 r; asm("mov.b64 %0, {%1, %2};" : "=l"(r) : "f"(lo), "f"(hi)); return r;
}
__device__ __forceinline__ void up2(u64 v, float& lo, float& hi) {
    asm("mov.b64 {%0, %1}, %2;" : "=f"(lo), "=f"(hi) : "l"(v));
}
__device__ __forceinline__ void fma2(u64& d, u64 a, u64 b) {
    asm("fma.rn.f32x2 %0, %1, %2, %0;" : "+l"(d) : "l"(a), "l"(b));
}

// ---------------- fast math ----------------
__device__ __forceinline__ float sigf(float x) {
    x = fminf(fmaxf(x, -30.f), 30.f);
    return __fdividef(1.f, 1.f + __expf(-x));
}
__device__ __forceinline__ float tanhfast(float x) {
    x = fminf(fmaxf(x, -15.f), 15.f);
    return __fdividef(2.f, 1.f + __expf(-2.f * x)) - 1.f;
}

// ============================================================
// Dual-half GEMM with f32x2 (unchanged from R3)
// ============================================================
template <int MODE>
__global__ void __launch_bounds__(256) gemm_dual(
    const float* __restrict__ Aparam, int M, int K, int NB,
    const float* __restrict__ B0, const float* __restrict__ B1,
    const float* __restrict__ bias0, const float* __restrict__ bias1,
    float* __restrict__ outParam)
{
    __shared__ __align__(16) u64 As2[8][128];
    __shared__ __align__(16) float Bs[8][128];

    const float* A;
    if (MODE == 0) A = Aparam;
    else if (MODE == 1 || MODE == 2) A = g_sentpres;
    else if (MODE == 3) A = g_tag_out;
    else A = g_agg;

    int hsel = (blockIdx.y * 128) / NB;
    int g0 = blockIdx.y * 128 - hsel * NB;
    int m0 = blockIdx.x * 128;

    const float* B = hsel ? B1 : B0;
    const float* bias = hsel ? bias1 : bias0;

    float* out;
    if (MODE == 0) out = hsel ? g_xp1 : g_xp0;
    else if (MODE == 1) out = hsel ? g_txp1 : g_txp0;
    else if (MODE == 2 || MODE == 3) out = hsel ? g_k : g_q;
    else out = outParam;

    int tid = threadIdx.x;
    int tx = tid & 15;
    int ty = tid >> 4;
    int lr = tid >> 1;
    int lc4 = tid & 1;

    u64 acc2[8][4];
#pragma unroll
    for (int i = 0; i < 8; i++)
#pragma unroll
        for (int j = 0; j < 4; j++) acc2[i][j] = 0ULL;

    int KT = K / 8;
    const float* aPtr = A + (size_t)(m0 + lr) * K + lc4 * 4;
    const float* bPtr = B + (size_t)(g0 + lr) * K + lc4 * 4;
    float4 av = *(const float4*)(aPtr);
    float4 bv = *(const float4*)(bPtr);

    for (int kt = 0; kt < KT; kt++) {
        As2[lc4 * 4 + 0][lr] = pk2(av.x, av.x);
        As2[lc4 * 4 + 1][lr] = pk2(av.y, av.y);
        As2[lc4 * 4 + 2][lr] = pk2(av.z, av.z);
        As2[lc4 * 4 + 3][lr] = pk2(av.w, av.w);
        Bs[lc4 * 4 + 0][lr] = bv.x; Bs[lc4 * 4 + 1][lr] = bv.y;
        Bs[lc4 * 4 + 2][lr] = bv.z; Bs[lc4 * 4 + 3][lr] = bv.w;
        __syncthreads();
        if (kt + 1 < KT) {
            av = *(const float4*)(aPtr + (kt + 1) * 8);
            bv = *(const float4*)(bPtr + (kt + 1) * 8);
        }
#pragma unroll
        for (int kk = 0; kk < 8; kk++) {
            u64 b2[4];
#pragma unroll
            for (int jq = 0; jq < 4; jq++)
                b2[jq] = *(const u64*)&Bs[kk][2 * (tx + 16 * jq)];
            u64 a2[8];
#pragma unroll
            for (int i = 0; i < 8; i++) a2[i] = As2[kk][ty * 8 + i];
#pragma unroll
            for (int i = 0; i < 8; i++)
#pragma unroll
                for (int jq = 0; jq < 4; jq++)
                    fma2(acc2[i][jq], a2[i], b2[jq]);
        }
        __syncthreads();
    }

#pragma unroll
    for (int i = 0; i < 8; i++) {
        int m = m0 + ty * 8 + i;
        size_t rowbase;
        if (MODE == 0) {
            int p = m / 50; int t = m - p * 50;
            rowbase = ((size_t)t * BN + p) * 512;
        } else if (MODE == 1) {
            int b = m >> 6; int n = m & 63;
            rowbase = ((size_t)n * BB + b) * 512;
        } else {
            rowbase = (size_t)m * 256;
        }
#pragma unroll
        for (int jq = 0; jq < 4; jq++) {
            int g = g0 + 2 * (tx + 16 * jq);
            float lo, hi;
            up2(acc2[i][jq], lo, hi);
            float2 bb = *(const float2*)(bias + g);
            float2 o;
            o.x = lo + bb.x;
            o.y = hi + bb.y;
            if (MODE == 4) { o.x = fmaxf(o.x, 0.f); o.y = fmaxf(o.y, 0.f); }
            *(float2*)(out + rowbase + g) = o;
        }
    }
}

// ============================================================
// Sentence LSTM step v2: 64p x 16j x 4 gates per block.
// grid (32 pch, 8 jch, 2 dir), 256 threads, 2 blocks/SM.
// smem: Wp u64[4][16][66] (33792 B) + hp u64[64][66] (33792 B).
// h packed as k-pair u64 at staging; inner loop = ulonglong2 LDS only.
// Folds sentpres = tanh(hsum/50) at s==49.
// ============================================================
#define SENT2_WP   (4 * 16 * 66)
#define SENT2_SMEM ((SENT2_WP + 64 * 66) * 8)

__global__ void __launch_bounds__(256, 2) lstm_sent2(
    const float* __restrict__ W0, const float* __restrict__ W1, int s)
{
    extern __shared__ __align__(16) u64 sm2[];
    u64 (*Wp)[16][66] = (u64 (*)[16][66])sm2;
    u64 (*hp)[66] = (u64 (*)[66])(sm2 + SENT2_WP);

    int dir = blockIdx.z;
    int j0 = blockIdx.y * 16;
    int p0 = blockIdx.x * 64;
    int t = dir ? (TSEQ - 1 - s) : s;
    const float* W = dir ? W1 : W0;
    const float* xp = dir ? g_xp1 : g_xp0;
    const float* hIn = g_hbuf[s & 1] + (size_t)dir * BN * 128;
    float* hOut = g_hbuf[(s + 1) & 1] + (size_t)dir * BN * 128;
    float* cD = g_cst + (size_t)dir * BN * 128;
    float* hsD = g_hsum + (size_t)dir * BN * 128;

    int tid = threadIdx.x;
    int jj = tid & 15;        // j lane (0..15)
    int pg = tid >> 4;        // 0..15, each owns 4 p

    u64 acc2[4][4];
#pragma unroll
    for (int a = 0; a < 4; a++)
#pragma unroll
        for (int b = 0; b < 4; b++) acc2[a][b] = 0ULL;

    if (s > 0) {
        // stage W slice (4 gates x 16 j x 128 k) packed as k-pair u64
        {
            int row = tid >> 2;           // 0..63 = g*16+jr
            int g = row >> 4, jr = row & 15;
            int quarter = tid & 3;        // 32 k each
            const float* wrow = W + (size_t)(g * 128 + j0 + jr) * 128 + quarter * 32;
            u64* dst = &Wp[g][jr][quarter * 16];
#pragma unroll
            for (int q = 0; q < 8; q++) {
                float4 v = *(const float4*)(wrow + q * 4);
                dst[q * 2 + 0] = pk2(v.x, v.y);
                dst[q * 2 + 1] = pk2(v.z, v.w);
            }
        }
        // stage h (64 p x 128 k) packed as k-pair u64
        {
            int prow = tid >> 2;          // 0..63
            int quarter = tid & 3;
            const float* hrow = hIn + (size_t)(p0 + prow) * 128 + quarter * 32;
            u64* dst = &hp[prow][quarter * 16];
#pragma unroll
            for (int q = 0; q < 8; q++) {
                float4 v = *(const float4*)(hrow + q * 4);
                dst[q * 2 + 0] = pk2(v.x, v.y);
                dst[q * 2 + 1] = pk2(v.z, v.w);
            }
        }
        __syncthreads();

#pragma unroll 2
        for (int k4 = 0; k4 < 32; k4++) {
            ulonglong2 w0 = *(const ulonglong2*)&Wp[0][jj][k4 * 2];
            ulonglong2 w1 = *(const ulonglong2*)&Wp[1][jj][k4 * 2];
            ulonglong2 w2 = *(const ulonglong2*)&Wp[2][jj][k4 * 2];
            ulonglong2 w3 = *(const ulonglong2*)&Wp[3][jj][k4 * 2];
#pragma unroll
            for (int pp = 0; pp < 4; pp++) {
                ulonglong2 hv = *(const ulonglong2*)&hp[pg * 4 + pp][k4 * 2];
                fma2(acc2[pp][0], hv.x, w0.x); fma2(acc2[pp][0], hv.y, w0.y);
                fma2(acc2[pp][1], hv.x, w1.x); fma2(acc2[pp][1], hv.y, w1.y);
                fma2(acc2[pp][2], hv.x, w2.x); fma2(acc2[pp][2], hv.y, w2.y);
                fma2(acc2[pp][3], hv.x, w3.x); fma2(acc2[pp][3], hv.y, w3.y);
            }
        }
    }

    size_t xbase = (size_t)t * BN * 512;
    int j = j0 + jj;
#pragma unroll
    for (int pp = 0; pp < 4; pp++) {
        int p = p0 + pg * 4 + pp;
        const float* xr = xp + xbase + (size_t)p * 512 + j;
        float lo, hi;
        up2(acc2[pp][0], lo, hi); float gi = lo + hi + xr[0];
        up2(acc2[pp][1], lo, hi); float gf = lo + hi + xr[128];
        up2(acc2[pp][2], lo, hi); float gg = lo + hi + xr[256];
        up2(acc2[pp][3], lo, hi); float go = lo + hi + xr[384];
        size_t hidx = (size_t)p * 128 + j;
        float cold = (s == 0) ? 0.0f : cD[hidx];
        float cn = sigf(gf) * cold + sigf(gi) * tanhfast(gg);
        float hn = sigf(go) * tanhfast(cn);
        if (s == TSEQ - 1) {
            float hs = hsD[hidx] + hn;
            g_sentpres[(size_t)p * 256 + dir * 128 + j] = tanhfast(hs * (1.0f / 50.0f));
        } else {
            cD[hidx] = cn;
            hOut[hidx] = hn;
            hsD[hidx] = (s == 0) ? hn : (hsD[hidx] + hn);
        }
    }
}

// ============================================================
// Persistent tag BiLSTM (unchanged from R3)
// ============================================================
#define TAG_NBLK 8
__global__ void __launch_bounds__(256) tag_persistent(
    const float* __restrict__ W0, const float* __restrict__ W1)
{
    extern __shared__ __align__(16) char sm[];
    u64 (*Wf)[32][65] = (u64 (*)[32][65])sm;
    float (*hsf)[128] = (float (*)[128])(sm + 4 * 32 * 65 * 8);

    int dir = blockIdx.x >> 2;
    int j0 = (blockIdx.x & 3) * 32;
    const float* W = dir ? W1 : W0;
    const float* xp = dir ? g_txp1 : g_txp0;
    int tid = threadIdx.x;
    int jj = tid & 31;
    int pg = tid >> 5;
    int j = j0 + jj;

    {
        int rowId = tid >> 1;
        int g = rowId >> 5, jr = rowId & 31;
        int half = tid & 1;
        const float* wrow = W + (size_t)(g * 128 + j0 + jr) * 128 + half * 64;
        u64* dst = &Wf[g][jr][half * 32];
#pragma unroll
        for (int q = 0; q < 16; q++) {
            float4 v = *(const float4*)(wrow + q * 4);
            dst[q * 2 + 0] = pk2(v.x, v.y);
            dst[q * 2 + 1] = pk2(v.z, v.w);
        }
    }

    float creg[4] = {0.f, 0.f, 0.f, 0.f};

    for (int s = 0; s < NSEQ; s++) {
        int t = dir ? (NSEQ - 1 - s) : s;
        u64 acc2[4][4];
#pragma unroll
        for (int a = 0; a < 4; a++)
#pragma unroll
            for (int b = 0; b < 4; b++) acc2[a][b] = 0ULL;

        if (s > 0) {
            const float* hIn = g_thbuf[s & 1] + (size_t)dir * BB * 128;
#pragma unroll
            for (int i = 0; i < 4; i++) {
                int idx = tid + i * 256;
                int r = idx >> 5, c4 = idx & 31;
                *(float4*)&hsf[r][c4 * 4] =
                    *(const float4*)(hIn + (size_t)r * 128 + c4 * 4);
            }
            __syncthreads();
#pragma unroll 4
            for (int kp = 0; kp < 64; kp++) {
                u64 w0 = Wf[0][jj][kp];
                u64 w1 = Wf[1][jj][kp];
                u64 w2 = Wf[2][jj][kp];
                u64 w3 = Wf[3][jj][kp];
#pragma unroll
                for (int bb = 0; bb < 4; bb++) {
                    u64 a2 = *(const u64*)&hsf[pg * 4 + bb][kp * 2];
                    fma2(acc2[bb][0], a2, w0);
                    fma2(acc2[bb][1], a2, w1);
                    fma2(acc2[bb][2], a2, w2);
                    fma2(acc2[bb][3], a2, w3);
                }
            }
        }

        float* hOut = g_thbuf[(s + 1) & 1] + (size_t)dir * BB * 128;
#pragma unroll
        for (int bb = 0; bb < 4; bb++) {
            int b = pg * 4 + bb;
            const float* xr = xp + ((size_t)t * BB + b) * 512 + j;
            float lo, hi;
            up2(acc2[bb][0], lo, hi); float gi = lo + hi + xr[0];
            up2(acc2[bb][1], lo, hi); float gf = lo + hi + xr[128];
            up2(acc2[bb][2], lo, hi); float gg = lo + hi + xr[256];
            up2(acc2[bb][3], lo, hi); float go = lo + hi + xr[384];
            float cn = sigf(gf) * creg[bb] + sigf(gi) * tanhfast(gg);
            float hn = sigf(go) * tanhfast(cn);
            creg[bb] = cn;
            hOut[(size_t)b * 128 + j] = hn;
            g_tag_out[((size_t)b * NSEQ + t) * 256 + dir * 128 + j] = tanhfast(hn);
        }

        if (s < NSEQ - 1) {
            __syncthreads();
            if (tid == 0) {
                __threadfence();
                atomicAdd(&g_tbar, 1);
                int target = TAG_NBLK * (s + 1);
                while (*(volatile int*)&g_tbar < target) { }
                __threadfence();
            }
            __syncthreads();
        }
    }

    __syncthreads();
    if (tid == 0) {
        int old = atomicAdd(&g_tdone, 1);
        if (old == TAG_NBLK - 1) {
            g_tbar = 0;
            __threadfence();
            g_tdone = 0;
        }
    }
}

// ---------------- SPP ----------------
__global__ void __launch_bounds__(256) spp_kernel(int which) {
    int b = blockIdx.x;
    int tid = threadIdx.x;
    __shared__ float qs[64][33];
    __shared__ float ks[64][33];
    __shared__ float segs[64][8];

    float acc[16];
#pragma unroll
    for (int i = 0; i < 16; i++) acc[i] = 0.0f;
    int n = tid >> 2;
    int mBase = (tid & 3) * 16;

    for (int d0 = 0; d0 < 256; d0 += 32) {
        __syncthreads();
        for (int idx = tid; idx < 64 * 32; idx += 256) {
            int r = idx >> 5, cc = idx & 31;
            size_t gi = ((size_t)(b * 64 + r)) * 256 + d0 + cc;
            qs[r][cc] = g_q[gi];
            ks[r][cc] = g_k[gi];
        }
        __syncthreads();
#pragma unroll 4
        for (int dd = 0; dd < 32; dd++) {
            float qv = qs[n][dd];
#pragma unroll
            for (int mm = 0; mm < 16; mm++)
                acc[mm] += qv * ks[mBase + mm][dd];
        }
    }
    float s8a = -3.4e38f, s8b = -3.4e38f;
#pragma unroll
    for (int mm = 0; mm < 8; mm++)  s8a = fmaxf(s8a, acc[mm]);
#pragma unroll
    for (int mm = 8; mm < 16; mm++) s8b = fmaxf(s8b, acc[mm]);
    segs[n][(tid & 3) * 2 + 0] = s8a * 0.0625f;
    segs[n][(tid & 3) * 2 + 1] = s8b * 0.0625f;
    __syncthreads();

    if (tid < 64) {
        float e[8];
#pragma unroll
        for (int i = 0; i < 8; i++) e[i] = segs[tid][i];
        float q4[4], h2[2];
#pragma unroll
        for (int i = 0; i < 4; i++) q4[i] = fmaxf(e[2 * i], e[2 * i + 1]);
        h2[0] = fmaxf(q4[0], q4[1]);
        h2[1] = fmaxf(q4[2], q4[3]);
        float a1 = fmaxf(h2[0], h2[1]);
        float* o = (which ? g_roleFt : g_sentFt) + (size_t)(b * 64 + tid) * 15;
        o[0] = a1;
        o[1] = h2[0]; o[2] = h2[1];
#pragma unroll
        for (int i = 0; i < 4; i++) o[3 + i] = q4[i];
#pragma unroll
        for (int i = 0; i < 8; i++) o[7 + i] = e[i];
    }
}

// ---------------- GCN pre ----------------
__global__ void __launch_bounds__(256) gcn_pre() {
    int b = blockIdx.x;
    int tid = threadIdx.x;
    __shared__ float cosm[64][65];
    __shared__ float xs[64][33];
    __shared__ float inv[64];

    if (tid < 64) {
        const float* xr = g_tag_out + (size_t)(b * 64 + tid) * 256;
        float s = 0.0f;
        for (int d = 0; d < 256; d++) { float v = xr[d]; s += v * v; }
        inv[tid] = 1.0f / (sqrtf(s) + 1e-8f);
    }

    float acc[16];
#pragma unroll
    for (int i = 0; i < 16; i++) acc[i] = 0.0f;
    int n = tid >> 2;
    int mBase = (tid & 3) * 16;

    for (int d0 = 0; d0 < 256; d0 += 32) {
        __syncthreads();
        for (int idx = tid; idx < 64 * 32; idx += 256) {
            int r = idx >> 5, cc = idx & 31;
            xs[r][cc] = g_tag_out[((size_t)(b * 64 + r)) * 256 + d0 + cc];
        }
        __syncthreads();
#pragma unroll 4
        for (int dd = 0; dd < 32; dd++) {
            float xv = xs[n][dd];
#pragma unroll
            for (int mm = 0; mm < 16; mm++)
                acc[mm] += xv * xs[mBase + mm][dd];
        }
    }
#pragma unroll
    for (int mm = 0; mm < 16; mm++)
        cosm[n][mBase + mm] = acc[mm] * inv[n] * inv[mBase + mm];

    int ddBase = (tid & 3) * 8;
    for (int d0 = 0; d0 < 256; d0 += 32) {
        __syncthreads();
        for (int idx = tid; idx < 64 * 32; idx += 256) {
            int r = idx >> 5, cc = idx & 31;
            xs[r][cc] = g_tag_out[((size_t)(b * 64 + r)) * 256 + d0 + cc];
        }
        __syncthreads();
        float r8[8];
#pragma unroll
        for (int i = 0; i < 8; i++) r8[i] = 0.0f;
        for (int m = 0; m < 64; m++) {
            float cv = cosm[n][m];
#pragma unroll
            for (int i = 0; i < 8; i++) r8[i] += cv * xs[m][ddBase + i];
        }
#pragma unroll
        for (int i = 0; i < 8; i++) {
            float v = (r8[i] + 2.0f * xs[n][ddBase + i]) * (1.0f / 66.0f);
            g_agg[(size_t)(b * 64 + n) * 256 + d0 + ddBase + i] = v;
        }
    }
}

// ---------------- classifier + log_softmax ----------------
__global__ void __launch_bounds__(256) cls_kernel(
    const float* __restrict__ W, const float* __restrict__ bias,
    float* __restrict__ out)
{
    __shared__ float Wsh[8][288];
    __shared__ float bsh[8];
    __shared__ float ftile[256][33];

    int tid = threadIdx.x;
    for (int i = tid; i < 8 * 286; i += 256) Wsh[i / 286][i % 286] = W[i];
    if (tid < 8) bsh[tid] = bias[tid];
    __syncthreads();

    int p0 = blockIdx.x * 256;
    int p = p0 + tid;
    float z[8];
#pragma unroll
    for (int c = 0; c < 8; c++) z[c] = bsh[c];

    for (int d0 = 0; d0 < 256; d0 += 32) {
        __syncthreads();
        for (int idx = tid; idx < 256 * 32; idx += 256) {
            int r = idx >> 5, cc = idx & 31;
            ftile[r][cc] = g_tag_out[(size_t)(p0 + r) * 256 + d0 + cc];
        }
        __syncthreads();
#pragma unroll 4
        for (int dd = 0; dd < 32; dd++) {
            float f = ftile[tid][dd];
#pragma unroll
            for (int c = 0; c < 8; c++) z[c] += f * Wsh[c][d0 + dd];
        }
    }
#pragma unroll
    for (int d = 0; d < 15; d++) {
        float f = g_sentFt[(size_t)p * 15 + d];
#pragma unroll
        for (int c = 0; c < 8; c++) z[c] += f * Wsh[c][256 + d];
    }
#pragma unroll
    for (int d = 0; d < 15; d++) {
        float f = g_roleFt[(size_t)p * 15 + d];
#pragma unroll
        for (int c = 0; c < 8; c++) z[c] += f * Wsh[c][271 + d];
    }
    float m = z[0];
#pragma unroll
    for (int c = 1; c < 8; c++) m = fmaxf(m, z[c]);
    float se = 0.0f;
#pragma unroll
    for (int c = 0; c < 8; c++) se += expf(z[c] - m);
    float lse = m + logf(se);
#pragma unroll
    for (int c = 0; c < 8; c++) out[(size_t)p * 8 + c] = z[c] - lse;
}

// ============================================================
extern "C" void kernel_launch(void* const* d_in, const int* in_sizes, int n_in,
                              void* d_out, int out_size)
{
    (void)in_sizes; (void)n_in; (void)out_size;
    const float* documents = (const float*)d_in[0];
    const float* sw_ih_f = (const float*)d_in[1];
    const float* sw_hh_f = (const float*)d_in[2];
    const float* sb_f    = (const float*)d_in[3];
    const float* sw_ih_b = (const float*)d_in[4];
    const float* sw_hh_b = (const float*)d_in[5];
    const float* sb_b    = (const float*)d_in[6];
    const float* sf_Wq   = (const float*)d_in[7];
    const float* sf_bq   = (const float*)d_in[8];
    const float* sf_Wk   = (const float*)d_in[9];
    const float* sf_bk   = (const float*)d_in[10];
    const float* rf_Wq   = (const float*)d_in[11];
    const float* rf_bq   = (const float*)d_in[12];
    const float* rf_Wk   = (const float*)d_in[13];
    const float* rf_bk   = (const float*)d_in[14];
    const float* tw_ih_f = (const float*)d_in[15];
    const float* tw_hh_f = (const float*)d_in[16];
    const float* tb_f    = (const float*)d_in[17];
    const float* tw_ih_b = (const float*)d_in[18];
    const float* tw_hh_b = (const float*)d_in[19];
    const float* tb_b    = (const float*)d_in[20];
    const float* sage_W  = (const float*)d_in[21];
    const float* sage_b  = (const float*)d_in[22];
    const float* cls_W   = (const float*)d_in[23];
    const float* cls_b   = (const float*)d_in[24];
    float* out = (float*)d_out;

    const int TAG_SMEM = 4 * 32 * 65 * 8 + 32 * 128 * 4;   // 82944
    cudaFuncSetAttribute(lstm_sent2, cudaFuncAttributeMaxDynamicSharedMemorySize, SENT2_SMEM);
    cudaFuncSetAttribute(tag_persistent, cudaFuncAttributeMaxDynamicSharedMemorySize, TAG_SMEM);

    // 1) sentence BiLSTM input projection (both dirs): 102400 x 1024 x 200
    gemm_dual<0><<<dim3(800, 8), 256>>>(documents, 102400, 200, 512,
                                        sw_ih_f, sw_ih_b, sb_f, sb_b, nullptr);
    // 2) sentence recurrence, 50 steps (sentpres folded into s=49)
    for (int s = 0; s < TSEQ; s++)
        lstm_sent2<<<dim3(32, 8, 2), 256, SENT2_SMEM>>>(sw_hh_f, sw_hh_b, s);
    // 3) tag BiLSTM input projection: 2048 x 1024 x 256
    gemm_dual<1><<<dim3(16, 8), 256>>>(nullptr, 2048, 256, 512,
                                       tw_ih_f, tw_ih_b, tb_f, tb_b, nullptr);
    // 4) tag recurrence: persistent kernel
    tag_persistent<<<TAG_NBLK, 256, TAG_SMEM>>>(tw_hh_f, tw_hh_b);
    // 5) SPP on sentpres -> sentFt
    gemm_dual<2><<<dim3(16, 4), 256>>>(nullptr, 2048, 256, 256,
                                       sf_Wq, sf_Wk, sf_bq, sf_bk, nullptr);
    spp_kernel<<<32, 256>>>(0);
    // 6) SPP on tag_out -> roleFt
    gemm_dual<3><<<dim3(16, 4), 256>>>(nullptr, 2048, 256, 256,
                                       rf_Wq, rf_Wk, rf_bq, rf_bk, nullptr);
    spp_kernel<<<32, 256>>>(1);
    // 7) GCN
    gcn_pre<<<32, 256>>>();
    gemm_dual<4><<<dim3(16, 2), 256>>>(nullptr, 2048, 256, 256,
                                       sage_W, sage_W, sage_b, sage_b, out + 16384);
    // 8) classifier + log_softmax
    cls_kernel<<<8, 256>>>(cls_W, cls_b, out);
}

// round 5
// speedup vs baseline: 1.2715x; 1.1588x over previous
#include <cuda_runtime.h>
#include <math.h>
#include <stdint.h>

typedef unsigned long long u64;
typedef unsigned int u32;

// ---------------- problem constants ----------------
#define BN   2048
#define TSEQ 50
#define NSEQ 64
#define BB   32

// ---------------- device scratch ----------------
__device__ float g_xp0[(size_t)TSEQ * BN * 512];
__device__ float g_xp1[(size_t)TSEQ * BN * 512];
__device__ float g_hbuf[2][2 * BN * 128];
__device__ float g_cst[2 * BN * 128];
__device__ float g_hsum[2 * BN * 128];
__device__ float g_sentpres[(size_t)BN * 256];
__device__ float g_txp0[(size_t)NSEQ * BB * 512];
__device__ float g_txp1[(size_t)NSEQ * BB * 512];
__device__ float g_thbuf[2][2 * BB * 128];
__device__ float g_tag_out[(size_t)BN * 256];
__device__ float g_q[(size_t)BN * 256];
__device__ float g_k[(size_t)BN * 256];
__device__ float g_sentFt[(size_t)BN * 15];
__device__ float g_roleFt[(size_t)BN * 15];
__device__ float g_agg[(size_t)BN * 256];
__device__ int g_tbar;
__device__ int g_tdone;

// ---------------- f32x2 helpers ----------------
__device__ __forceinline__ u64 pk2(float lo, float hi) {
    u64 r; asm("mov.b64 %0, {%1, %2};" : "=l"(r) : "f"(lo), "f"(hi)); return r;
}
__device__ __forceinline__ void up2(u64 v, float& lo, float& hi) {
    asm("mov.b64 {%0, %1}, %2;" : "=f"(lo), "=f"(hi) : "l"(v));
}
__device__ __forceinline__ void fma2(u64& d, u64 a, u64 b) {
    asm("fma.rn.f32x2 %0, %1, %2, %0;" : "+l"(d) : "l"(a), "l"(b));
}

// ---------------- tf32 helpers ----------------
__device__ __forceinline__ float tf32_rna(float x) {
    u32 u; asm("cvt.rna.tf32.f32 %0, %1;" : "=r"(u) : "f"(x));
    return __uint_as_float(u);
}
__device__ __forceinline__ void mma_tf32(float* d, const u32* a, const u32* b) {
    asm("mma.sync.aligned.m16n8k8.row.col.f32.tf32.tf32.f32 "
        "{%0,%1,%2,%3},{%4,%5,%6,%7},{%8,%9},{%0,%1,%2,%3};"
        : "+f"(d[0]), "+f"(d[1]), "+f"(d[2]), "+f"(d[3])
        : "r"(a[0]), "r"(a[1]), "r"(a[2]), "r"(a[3]), "r"(b[0]), "r"(b[1]));
}

// ---------------- fast math ----------------
__device__ __forceinline__ float sigf(float x) {
    x = fminf(fmaxf(x, -30.f), 30.f);
    return __fdividef(1.f, 1.f + __expf(-x));
}
__device__ __forceinline__ float tanhfast(float x) {
    x = fminf(fmaxf(x, -15.f), 15.f);
    return __fdividef(2.f, 1.f + __expf(-2.f * x)) - 1.f;
}

// ============================================================
// K1: sentence input projection with tensor cores (3xTF32).
// C[m][dir*512+g] = A[m][:200] . W_dir[g][:200] + b_dir[g]
// Block 128m x 128n, 8 warps (2m x 4n), warp m64 x n32.
// grid (800, 8): blockIdx.y 0-3 -> dir0 cols, 4-7 -> dir1.
// ============================================================
#define K1P 12   // padded row stride (words): conflict-free frag gathers
__global__ void __launch_bounds__(256) gemm_inproj_tc(
    const float* __restrict__ A,
    const float* __restrict__ B0, const float* __restrict__ B1,
    const float* __restrict__ bias0, const float* __restrict__ bias1)
{
    __shared__ float sAh[2][128 * K1P], sAl[2][128 * K1P];
    __shared__ float sBh[2][128 * K1P], sBl[2][128 * K1P];

    int m0 = blockIdx.x * 128;
    int nb = blockIdx.y;
    int dir = nb >> 2;
    int n0 = (nb & 3) * 128;            // column base within [0,512)
    const float* Bw = dir ? B1 : B0;
    const float* bias = dir ? bias1 : bias0;
    float* out = dir ? g_xp1 : g_xp0;

    int tid = threadIdx.x;
    int lane = tid & 31, warp = tid >> 5;
    int g = lane >> 2, tig = lane & 3;
    int wm = warp & 1, wn = warp >> 1;

    int srow = tid >> 1, shalf = tid & 1;
    const float* aP = A + (size_t)(m0 + srow) * 200 + shalf * 4;
    const float* bP = Bw + (size_t)(n0 + srow) * 200 + shalf * 4;

    float acc[4][4][4];
#pragma unroll
    for (int i = 0; i < 4; i++)
#pragma unroll
        for (int j = 0; j < 4; j++)
#pragma unroll
            for (int c = 0; c < 4; c++) acc[i][j][c] = 0.0f;

    float4 av = *(const float4*)aP;
    float4 bv = *(const float4*)bP;

    int soff = srow * K1P + shalf * 4;
#define K1_STAGE(buf, a4, b4) do {                                          \
        float4 _h, _l;                                                      \
        _h.x = tf32_rna(a4.x); _l.x = tf32_rna(a4.x - _h.x);                \
        _h.y = tf32_rna(a4.y); _l.y = tf32_rna(a4.y - _h.y);                \
        _h.z = tf32_rna(a4.z); _l.z = tf32_rna(a4.z - _h.z);                \
        _h.w = tf32_rna(a4.w); _l.w = tf32_rna(a4.w - _h.w);                \
        *(float4*)&sAh[buf][soff] = _h;                                     \
        *(float4*)&sAl[buf][soff] = _l;                                     \
        _h.x = tf32_rna(b4.x); _l.x = tf32_rna(b4.x - _h.x);                \
        _h.y = tf32_rna(b4.y); _l.y = tf32_rna(b4.y - _h.y);                \
        _h.z = tf32_rna(b4.z); _l.z = tf32_rna(b4.z - _h.z);                \
        _h.w = tf32_rna(b4.w); _l.w = tf32_rna(b4.w - _h.w);                \
        *(float4*)&sBh[buf][soff] = _h;                                     \
        *(float4*)&sBl[buf][soff] = _l;                                     \
    } while (0)

    K1_STAGE(0, av, bv);
    __syncthreads();

    for (int kt = 0; kt < 25; kt++) {
        int cur = kt & 1;
        if (kt < 24) {
            av = *(const float4*)(aP + (kt + 1) * 8);
            bv = *(const float4*)(bP + (kt + 1) * 8);
        }
        // B fragments (n32 = 4 tiles of n8)
        u32 bh[4][2], bl[4][2];
#pragma unroll
        for (int nt = 0; nt < 4; nt++) {
            int br = (wn * 32 + nt * 8 + g) * K1P;
            bh[nt][0] = __float_as_uint(sBh[cur][br + tig]);
            bh[nt][1] = __float_as_uint(sBh[cur][br + tig + 4]);
            bl[nt][0] = __float_as_uint(sBl[cur][br + tig]);
            bl[nt][1] = __float_as_uint(sBl[cur][br + tig + 4]);
        }
#pragma unroll
        for (int mt = 0; mt < 4; mt++) {
            int ar0 = (wm * 64 + mt * 16 + g) * K1P;
            int ar1 = ar0 + 8 * K1P;
            u32 ah[4], al[4];
            ah[0] = __float_as_uint(sAh[cur][ar0 + tig]);
            ah[1] = __float_as_uint(sAh[cur][ar1 + tig]);
            ah[2] = __float_as_uint(sAh[cur][ar0 + tig + 4]);
            ah[3] = __float_as_uint(sAh[cur][ar1 + tig + 4]);
            al[0] = __float_as_uint(sAl[cur][ar0 + tig]);
            al[1] = __float_as_uint(sAl[cur][ar1 + tig]);
            al[2] = __float_as_uint(sAl[cur][ar0 + tig + 4]);
            al[3] = __float_as_uint(sAl[cur][ar1 + tig + 4]);
#pragma unroll
            for (int nt = 0; nt < 4; nt++) {
                mma_tf32(acc[mt][nt], ah, bh[nt]);   // hi*hi
                mma_tf32(acc[mt][nt], al, bh[nt]);   // lo*hi
                mma_tf32(acc[mt][nt], ah, bl[nt]);   // hi*lo
            }
        }
        __syncthreads();
        if (kt < 24) {
            K1_STAGE((kt + 1) & 1, av, bv);
            __syncthreads();
        }
    }

    // epilogue: scatter to g_xp[t][p][gcol], add bias
#pragma unroll
    for (int mt = 0; mt < 4; mt++) {
#pragma unroll
        for (int nt = 0; nt < 4; nt++) {
            int col = n0 + wn * 32 + nt * 8 + 2 * tig;
            float b0v = __ldg(bias + col), b1v = __ldg(bias + col + 1);
            int r0 = m0 + wm * 64 + mt * 16 + g;
            int p0 = r0 / 50, t0 = r0 - p0 * 50;
            float2 o0 = make_float2(acc[mt][nt][0] + b0v, acc[mt][nt][1] + b1v);
            *(float2*)(out + ((size_t)t0 * BN + p0) * 512 + col) = o0;
            int r1 = r0 + 8;
            int p1 = r1 / 50, t1 = r1 - p1 * 50;
            float2 o1 = make_float2(acc[mt][nt][2] + b0v, acc[mt][nt][3] + b1v);
            *(float2*)(out + ((size_t)t1 * BN + p1) * 512 + col) = o1;
        }
    }
}

// ============================================================
// Dual-half GEMM with f32x2 (modes 1-4, unchanged)
// ============================================================
template <int MODE>
__global__ void __launch_bounds__(256) gemm_dual(
    const float* __restrict__ Aparam, int M, int K, int NB,
    const float* __restrict__ B0, const float* __restrict__ B1,
    const float* __restrict__ bias0, const float* __restrict__ bias1,
    float* __restrict__ outParam)
{
    __shared__ __align__(16) u64 As2[8][128];
    __shared__ __align__(16) float Bs[8][128];

    const float* A;
    if (MODE == 1 || MODE == 2) A = g_sentpres;
    else if (MODE == 3) A = g_tag_out;
    else A = g_agg;
    (void)Aparam;

    int hsel = (blockIdx.y * 128) / NB;
    int g0 = blockIdx.y * 128 - hsel * NB;
    int m0 = blockIdx.x * 128;

    const float* B = hsel ? B1 : B0;
    const float* bias = hsel ? bias1 : bias0;

    float* out;
    if (MODE == 1) out = hsel ? g_txp1 : g_txp0;
    else if (MODE == 2 || MODE == 3) out = hsel ? g_k : g_q;
    else out = outParam;

    int tid = threadIdx.x;
    int tx = tid & 15;
    int ty = tid >> 4;
    int lr = tid >> 1;
    int lc4 = tid & 1;

    u64 acc2[8][4];
#pragma unroll
    for (int i = 0; i < 8; i++)
#pragma unroll
        for (int j = 0; j < 4; j++) acc2[i][j] = 0ULL;

    int KT = K / 8;
    const float* aPtr = A + (size_t)(m0 + lr) * K + lc4 * 4;
    const float* bPtr = B + (size_t)(g0 + lr) * K + lc4 * 4;
    float4 av = *(const float4*)(aPtr);
    float4 bv = *(const float4*)(bPtr);

    for (int kt = 0; kt < KT; kt++) {
        As2[lc4 * 4 + 0][lr] = pk2(av.x, av.x);
        As2[lc4 * 4 + 1][lr] = pk2(av.y, av.y);
        As2[lc4 * 4 + 2][lr] = pk2(av.z, av.z);
        As2[lc4 * 4 + 3][lr] = pk2(av.w, av.w);
        Bs[lc4 * 4 + 0][lr] = bv.x; Bs[lc4 * 4 + 1][lr] = bv.y;
        Bs[lc4 * 4 + 2][lr] = bv.z; Bs[lc4 * 4 + 3][lr] = bv.w;
        __syncthreads();
        if (kt + 1 < KT) {
            av = *(const float4*)(aPtr + (kt + 1) * 8);
            bv = *(const float4*)(bPtr + (kt + 1) * 8);
        }
#pragma unroll
        for (int kk = 0; kk < 8; kk++) {
            u64 b2[4];
#pragma unroll
            for (int jq = 0; jq < 4; jq++)
                b2[jq] = *(const u64*)&Bs[kk][2 * (tx + 16 * jq)];
            u64 a2[8];
#pragma unroll
            for (int i = 0; i < 8; i++) a2[i] = As2[kk][ty * 8 + i];
#pragma unroll
            for (int i = 0; i < 8; i++)
#pragma unroll
                for (int jq = 0; jq < 4; jq++)
                    fma2(acc2[i][jq], a2[i], b2[jq]);
        }
        __syncthreads();
    }

#pragma unroll
    for (int i = 0; i < 8; i++) {
        int m = m0 + ty * 8 + i;
        size_t rowbase;
        if (MODE == 1) {
            int b = m >> 6; int n = m & 63;
            rowbase = ((size_t)n * BB + b) * 512;
        } else {
            rowbase = (size_t)m * 256;
        }
#pragma unroll
        for (int jq = 0; jq < 4; jq++) {
            int g = g0 + 2 * (tx + 16 * jq);
            float lo, hi;
            up2(acc2[i][jq], lo, hi);
            float2 bb = *(const float2*)(bias + g);
            float2 o;
            o.x = lo + bb.x;
            o.y = hi + bb.y;
            if (MODE == 4) { o.x = fmaxf(o.x, 0.f); o.y = fmaxf(o.y, 0.f); }
            *(float2*)(out + rowbase + g) = o;
        }
    }
}

// ============================================================
// Sentence LSTM step v3: 64p x 32j x 4 gates per block.
// Each thread: 4p x 2 j-slots (jj, jj+16) x 4 gates.
// grid (32 pch, 4 jch, 2 dir), 256 threads, 2 blocks/SM.
// smem: Wp u64[4][32][66] (67584 B) + hp u64[64][66] (33792 B).
// ============================================================
#define SENT3_WP   (4 * 32 * 66)
#define SENT3_SMEM ((SENT3_WP + 64 * 66) * 8)

__global__ void __launch_bounds__(256, 2) lstm_sent3(
    const float* __restrict__ W0, const float* __restrict__ W1, int s)
{
    extern __shared__ __align__(16) u64 sm3[];
    u64 (*Wp)[32][66] = (u64 (*)[32][66])sm3;
    u64 (*hp)[66] = (u64 (*)[66])(sm3 + SENT3_WP);

    int dir = blockIdx.z;
    int j0 = blockIdx.y * 32;
    int p0 = blockIdx.x * 64;
    int t = dir ? (TSEQ - 1 - s) : s;
    const float* W = dir ? W1 : W0;
    const float* xp = dir ? g_xp1 : g_xp0;
    const float* hIn = g_hbuf[s & 1] + (size_t)dir * BN * 128;
    float* hOut = g_hbuf[(s + 1) & 1] + (size_t)dir * BN * 128;
    float* cD = g_cst + (size_t)dir * BN * 128;
    float* hsD = g_hsum + (size_t)dir * BN * 128;

    int tid = threadIdx.x;
    int jj = tid & 15;
    int pg = tid >> 4;        // 16 groups x 4 p

    u64 acc2[4][4][2];        // [pp][gate][jslot]
#pragma unroll
    for (int a = 0; a < 4; a++)
#pragma unroll
        for (int b = 0; b < 4; b++) { acc2[a][b][0] = 0ULL; acc2[a][b][1] = 0ULL; }

    if (s > 0) {
        // stage W: 4 gates x 32 j x 128 k, packed k-pairs
        {
            int row = tid >> 1;             // 0..127 = g*32 + jr
            int gg = row >> 5, jr = row & 31;
            int half = tid & 1;
            const float* wrow = W + (size_t)(gg * 128 + j0 + jr) * 128 + half * 64;
            u64* dst = &Wp[gg][jr][half * 32];
#pragma unroll
            for (int q = 0; q < 8; q++) {
                float4 v = *(const float4*)(wrow + q * 8);
                float4 w = *(const float4*)(wrow + q * 8 + 4);
                dst[q * 4 + 0] = pk2(v.x, v.y);
                dst[q * 4 + 1] = pk2(v.z, v.w);
                dst[q * 4 + 2] = pk2(w.x, w.y);
                dst[q * 4 + 3] = pk2(w.z, w.w);
            }
        }
        // stage h: 64 p x 128 k, packed k-pairs
        {
            int prow = tid >> 2;            // 0..63
            int quarter = tid & 3;
            const float* hrow = hIn + (size_t)(p0 + prow) * 128 + quarter * 32;
            u64* dst = &hp[prow][quarter * 16];
#pragma unroll
            for (int q = 0; q < 8; q++) {
                float4 v = *(const float4*)(hrow + q * 4);
                dst[q * 2 + 0] = pk2(v.x, v.y);
                dst[q * 2 + 1] = pk2(v.z, v.w);
            }
        }
        __syncthreads();

#pragma unroll 2
        for (int k2 = 0; k2 < 32; k2++) {
            ulonglong2 hv0 = *(const ulonglong2*)&hp[pg * 4 + 0][k2 * 2];
            ulonglong2 hv1 = *(const ulonglong2*)&hp[pg * 4 + 1][k2 * 2];
            ulonglong2 hv2 = *(const ulonglong2*)&hp[pg * 4 + 2][k2 * 2];
            ulonglong2 hv3 = *(const ulonglong2*)&hp[pg * 4 + 3][k2 * 2];
#pragma unroll
            for (int g = 0; g < 4; g++) {
                ulonglong2 wa = *(const ulonglong2*)&Wp[g][jj][k2 * 2];
                ulonglong2 wb = *(const ulonglong2*)&Wp[g][jj + 16][k2 * 2];
                fma2(acc2[0][g][0], hv0.x, wa.x); fma2(acc2[0][g][0], hv0.y, wa.y);
                fma2(acc2[0][g][1], hv0.x, wb.x); fma2(acc2[0][g][1], hv0.y, wb.y);
                fma2(acc2[1][g][0], hv1.x, wa.x); fma2(acc2[1][g][0], hv1.y, wa.y);
                fma2(acc2[1][g][1], hv1.x, wb.x); fma2(acc2[1][g][1], hv1.y, wb.y);
                fma2(acc2[2][g][0], hv2.x, wa.x); fma2(acc2[2][g][0], hv2.y, wa.y);
                fma2(acc2[2][g][1], hv2.x, wb.x); fma2(acc2[2][g][1], hv2.y, wb.y);
                fma2(acc2[3][g][0], hv3.x, wa.x); fma2(acc2[3][g][0], hv3.y, wa.y);
                fma2(acc2[3][g][1], hv3.x, wb.x); fma2(acc2[3][g][1], hv3.y, wb.y);
            }
        }
    }

    size_t xbase = (size_t)t * BN * 512;
#pragma unroll
    for (int pp = 0; pp < 4; pp++) {
        int p = p0 + pg * 4 + pp;
        size_t xrow = xbase + (size_t)p * 512;
#pragma unroll
        for (int js = 0; js < 2; js++) {
            int j = j0 + jj + js * 16;
            const float* xr = xp + xrow + j;
            float lo, hi;
            up2(acc2[pp][0][js], lo, hi); float gi = lo + hi + xr[0];
            up2(acc2[pp][1][js], lo, hi); float gf = lo + hi + xr[128];
            up2(acc2[pp][2][js], lo, hi); float gg = lo + hi + xr[256];
            up2(acc2[pp][3][js], lo, hi); float go = lo + hi + xr[384];
            size_t hidx = (size_t)p * 128 + j;
            float cold = (s == 0) ? 0.0f : cD[hidx];
            float cn = sigf(gf) * cold + sigf(gi) * tanhfast(gg);
            float hn = sigf(go) * tanhfast(cn);
            if (s == TSEQ - 1) {
                float hs = hsD[hidx] + hn;
                g_sentpres[(size_t)p * 256 + dir * 128 + j] = tanhfast(hs * (1.0f / 50.0f));
            } else {
                cD[hidx] = cn;
                hOut[hidx] = hn;
                hsD[hidx] = (s == 0) ? hn : (hsD[hidx] + hn);
            }
        }
    }
}

// ============================================================
// Persistent tag BiLSTM (unchanged)
// ============================================================
#define TAG_NBLK 8
__global__ void __launch_bounds__(256) tag_persistent(
    const float* __restrict__ W0, const float* __restrict__ W1)
{
    extern __shared__ __align__(16) char sm[];
    u64 (*Wf)[32][65] = (u64 (*)[32][65])sm;
    float (*hsf)[128] = (float (*)[128])(sm + 4 * 32 * 65 * 8);

    int dir = blockIdx.x >> 2;
    int j0 = (blockIdx.x & 3) * 32;
    const float* W = dir ? W1 : W0;
    const float* xp = dir ? g_txp1 : g_txp0;
    int tid = threadIdx.x;
    int jj = tid & 31;
    int pg = tid >> 5;
    int j = j0 + jj;

    {
        int rowId = tid >> 1;
        int g = rowId >> 5, jr = rowId & 31;
        int half = tid & 1;
        const float* wrow = W + (size_t)(g * 128 + j0 + jr) * 128 + half * 64;
        u64* dst = &Wf[g][jr][half * 32];
#pragma unroll
        for (int q = 0; q < 16; q++) {
            float4 v = *(const float4*)(wrow + q * 4);
            dst[q * 2 + 0] = pk2(v.x, v.y);
            dst[q * 2 + 1] = pk2(v.z, v.w);
        }
    }

    float creg[4] = {0.f, 0.f, 0.f, 0.f};

    for (int s = 0; s < NSEQ; s++) {
        int t = dir ? (NSEQ - 1 - s) : s;
        u64 acc2[4][4];
#pragma unroll
        for (int a = 0; a < 4; a++)
#pragma unroll
            for (int b = 0; b < 4; b++) acc2[a][b] = 0ULL;

        if (s > 0) {
            const float* hIn = g_thbuf[s & 1] + (size_t)dir * BB * 128;
#pragma unroll
            for (int i = 0; i < 4; i++) {
                int idx = tid + i * 256;
                int r = idx >> 5, c4 = idx & 31;
                *(float4*)&hsf[r][c4 * 4] =
                    *(const float4*)(hIn + (size_t)r * 128 + c4 * 4);
            }
            __syncthreads();
#pragma unroll 4
            for (int kp = 0; kp < 64; kp++) {
                u64 w0 = Wf[0][jj][kp];
                u64 w1 = Wf[1][jj][kp];
                u64 w2 = Wf[2][jj][kp];
                u64 w3 = Wf[3][jj][kp];
#pragma unroll
                for (int bb = 0; bb < 4; bb++) {
                    u64 a2 = *(const u64*)&hsf[pg * 4 + bb][kp * 2];
                    fma2(acc2[bb][0], a2, w0);
                    fma2(acc2[bb][1], a2, w1);
                    fma2(acc2[bb][2], a2, w2);
                    fma2(acc2[bb][3], a2, w3);
                }
            }
        }

        float* hOut = g_thbuf[(s + 1) & 1] + (size_t)dir * BB * 128;
#pragma unroll
        for (int bb = 0; bb < 4; bb++) {
            int b = pg * 4 + bb;
            const float* xr = xp + ((size_t)t * BB + b) * 512 + j;
            float lo, hi;
            up2(acc2[bb][0], lo, hi); float gi = lo + hi + xr[0];
            up2(acc2[bb][1], lo, hi); float gf = lo + hi + xr[128];
            up2(acc2[bb][2], lo, hi); float gg = lo + hi + xr[256];
            up2(acc2[bb][3], lo, hi); float go = lo + hi + xr[384];
            float cn = sigf(gf) * creg[bb] + sigf(gi) * tanhfast(gg);
            float hn = sigf(go) * tanhfast(cn);
            creg[bb] = cn;
            hOut[(size_t)b * 128 + j] = hn;
            g_tag_out[((size_t)b * NSEQ + t) * 256 + dir * 128 + j] = tanhfast(hn);
        }

        if (s < NSEQ - 1) {
            __syncthreads();
            if (tid == 0) {
                __threadfence();
                atomicAdd(&g_tbar, 1);
                int target = TAG_NBLK * (s + 1);
                while (*(volatile int*)&g_tbar < target) { }
                __threadfence();
            }
            __syncthreads();
        }
    }

    __syncthreads();
    if (tid == 0) {
        int old = atomicAdd(&g_tdone, 1);
        if (old == TAG_NBLK - 1) {
            g_tbar = 0;
            __threadfence();
            g_tdone = 0;
        }
    }
}

// ---------------- SPP ----------------
__global__ void __launch_bounds__(256) spp_kernel(int which) {
    int b = blockIdx.x;
    int tid = threadIdx.x;
    __shared__ float qs[64][33];
    __shared__ float ks[64][33];
    __shared__ float segs[64][8];

    float acc[16];
#pragma unroll
    for (int i = 0; i < 16; i++) acc[i] = 0.0f;
    int n = tid >> 2;
    int mBase = (tid & 3) * 16;

    for (int d0 = 0; d0 < 256; d0 += 32) {
        __syncthreads();
        for (int idx = tid; idx < 64 * 32; idx += 256) {
            int r = idx >> 5, cc = idx & 31;
            size_t gi = ((size_t)(b * 64 + r)) * 256 + d0 + cc;
            qs[r][cc] = g_q[gi];
            ks[r][cc] = g_k[gi];
        }
        __syncthreads();
#pragma unroll 4
        for (int dd = 0; dd < 32; dd++) {
            float qv = qs[n][dd];
#pragma unroll
            for (int mm = 0; mm < 16; mm++)
                acc[mm] += qv * ks[mBase + mm][dd];
        }
    }
    float s8a = -3.4e38f, s8b = -3.4e38f;
#pragma unroll
    for (int mm = 0; mm < 8; mm++)  s8a = fmaxf(s8a, acc[mm]);
#pragma unroll
    for (int mm = 8; mm < 16; mm++) s8b = fmaxf(s8b, acc[mm]);
    segs[n][(tid & 3) * 2 + 0] = s8a * 0.0625f;
    segs[n][(tid & 3) * 2 + 1] = s8b * 0.0625f;
    __syncthreads();

    if (tid < 64) {
        float e[8];
#pragma unroll
        for (int i = 0; i < 8; i++) e[i] = segs[tid][i];
        float q4[4], h2[2];
#pragma unroll
        for (int i = 0; i < 4; i++) q4[i] = fmaxf(e[2 * i], e[2 * i + 1]);
        h2[0] = fmaxf(q4[0], q4[1]);
        h2[1] = fmaxf(q4[2], q4[3]);
        float a1 = fmaxf(h2[0], h2[1]);
        float* o = (which ? g_roleFt : g_sentFt) + (size_t)(b * 64 + tid) * 15;
        o[0] = a1;
        o[1] = h2[0]; o[2] = h2[1];
#pragma unroll
        for (int i = 0; i < 4; i++) o[3 + i] = q4[i];
#pragma unroll
        for (int i = 0; i < 8; i++) o[7 + i] = e[i];
    }
}

// ---------------- GCN pre ----------------
__global__ void __launch_bounds__(256) gcn_pre() {
    int b = blockIdx.x;
    int tid = threadIdx.x;
    __shared__ float cosm[64][65];
    __shared__ float xs[64][33];
    __shared__ float inv[64];

    if (tid < 64) {
        const float* xr = g_tag_out + (size_t)(b * 64 + tid) * 256;
        float s = 0.0f;
        for (int d = 0; d < 256; d++) { float v = xr[d]; s += v * v; }
        inv[tid] = 1.0f / (sqrtf(s) + 1e-8f);
    }

    float acc[16];
#pragma unroll
    for (int i = 0; i < 16; i++) acc[i] = 0.0f;
    int n = tid >> 2;
    int mBase = (tid & 3) * 16;

    for (int d0 = 0; d0 < 256; d0 += 32) {
        __syncthreads();
        for (int idx = tid; idx < 64 * 32; idx += 256) {
            int r = idx >> 5, cc = idx & 31;
            xs[r][cc] = g_tag_out[((size_t)(b * 64 + r)) * 256 + d0 + cc];
        }
        __syncthreads();
#pragma unroll 4
        for (int dd = 0; dd < 32; dd++) {
            float xv = xs[n][dd];
#pragma unroll
            for (int mm = 0; mm < 16; mm++)
                acc[mm] += xv * xs[mBase + mm][dd];
        }
    }
#pragma unroll
    for (int mm = 0; mm < 16; mm++)
        cosm[n][mBase + mm] = acc[mm] * inv[n] * inv[mBase + mm];

    int ddBase = (tid & 3) * 8;
    for (int d0 = 0; d0 < 256; d0 += 32) {
        __syncthreads();
        for (int idx = tid; idx < 64 * 32; idx += 256) {
            int r = idx >> 5, cc = idx & 31;
            xs[r][cc] = g_tag_out[((size_t)(b * 64 + r)) * 256 + d0 + cc];
        }
        __syncthreads();
        float r8[8];
#pragma unroll
        for (int i = 0; i < 8; i++) r8[i] = 0.0f;
        for (int m = 0; m < 64; m++) {
            float cv = cosm[n][m];
#pragma unroll
            for (int i = 0; i < 8; i++) r8[i] += cv * xs[m][ddBase + i];
        }
#pragma unroll
        for (int i = 0; i < 8; i++) {
            float v = (r8[i] + 2.0f * xs[n][ddBase + i]) * (1.0f / 66.0f);
            g_agg[(size_t)(b * 64 + n) * 256 + d0 + ddBase + i] = v;
        }
    }
}

// ---------------- classifier + log_softmax ----------------
__global__ void __launch_bounds__(256) cls_kernel(
    const float* __restrict__ W, const float* __restrict__ bias,
    float* __restrict__ out)
{
    __shared__ float Wsh[8][288];
    __shared__ float bsh[8];
    __shared__ float ftile[256][33];

    int tid = threadIdx.x;
    for (int i = tid; i < 8 * 286; i += 256) Wsh[i / 286][i % 286] = W[i];
    if (tid < 8) bsh[tid] = bias[tid];
    __syncthreads();

    int p0 = blockIdx.x * 256;
    int p = p0 + tid;
    float z[8];
#pragma unroll
    for (int c = 0; c < 8; c++) z[c] = bsh[c];

    for (int d0 = 0; d0 < 256; d0 += 32) {
        __syncthreads();
        for (int idx = tid; idx < 256 * 32; idx += 256) {
            int r = idx >> 5, cc = idx & 31;
            ftile[r][cc] = g_tag_out[(size_t)(p0 + r) * 256 + d0 + cc];
        }
        __syncthreads();
#pragma unroll 4
        for (int dd = 0; dd < 32; dd++) {
            float f = ftile[tid][dd];
#pragma unroll
            for (int c = 0; c < 8; c++) z[c] += f * Wsh[c][d0 + dd];
        }
    }
#pragma unroll
    for (int d = 0; d < 15; d++) {
        float f = g_sentFt[(size_t)p * 15 + d];
#pragma unroll
        for (int c = 0; c < 8; c++) z[c] += f * Wsh[c][256 + d];
    }
#pragma unroll
    for (int d = 0; d < 15; d++) {
        float f = g_roleFt[(size_t)p * 15 + d];
#pragma unroll
        for (int c = 0; c < 8; c++) z[c] += f * Wsh[c][271 + d];
    }
    float m = z[0];
#pragma unroll
    for (int c = 1; c < 8; c++) m = fmaxf(m, z[c]);
    float se = 0.0f;
#pragma unroll
    for (int c = 0; c < 8; c++) se += expf(z[c] - m);
    float lse = m + logf(se);
#pragma unroll
    for (int c = 0; c < 8; c++) out[(size_t)p * 8 + c] = z[c] - lse;
}

// ============================================================
extern "C" void kernel_launch(void* const* d_in, const int* in_sizes, int n_in,
                              void* d_out, int out_size)
{
    (void)in_sizes; (void)n_in; (void)out_size;
    const float* documents = (const float*)d_in[0];
    const float* sw_ih_f = (const float*)d_in[1];
    const float* sw_hh_f = (const float*)d_in[2];
    const float* sb_f    = (const float*)d_in[3];
    const float* sw_ih_b = (const float*)d_in[4];
    const float* sw_hh_b = (const float*)d_in[5];
    const float* sb_b    = (const float*)d_in[6];
    const float* sf_Wq   = (const float*)d_in[7];
    const float* sf_bq   = (const float*)d_in[8];
    const float* sf_Wk   = (const float*)d_in[9];
    const float* sf_bk   = (const float*)d_in[10];
    const float* rf_Wq   = (const float*)d_in[11];
    const float* rf_bq   = (const float*)d_in[12];
    const float* rf_Wk   = (const float*)d_in[13];
    const float* rf_bk   = (const float*)d_in[14];
    const float* tw_ih_f = (const float*)d_in[15];
    const float* tw_hh_f = (const float*)d_in[16];
    const float* tb_f    = (const float*)d_in[17];
    const float* tw_ih_b = (const float*)d_in[18];
    const float* tw_hh_b = (const float*)d_in[19];
    const float* tb_b    = (const float*)d_in[20];
    const float* sage_W  = (const float*)d_in[21];
    const float* sage_b  = (const float*)d_in[22];
    const float* cls_W   = (const float*)d_in[23];
    const float* cls_b   = (const float*)d_in[24];
    float* out = (float*)d_out;

    const int TAG_SMEM = 4 * 32 * 65 * 8 + 32 * 128 * 4;   // 82944
    cudaFuncSetAttribute(lstm_sent3, cudaFuncAttributeMaxDynamicSharedMemorySize, SENT3_SMEM);
    cudaFuncSetAttribute(tag_persistent, cudaFuncAttributeMaxDynamicSharedMemorySize, TAG_SMEM);

    // 1) sentence BiLSTM input projection: tensor cores, 3xTF32
    gemm_inproj_tc<<<dim3(800, 8), 256>>>(documents, sw_ih_f, sw_ih_b, sb_f, sb_b);
    // 2) sentence recurrence, 50 steps (sentpres folded into s=49)
    for (int s = 0; s < TSEQ; s++)
        lstm_sent3<<<dim3(32, 4, 2), 256, SENT3_SMEM>>>(sw_hh_f, sw_hh_b, s);
    // 3) tag BiLSTM input projection
    gemm_dual<1><<<dim3(16, 8), 256>>>(nullptr, 2048, 256, 512,
                                       tw_ih_f, tw_ih_b, tb_f, tb_b, nullptr);
    // 4) tag recurrence: persistent kernel
    tag_persistent<<<TAG_NBLK, 256, TAG_SMEM>>>(tw_hh_f, tw_hh_b);
    // 5) SPP on sentpres -> sentFt
    gemm_dual<2><<<dim3(16, 4), 256>>>(nullptr, 2048, 256, 256,
                                       sf_Wq, sf_Wk, sf_bq, sf_bk, nullptr);
    spp_kernel<<<32, 256>>>(0);
    // 6) SPP on tag_out -> roleFt
    gemm_dual<3><<<dim3(16, 4), 256>>>(nullptr, 2048, 256, 256,
                                       rf_Wq, rf_Wk, rf_bq, rf_bk, nullptr);
    spp_kernel<<<32, 256>>>(1);
    // 7) GCN
    gcn_pre<<<32, 256>>>();
    gemm_dual<4><<<dim3(16, 2), 256>>>(nullptr, 2048, 256, 256,
                                       sage_W, sage_W, sage_b, sage_b, out + 16384);
    // 8) classifier + log_softmax
    cls_kernel<<<8, 256>>>(cls_W, cls_b, out);
}

// round 6
// speedup vs baseline: 1.3930x; 1.0955x over previous
#include <cuda_runtime.h>
#include <math.h>
#include <stdint.h>

typedef unsigned long long u64;
typedef unsigned int u32;

// ---------------- problem constants ----------------
#define BN   2048
#define TSEQ 50
#define NSEQ 64
#define BB   32

// ---------------- device scratch ----------------
__device__ float g_xp0[(size_t)TSEQ * BN * 512];
__device__ float g_xp1[(size_t)TSEQ * BN * 512];
__device__ float g_hbuf[2][2 * BN * 128];
__device__ float g_cst[2 * BN * 128];
__device__ float g_hsum[2 * BN * 128];
__device__ float g_sentpres[(size_t)BN * 256];
__device__ float g_txp0[(size_t)NSEQ * BB * 512];
__device__ float g_txp1[(size_t)NSEQ * BB * 512];
__device__ float g_thbuf[2][2 * BB * 128];
__device__ float g_tag_out[(size_t)BN * 256];
__device__ float g_q[(size_t)BN * 256];
__device__ float g_k[(size_t)BN * 256];
__device__ float g_sentFt[(size_t)BN * 15];
__device__ float g_roleFt[(size_t)BN * 15];
__device__ float g_agg[(size_t)BN * 256];
__device__ int g_tbar;
__device__ int g_tdone;

// ---------------- f32x2 helpers ----------------
__device__ __forceinline__ u64 pk2(float lo, float hi) {
    u64 r; asm("mov.b64 %0, {%1, %2};" : "=l"(r) : "f"(lo), "f"(hi)); return r;
}
__device__ __forceinline__ void up2(u64 v, float& lo, float& hi) {
    asm("mov.b64 {%0, %1}, %2;" : "=f"(lo), "=f"(hi) : "l"(v));
}
__device__ __forceinline__ void fma2(u64& d, u64 a, u64 b) {
    asm("fma.rn.f32x2 %0, %1, %2, %0;" : "+l"(d) : "l"(a), "l"(b));
}

// ---------------- tf32 helpers ----------------
__device__ __forceinline__ float tf32_rna(float x) {
    u32 u; asm("cvt.rna.tf32.f32 %0, %1;" : "=r"(u) : "f"(x));
    return __uint_as_float(u);
}
__device__ __forceinline__ void mma_tf32(float* d, const u32* a, const u32* b) {
    asm("mma.sync.aligned.m16n8k8.row.col.f32.tf32.tf32.f32 "
        "{%0,%1,%2,%3},{%4,%5,%6,%7},{%8,%9},{%0,%1,%2,%3};"
        : "+f"(d[0]), "+f"(d[1]), "+f"(d[2]), "+f"(d[3])
        : "r"(a[0]), "r"(a[1]), "r"(a[2]), "r"(a[3]), "r"(b[0]), "r"(b[1]));
}

// ---------------- fast math ----------------
__device__ __forceinline__ float sigf(float x) {
    x = fminf(fmaxf(x, -30.f), 30.f);
    return __fdividef(1.f, 1.f + __expf(-x));
}
__device__ __forceinline__ float tanhfast(float x) {
    x = fminf(fmaxf(x, -15.f), 15.f);
    return __fdividef(2.f, 1.f + __expf(-2.f * x)) - 1.f;
}

// ============================================================
// K1: sentence input projection with tensor cores (3xTF32).
// (unchanged from R5 — validated)
// ============================================================
#define K1P 12
__global__ void __launch_bounds__(256) gemm_inproj_tc(
    const float* __restrict__ A,
    const float* __restrict__ B0, const float* __restrict__ B1,
    const float* __restrict__ bias0, const float* __restrict__ bias1)
{
    __shared__ float sAh[2][128 * K1P], sAl[2][128 * K1P];
    __shared__ float sBh[2][128 * K1P], sBl[2][128 * K1P];

    int m0 = blockIdx.x * 128;
    int nb = blockIdx.y;
    int dir = nb >> 2;
    int n0 = (nb & 3) * 128;
    const float* Bw = dir ? B1 : B0;
    const float* bias = dir ? bias1 : bias0;
    float* out = dir ? g_xp1 : g_xp0;

    int tid = threadIdx.x;
    int lane = tid & 31, warp = tid >> 5;
    int g = lane >> 2, tig = lane & 3;
    int wm = warp & 1, wn = warp >> 1;

    int srow = tid >> 1, shalf = tid & 1;
    const float* aP = A + (size_t)(m0 + srow) * 200 + shalf * 4;
    const float* bP = Bw + (size_t)(n0 + srow) * 200 + shalf * 4;

    float acc[4][4][4];
#pragma unroll
    for (int i = 0; i < 4; i++)
#pragma unroll
        for (int j = 0; j < 4; j++)
#pragma unroll
            for (int c = 0; c < 4; c++) acc[i][j][c] = 0.0f;

    float4 av = *(const float4*)aP;
    float4 bv = *(const float4*)bP;

    int soff = srow * K1P + shalf * 4;
#define K1_STAGE(buf, a4, b4) do {                                          \
        float4 _h, _l;                                                      \
        _h.x = tf32_rna(a4.x); _l.x = tf32_rna(a4.x - _h.x);                \
        _h.y = tf32_rna(a4.y); _l.y = tf32_rna(a4.y - _h.y);                \
        _h.z = tf32_rna(a4.z); _l.z = tf32_rna(a4.z - _h.z);                \
        _h.w = tf32_rna(a4.w); _l.w = tf32_rna(a4.w - _h.w);                \
        *(float4*)&sAh[buf][soff] = _h;                                     \
        *(float4*)&sAl[buf][soff] = _l;                                     \
        _h.x = tf32_rna(b4.x); _l.x = tf32_rna(b4.x - _h.x);                \
        _h.y = tf32_rna(b4.y); _l.y = tf32_rna(b4.y - _h.y);                \
        _h.z = tf32_rna(b4.z); _l.z = tf32_rna(b4.z - _h.z);                \
        _h.w = tf32_rna(b4.w); _l.w = tf32_rna(b4.w - _h.w);                \
        *(float4*)&sBh[buf][soff] = _h;                                     \
        *(float4*)&sBl[buf][soff] = _l;                                     \
    } while (0)

    K1_STAGE(0, av, bv);
    __syncthreads();

    for (int kt = 0; kt < 25; kt++) {
        int cur = kt & 1;
        if (kt < 24) {
            av = *(const float4*)(aP + (kt + 1) * 8);
            bv = *(const float4*)(bP + (kt + 1) * 8);
        }
        u32 bh[4][2], bl[4][2];
#pragma unroll
        for (int nt = 0; nt < 4; nt++) {
            int br = (wn * 32 + nt * 8 + g) * K1P;
            bh[nt][0] = __float_as_uint(sBh[cur][br + tig]);
            bh[nt][1] = __float_as_uint(sBh[cur][br + tig + 4]);
            bl[nt][0] = __float_as_uint(sBl[cur][br + tig]);
            bl[nt][1] = __float_as_uint(sBl[cur][br + tig + 4]);
        }
#pragma unroll
        for (int mt = 0; mt < 4; mt++) {
            int ar0 = (wm * 64 + mt * 16 + g) * K1P;
            int ar1 = ar0 + 8 * K1P;
            u32 ah[4], al[4];
            ah[0] = __float_as_uint(sAh[cur][ar0 + tig]);
            ah[1] = __float_as_uint(sAh[cur][ar1 + tig]);
            ah[2] = __float_as_uint(sAh[cur][ar0 + tig + 4]);
            ah[3] = __float_as_uint(sAh[cur][ar1 + tig + 4]);
            al[0] = __float_as_uint(sAl[cur][ar0 + tig]);
            al[1] = __float_as_uint(sAl[cur][ar1 + tig]);
            al[2] = __float_as_uint(sAl[cur][ar0 + tig + 4]);
            al[3] = __float_as_uint(sAl[cur][ar1 + tig + 4]);
#pragma unroll
            for (int nt = 0; nt < 4; nt++) {
                mma_tf32(acc[mt][nt], ah, bh[nt]);
                mma_tf32(acc[mt][nt], al, bh[nt]);
                mma_tf32(acc[mt][nt], ah, bl[nt]);
            }
        }
        __syncthreads();
        if (kt < 24) {
            K1_STAGE((kt + 1) & 1, av, bv);
            __syncthreads();
        }
    }

#pragma unroll
    for (int mt = 0; mt < 4; mt++) {
#pragma unroll
        for (int nt = 0; nt < 4; nt++) {
            int col = n0 + wn * 32 + nt * 8 + 2 * tig;
            float b0v = __ldg(bias + col), b1v = __ldg(bias + col + 1);
            int r0 = m0 + wm * 64 + mt * 16 + g;
            int p0 = r0 / 50, t0 = r0 - p0 * 50;
            float2 o0 = make_float2(acc[mt][nt][0] + b0v, acc[mt][nt][1] + b1v);
            *(float2*)(out + ((size_t)t0 * BN + p0) * 512 + col) = o0;
            int r1 = r0 + 8;
            int p1 = r1 / 50, t1 = r1 - p1 * 50;
            float2 o1 = make_float2(acc[mt][nt][2] + b0v, acc[mt][nt][3] + b1v);
            *(float2*)(out + ((size_t)t1 * BN + p1) * 512 + col) = o1;
        }
    }
}

// ============================================================
// Sentence LSTM step v4: TENSOR CORE recurrence.
// Block = 128 p x (4 gates x 32 j), K=128 in 4 chunks of 32.
// grid (16, 4, 2) = 128 blocks, 256 threads, 8 warps (2m x 4n),
// warp = 64p x 32cols; wn = gate index. 3xTF32 split.
// After GEMM, gates go to smem (aliased) and the LSTM state
// update epilogue runs in the same kernel.
// smem: sAh/sAl/sBh/sBl 128x36 floats each = 73728 B.
// ============================================================
#define S4_PAD  36
#define S4_SMEM (4 * 128 * S4_PAD * 4)

__global__ void __launch_bounds__(256) lstm_sent4(
    const float* __restrict__ W0, const float* __restrict__ W1, int s)
{
    extern __shared__ __align__(16) float s4[];
    float* sAh = s4;
    float* sAl = s4 + 128 * S4_PAD;
    float* sBh = s4 + 2 * 128 * S4_PAD;
    float* sBl = s4 + 3 * 128 * S4_PAD;
    float* gsm = s4;                      // aliased gate out [128][132]

    int dir = blockIdx.z;
    int j0 = blockIdx.y * 32;
    int p0 = blockIdx.x * 128;
    int t = dir ? (TSEQ - 1 - s) : s;
    const float* W = dir ? W1 : W0;
    const float* xp = dir ? g_xp1 : g_xp0;
    const float* hIn = g_hbuf[s & 1] + (size_t)dir * BN * 128;
    float* hOut = g_hbuf[(s + 1) & 1] + (size_t)dir * BN * 128;
    float* cD = g_cst + (size_t)dir * BN * 128;
    float* hsD = g_hsum + (size_t)dir * BN * 128;

    int tid = threadIdx.x;
    int lane = tid & 31, warp = tid >> 5;
    int g = lane >> 2, tig = lane & 3;
    int wm = warp & 1, wn = warp >> 1;    // wn = gate

    if (s > 0) {
        float acc[4][4][4];
#pragma unroll
        for (int i = 0; i < 4; i++)
#pragma unroll
            for (int j = 0; j < 4; j++)
#pragma unroll
                for (int c = 0; c < 4; c++) acc[i][j][c] = 0.0f;

        int srow = tid >> 1;          // 0..127
        int shalf = tid & 1;          // k offset 0/16 within chunk
        const float* aP = hIn + (size_t)(p0 + srow) * 128 + shalf * 16;
        int bgate = srow >> 5, bjj = srow & 31;
        const float* bP = W + (size_t)(bgate * 128 + j0 + bjj) * 128 + shalf * 16;
        int soff = srow * S4_PAD + shalf * 16;

        for (int kc = 0; kc < 4; kc++) {
            __syncthreads();
#pragma unroll
            for (int q = 0; q < 4; q++) {
                float4 a4 = *(const float4*)(aP + kc * 32 + q * 4);
                float4 h4, l4;
                h4.x = tf32_rna(a4.x); l4.x = tf32_rna(a4.x - h4.x);
                h4.y = tf32_rna(a4.y); l4.y = tf32_rna(a4.y - h4.y);
                h4.z = tf32_rna(a4.z); l4.z = tf32_rna(a4.z - h4.z);
                h4.w = tf32_rna(a4.w); l4.w = tf32_rna(a4.w - h4.w);
                *(float4*)&sAh[soff + q * 4] = h4;
                *(float4*)&sAl[soff + q * 4] = l4;
                float4 b4 = *(const float4*)(bP + kc * 32 + q * 4);
                h4.x = tf32_rna(b4.x); l4.x = tf32_rna(b4.x - h4.x);
                h4.y = tf32_rna(b4.y); l4.y = tf32_rna(b4.y - h4.y);
                h4.z = tf32_rna(b4.z); l4.z = tf32_rna(b4.z - h4.z);
                h4.w = tf32_rna(b4.w); l4.w = tf32_rna(b4.w - h4.w);
                *(float4*)&sBh[soff + q * 4] = h4;
                *(float4*)&sBl[soff + q * 4] = l4;
            }
            __syncthreads();
#pragma unroll
            for (int kt = 0; kt < 4; kt++) {
                int kb = kt * 8;
                u32 bh[4][2], bl[4][2];
#pragma unroll
                for (int nt = 0; nt < 4; nt++) {
                    int br = (wn * 32 + nt * 8 + g) * S4_PAD + kb;
                    bh[nt][0] = __float_as_uint(sBh[br + tig]);
                    bh[nt][1] = __float_as_uint(sBh[br + tig + 4]);
                    bl[nt][0] = __float_as_uint(sBl[br + tig]);
                    bl[nt][1] = __float_as_uint(sBl[br + tig + 4]);
                }
#pragma unroll
                for (int mt = 0; mt < 4; mt++) {
                    int ar0 = (wm * 64 + mt * 16 + g) * S4_PAD + kb;
                    int ar1 = ar0 + 8 * S4_PAD;
                    u32 ah[4], al[4];
                    ah[0] = __float_as_uint(sAh[ar0 + tig]);
                    ah[1] = __float_as_uint(sAh[ar1 + tig]);
                    ah[2] = __float_as_uint(sAh[ar0 + tig + 4]);
                    ah[3] = __float_as_uint(sAh[ar1 + tig + 4]);
                    al[0] = __float_as_uint(sAl[ar0 + tig]);
                    al[1] = __float_as_uint(sAl[ar1 + tig]);
                    al[2] = __float_as_uint(sAl[ar0 + tig + 4]);
                    al[3] = __float_as_uint(sAl[ar1 + tig + 4]);
#pragma unroll
                    for (int nt = 0; nt < 4; nt++) {
                        mma_tf32(acc[mt][nt], ah, bh[nt]);
                        mma_tf32(acc[mt][nt], al, bh[nt]);
                        mma_tf32(acc[mt][nt], ah, bl[nt]);
                    }
                }
            }
        }
        __syncthreads();      // all smem reads done; safe to alias as gsm
#pragma unroll
        for (int mt = 0; mt < 4; mt++) {
            int r0 = wm * 64 + mt * 16 + g;
#pragma unroll
            for (int nt = 0; nt < 4; nt++) {
                int col = wn * 32 + nt * 8 + 2 * tig;
                *(float2*)&gsm[r0 * 132 + col] =
                    make_float2(acc[mt][nt][0], acc[mt][nt][1]);
                *(float2*)&gsm[(r0 + 8) * 132 + col] =
                    make_float2(acc[mt][nt][2], acc[mt][nt][3]);
            }
        }
        __syncthreads();
    }

    // ---- fused LSTM epilogue: 128 p x 32 j per block ----
    size_t xbase = (size_t)t * BN * 512;
#pragma unroll
    for (int i = 0; i < 16; i++) {
        int pj = tid + i * 256;
        int pp = pj >> 5, jj = pj & 31;
        int p = p0 + pp;
        int j = j0 + jj;
        const float* xr = xp + xbase + (size_t)p * 512 + j;
        float gi = xr[0], gf = xr[128], gg = xr[256], go = xr[384];
        if (s > 0) {
            gi += gsm[pp * 132 + jj];
            gf += gsm[pp * 132 + 32 + jj];
            gg += gsm[pp * 132 + 64 + jj];
            go += gsm[pp * 132 + 96 + jj];
        }
        size_t hidx = (size_t)p * 128 + j;
        float cold = (s == 0) ? 0.0f : cD[hidx];
        float cn = sigf(gf) * cold + sigf(gi) * tanhfast(gg);
        float hn = sigf(go) * tanhfast(cn);
        if (s == TSEQ - 1) {
            float hs = hsD[hidx] + hn;
            g_sentpres[(size_t)p * 256 + dir * 128 + j] = tanhfast(hs * (1.0f / 50.0f));
        } else {
            cD[hidx] = cn;
            hOut[hidx] = hn;
            hsD[hidx] = (s == 0) ? hn : (hsD[hidx] + hn);
        }
    }
}

// ============================================================
// Dual-half GEMM with f32x2 (modes 1-4, unchanged)
// ============================================================
template <int MODE>
__global__ void __launch_bounds__(256) gemm_dual(
    const float* __restrict__ Aparam, int M, int K, int NB,
    const float* __restrict__ B0, const float* __restrict__ B1,
    const float* __restrict__ bias0, const float* __restrict__ bias1,
    float* __restrict__ outParam)
{
    __shared__ __align__(16) u64 As2[8][128];
    __shared__ __align__(16) float Bs[8][128];

    const float* A;
    if (MODE == 1 || MODE == 2) A = g_sentpres;
    else if (MODE == 3) A = g_tag_out;
    else A = g_agg;
    (void)Aparam;

    int hsel = (blockIdx.y * 128) / NB;
    int g0 = blockIdx.y * 128 - hsel * NB;
    int m0 = blockIdx.x * 128;

    const float* B = hsel ? B1 : B0;
    const float* bias = hsel ? bias1 : bias0;

    float* out;
    if (MODE == 1) out = hsel ? g_txp1 : g_txp0;
    else if (MODE == 2 || MODE == 3) out = hsel ? g_k : g_q;
    else out = outParam;

    int tid = threadIdx.x;
    int tx = tid & 15;
    int ty = tid >> 4;
    int lr = tid >> 1;
    int lc4 = tid & 1;

    u64 acc2[8][4];
#pragma unroll
    for (int i = 0; i < 8; i++)
#pragma unroll
        for (int j = 0; j < 4; j++) acc2[i][j] = 0ULL;

    int KT = K / 8;
    const float* aPtr = A + (size_t)(m0 + lr) * K + lc4 * 4;
    const float* bPtr = B + (size_t)(g0 + lr) * K + lc4 * 4;
    float4 av = *(const float4*)(aPtr);
    float4 bv = *(const float4*)(bPtr);

    for (int kt = 0; kt < KT; kt++) {
        As2[lc4 * 4 + 0][lr] = pk2(av.x, av.x);
        As2[lc4 * 4 + 1][lr] = pk2(av.y, av.y);
        As2[lc4 * 4 + 2][lr] = pk2(av.z, av.z);
        As2[lc4 * 4 + 3][lr] = pk2(av.w, av.w);
        Bs[lc4 * 4 + 0][lr] = bv.x; Bs[lc4 * 4 + 1][lr] = bv.y;
        Bs[lc4 * 4 + 2][lr] = bv.z; Bs[lc4 * 4 + 3][lr] = bv.w;
        __syncthreads();
        if (kt + 1 < KT) {
            av = *(const float4*)(aPtr + (kt + 1) * 8);
            bv = *(const float4*)(bPtr + (kt + 1) * 8);
        }
#pragma unroll
        for (int kk = 0; kk < 8; kk++) {
            u64 b2[4];
#pragma unroll
            for (int jq = 0; jq < 4; jq++)
                b2[jq] = *(const u64*)&Bs[kk][2 * (tx + 16 * jq)];
            u64 a2[8];
#pragma unroll
            for (int i = 0; i < 8; i++) a2[i] = As2[kk][ty * 8 + i];
#pragma unroll
            for (int i = 0; i < 8; i++)
#pragma unroll
                for (int jq = 0; jq < 4; jq++)
                    fma2(acc2[i][jq], a2[i], b2[jq]);
        }
        __syncthreads();
    }

#pragma unroll
    for (int i = 0; i < 8; i++) {
        int m = m0 + ty * 8 + i;
        size_t rowbase;
        if (MODE == 1) {
            int b = m >> 6; int n = m & 63;
            rowbase = ((size_t)n * BB + b) * 512;
        } else {
            rowbase = (size_t)m * 256;
        }
#pragma unroll
        for (int jq = 0; jq < 4; jq++) {
            int g = g0 + 2 * (tx + 16 * jq);
            float lo, hi;
            up2(acc2[i][jq], lo, hi);
            float2 bb = *(const float2*)(bias + g);
            float2 o;
            o.x = lo + bb.x;
            o.y = hi + bb.y;
            if (MODE == 4) { o.x = fmaxf(o.x, 0.f); o.y = fmaxf(o.y, 0.f); }
            *(float2*)(out + rowbase + g) = o;
        }
    }
}

// ============================================================
// Persistent tag BiLSTM (unchanged)
// ============================================================
#define TAG_NBLK 8
__global__ void __launch_bounds__(256) tag_persistent(
    const float* __restrict__ W0, const float* __restrict__ W1)
{
    extern __shared__ __align__(16) char sm[];
    u64 (*Wf)[32][65] = (u64 (*)[32][65])sm;
    float (*hsf)[128] = (float (*)[128])(sm + 4 * 32 * 65 * 8);

    int dir = blockIdx.x >> 2;
    int j0 = (blockIdx.x & 3) * 32;
    const float* W = dir ? W1 : W0;
    const float* xp = dir ? g_txp1 : g_txp0;
    int tid = threadIdx.x;
    int jj = tid & 31;
    int pg = tid >> 5;
    int j = j0 + jj;

    {
        int rowId = tid >> 1;
        int g = rowId >> 5, jr = rowId & 31;
        int half = tid & 1;
        const float* wrow = W + (size_t)(g * 128 + j0 + jr) * 128 + half * 64;
        u64* dst = &Wf[g][jr][half * 32];
#pragma unroll
        for (int q = 0; q < 16; q++) {
            float4 v = *(const float4*)(wrow + q * 4);
            dst[q * 2 + 0] = pk2(v.x, v.y);
            dst[q * 2 + 1] = pk2(v.z, v.w);
        }
    }

    float creg[4] = {0.f, 0.f, 0.f, 0.f};

    for (int s = 0; s < NSEQ; s++) {
        int t = dir ? (NSEQ - 1 - s) : s;
        u64 acc2[4][4];
#pragma unroll
        for (int a = 0; a < 4; a++)
#pragma unroll
            for (int b = 0; b < 4; b++) acc2[a][b] = 0ULL;

        if (s > 0) {
            const float* hIn = g_thbuf[s & 1] + (size_t)dir * BB * 128;
#pragma unroll
            for (int i = 0; i < 4; i++) {
                int idx = tid + i * 256;
                int r = idx >> 5, c4 = idx & 31;
                *(float4*)&hsf[r][c4 * 4] =
                    *(const float4*)(hIn + (size_t)r * 128 + c4 * 4);
            }
            __syncthreads();
#pragma unroll 4
            for (int kp = 0; kp < 64; kp++) {
                u64 w0 = Wf[0][jj][kp];
                u64 w1 = Wf[1][jj][kp];
                u64 w2 = Wf[2][jj][kp];
                u64 w3 = Wf[3][jj][kp];
#pragma unroll
                for (int bb = 0; bb < 4; bb++) {
                    u64 a2 = *(const u64*)&hsf[pg * 4 + bb][kp * 2];
                    fma2(acc2[bb][0], a2, w0);
                    fma2(acc2[bb][1], a2, w1);
                    fma2(acc2[bb][2], a2, w2);
                    fma2(acc2[bb][3], a2, w3);
                }
            }
        }

        float* hOut = g_thbuf[(s + 1) & 1] + (size_t)dir * BB * 128;
#pragma unroll
        for (int bb = 0; bb < 4; bb++) {
            int b = pg * 4 + bb;
            const float* xr = xp + ((size_t)t * BB + b) * 512 + j;
            float lo, hi;
            up2(acc2[bb][0], lo, hi); float gi = lo + hi + xr[0];
            up2(acc2[bb][1], lo, hi); float gf = lo + hi + xr[128];
            up2(acc2[bb][2], lo, hi); float gg = lo + hi + xr[256];
            up2(acc2[bb][3], lo, hi); float go = lo + hi + xr[384];
            float cn = sigf(gf) * creg[bb] + sigf(gi) * tanhfast(gg);
            float hn = sigf(go) * tanhfast(cn);
            creg[bb] = cn;
            hOut[(size_t)b * 128 + j] = hn;
            g_tag_out[((size_t)b * NSEQ + t) * 256 + dir * 128 + j] = tanhfast(hn);
        }

        if (s < NSEQ - 1) {
            __syncthreads();
            if (tid == 0) {
                __threadfence();
                atomicAdd(&g_tbar, 1);
                int target = TAG_NBLK * (s + 1);
                while (*(volatile int*)&g_tbar < target) { }
                __threadfence();
            }
            __syncthreads();
        }
    }

    __syncthreads();
    if (tid == 0) {
        int old = atomicAdd(&g_tdone, 1);
        if (old == TAG_NBLK - 1) {
            g_tbar = 0;
            __threadfence();
            g_tdone = 0;
        }
    }
}

// ---------------- SPP ----------------
__global__ void __launch_bounds__(256) spp_kernel(int which) {
    int b = blockIdx.x;
    int tid = threadIdx.x;
    __shared__ float qs[64][33];
    __shared__ float ks[64][33];
    __shared__ float segs[64][8];

    float acc[16];
#pragma unroll
    for (int i = 0; i < 16; i++) acc[i] = 0.0f;
    int n = tid >> 2;
    int mBase = (tid & 3) * 16;

    for (int d0 = 0; d0 < 256; d0 += 32) {
        __syncthreads();
        for (int idx = tid; idx < 64 * 32; idx += 256) {
            int r = idx >> 5, cc = idx & 31;
            size_t gi = ((size_t)(b * 64 + r)) * 256 + d0 + cc;
            qs[r][cc] = g_q[gi];
            ks[r][cc] = g_k[gi];
        }
        __syncthreads();
#pragma unroll 4
        for (int dd = 0; dd < 32; dd++) {
            float qv = qs[n][dd];
#pragma unroll
            for (int mm = 0; mm < 16; mm++)
                acc[mm] += qv * ks[mBase + mm][dd];
        }
    }
    float s8a = -3.4e38f, s8b = -3.4e38f;
#pragma unroll
    for (int mm = 0; mm < 8; mm++)  s8a = fmaxf(s8a, acc[mm]);
#pragma unroll
    for (int mm = 8; mm < 16; mm++) s8b = fmaxf(s8b, acc[mm]);
    segs[n][(tid & 3) * 2 + 0] = s8a * 0.0625f;
    segs[n][(tid & 3) * 2 + 1] = s8b * 0.0625f;
    __syncthreads();

    if (tid < 64) {
        float e[8];
#pragma unroll
        for (int i = 0; i < 8; i++) e[i] = segs[tid][i];
        float q4[4], h2[2];
#pragma unroll
        for (int i = 0; i < 4; i++) q4[i] = fmaxf(e[2 * i], e[2 * i + 1]);
        h2[0] = fmaxf(q4[0], q4[1]);
        h2[1] = fmaxf(q4[2], q4[3]);
        float a1 = fmaxf(h2[0], h2[1]);
        float* o = (which ? g_roleFt : g_sentFt) + (size_t)(b * 64 + tid) * 15;
        o[0] = a1;
        o[1] = h2[0]; o[2] = h2[1];
#pragma unroll
        for (int i = 0; i < 4; i++) o[3 + i] = q4[i];
#pragma unroll
        for (int i = 0; i < 8; i++) o[7 + i] = e[i];
    }
}

// ---------------- GCN pre ----------------
__global__ void __launch_bounds__(256) gcn_pre() {
    int b = blockIdx.x;
    int tid = threadIdx.x;
    __shared__ float cosm[64][65];
    __shared__ float xs[64][33];
    __shared__ float inv[64];

    if (tid < 64) {
        const float* xr = g_tag_out + (size_t)(b * 64 + tid) * 256;
        float s = 0.0f;
        for (int d = 0; d < 256; d++) { float v = xr[d]; s += v * v; }
        inv[tid] = 1.0f / (sqrtf(s) + 1e-8f);
    }

    float acc[16];
#pragma unroll
    for (int i = 0; i < 16; i++) acc[i] = 0.0f;
    int n = tid >> 2;
    int mBase = (tid & 3) * 16;

    for (int d0 = 0; d0 < 256; d0 += 32) {
        __syncthreads();
        for (int idx = tid; idx < 64 * 32; idx += 256) {
            int r = idx >> 5, cc = idx & 31;
            xs[r][cc] = g_tag_out[((size_t)(b * 64 + r)) * 256 + d0 + cc];
        }
        __syncthreads();
#pragma unroll 4
        for (int dd = 0; dd < 32; dd++) {
            float xv = xs[n][dd];
#pragma unroll
            for (int mm = 0; mm < 16; mm++)
                acc[mm] += xv * xs[mBase + mm][dd];
        }
    }
#pragma unroll
    for (int mm = 0; mm < 16; mm++)
        cosm[n][mBase + mm] = acc[mm] * inv[n] * inv[mBase + mm];

    int ddBase = (tid & 3) * 8;
    for (int d0 = 0; d0 < 256; d0 += 32) {
        __syncthreads();
        for (int idx = tid; idx < 64 * 32; idx += 256) {
            int r = idx >> 5, cc = idx & 31;
            xs[r][cc] = g_tag_out[((size_t)(b * 64 + r)) * 256 + d0 + cc];
        }
        __syncthreads();
        float r8[8];
#pragma unroll
        for (int i = 0; i < 8; i++) r8[i] = 0.0f;
        for (int m = 0; m < 64; m++) {
            float cv = cosm[n][m];
#pragma unroll
            for (int i = 0; i < 8; i++) r8[i] += cv * xs[m][ddBase + i];
        }
#pragma unroll
        for (int i = 0; i < 8; i++) {
            float v = (r8[i] + 2.0f * xs[n][ddBase + i]) * (1.0f / 66.0f);
            g_agg[(size_t)(b * 64 + n) * 256 + d0 + ddBase + i] = v;
        }
    }
}

// ---------------- classifier + log_softmax ----------------
__global__ void __launch_bounds__(256) cls_kernel(
    const float* __restrict__ W, const float* __restrict__ bias,
    float* __restrict__ out)
{
    __shared__ float Wsh[8][288];
    __shared__ float bsh[8];
    __shared__ float ftile[256][33];

    int tid = threadIdx.x;
    for (int i = tid; i < 8 * 286; i += 256) Wsh[i / 286][i % 286] = W[i];
    if (tid < 8) bsh[tid] = bias[tid];
    __syncthreads();

    int p0 = blockIdx.x * 256;
    int p = p0 + tid;
    float z[8];
#pragma unroll
    for (int c = 0; c < 8; c++) z[c] = bsh[c];

    for (int d0 = 0; d0 < 256; d0 += 32) {
        __syncthreads();
        for (int idx = tid; idx < 256 * 32; idx += 256) {
            int r = idx >> 5, cc = idx & 31;
            ftile[r][cc] = g_tag_out[(size_t)(p0 + r) * 256 + d0 + cc];
        }
        __syncthreads();
#pragma unroll 4
        for (int dd = 0; dd < 32; dd++) {
            float f = ftile[tid][dd];
#pragma unroll
            for (int c = 0; c < 8; c++) z[c] += f * Wsh[c][d0 + dd];
        }
    }
#pragma unroll
    for (int d = 0; d < 15; d++) {
        float f = g_sentFt[(size_t)p * 15 + d];
#pragma unroll
        for (int c = 0; c < 8; c++) z[c] += f * Wsh[c][256 + d];
    }
#pragma unroll
    for (int d = 0; d < 15; d++) {
        float f = g_roleFt[(size_t)p * 15 + d];
#pragma unroll
        for (int c = 0; c < 8; c++) z[c] += f * Wsh[c][271 + d];
    }
    float m = z[0];
#pragma unroll
    for (int c = 1; c < 8; c++) m = fmaxf(m, z[c]);
    float se = 0.0f;
#pragma unroll
    for (int c = 0; c < 8; c++) se += expf(z[c] - m);
    float lse = m + logf(se);
#pragma unroll
    for (int c = 0; c < 8; c++) out[(size_t)p * 8 + c] = z[c] - lse;
}

// ============================================================
extern "C" void kernel_launch(void* const* d_in, const int* in_sizes, int n_in,
                              void* d_out, int out_size)
{
    (void)in_sizes; (void)n_in; (void)out_size;
    const float* documents = (const float*)d_in[0];
    const float* sw_ih_f = (const float*)d_in[1];
    const float* sw_hh_f = (const float*)d_in[2];
    const float* sb_f    = (const float*)d_in[3];
    const float* sw_ih_b = (const float*)d_in[4];
    const float* sw_hh_b = (const float*)d_in[5];
    const float* sb_b    = (const float*)d_in[6];
    const float* sf_Wq   = (const float*)d_in[7];
    const float* sf_bq   = (const float*)d_in[8];
    const float* sf_Wk   = (const float*)d_in[9];
    const float* sf_bk   = (const float*)d_in[10];
    const float* rf_Wq   = (const float*)d_in[11];
    const float* rf_bq   = (const float*)d_in[12];
    const float* rf_Wk   = (const float*)d_in[13];
    const float* rf_bk   = (const float*)d_in[14];
    const float* tw_ih_f = (const float*)d_in[15];
    const float* tw_hh_f = (const float*)d_in[16];
    const float* tb_f    = (const float*)d_in[17];
    const float* tw_ih_b = (const float*)d_in[18];
    const float* tw_hh_b = (const float*)d_in[19];
    const float* tb_b    = (const float*)d_in[20];
    const float* sage_W  = (const float*)d_in[21];
    const float* sage_b  = (const float*)d_in[22];
    const float* cls_W   = (const float*)d_in[23];
    const float* cls_b   = (const float*)d_in[24];
    float* out = (float*)d_out;

    const int TAG_SMEM = 4 * 32 * 65 * 8 + 32 * 128 * 4;   // 82944
    cudaFuncSetAttribute(lstm_sent4, cudaFuncAttributeMaxDynamicSharedMemorySize, S4_SMEM);
    cudaFuncSetAttribute(tag_persistent, cudaFuncAttributeMaxDynamicSharedMemorySize, TAG_SMEM);

    // 1) sentence BiLSTM input projection: tensor cores, 3xTF32
    gemm_inproj_tc<<<dim3(800, 8), 256>>>(documents, sw_ih_f, sw_ih_b, sb_f, sb_b);
    // 2) sentence recurrence: tensor-core steps (sentpres folded into s=49)
    for (int s = 0; s < TSEQ; s++)
        lstm_sent4<<<dim3(16, 4, 2), 256, S4_SMEM>>>(sw_hh_f, sw_hh_b, s);
    // 3) tag BiLSTM input projection
    gemm_dual<1><<<dim3(16, 8), 256>>>(nullptr, 2048, 256, 512,
                                       tw_ih_f, tw_ih_b, tb_f, tb_b, nullptr);
    // 4) tag recurrence: persistent kernel
    tag_persistent<<<TAG_NBLK, 256, TAG_SMEM>>>(tw_hh_f, tw_hh_b);
    // 5) SPP on sentpres -> sentFt
    gemm_dual<2><<<dim3(16, 4), 256>>>(nullptr, 2048, 256, 256,
                                       sf_Wq, sf_Wk, sf_bq, sf_bk, nullptr);
    spp_kernel<<<32, 256>>>(0);
    // 6) SPP on tag_out -> roleFt
    gemm_dual<3><<<dim3(16, 4), 256>>>(nullptr, 2048, 256, 256,
                                       rf_Wq, rf_Wk, rf_bq, rf_bk, nullptr);
    spp_kernel<<<32, 256>>>(1);
    // 7) GCN
    gcn_pre<<<32, 256>>>();
    gemm_dual<4><<<dim3(16, 2), 256>>>(nullptr, 2048, 256, 256,
                                       sage_W, sage_W, sage_b, sage_b, out + 16384);
    // 8) classifier + log_softmax
    cls_kernel<<<8, 256>>>(cls_W, cls_b, out);
}

// round 7
// speedup vs baseline: 1.4679x; 1.0538x over previous
#include <cuda_runtime.h>
#include <math.h>
#include <stdint.h>

typedef unsigned long long u64;
typedef unsigned int u32;

// ---------------- problem constants ----------------
#define BN   2048
#define TSEQ 50
#define NSEQ 64
#define BB   32

// ---------------- device scratch ----------------
__device__ float g_xp0[(size_t)TSEQ * BN * 512];
__device__ float g_xp1[(size_t)TSEQ * BN * 512];
__device__ float g_hbuf[2][2 * BN * 128];
__device__ float g_cst[2 * BN * 128];
__device__ float g_hsum[2 * BN * 128];
__device__ float g_sentpres[(size_t)BN * 256];
__device__ float g_txp0[(size_t)NSEQ * BB * 512];
__device__ float g_txp1[(size_t)NSEQ * BB * 512];
__device__ float g_thbuf[2][2 * BB * 128];
__device__ float g_tag_out[(size_t)BN * 256];
__device__ float g_q[(size_t)BN * 256];
__device__ float g_k[(size_t)BN * 256];
__device__ float g_sentFt[(size_t)BN * 15];
__device__ float g_roleFt[(size_t)BN * 15];
__device__ float g_agg[(size_t)BN * 256];
__device__ int g_tbar;
__device__ int g_tdone;
__device__ int g_sbar[32];
__device__ int g_sdone[32];

// ---------------- f32x2 helpers ----------------
__device__ __forceinline__ u64 pk2(float lo, float hi) {
    u64 r; asm("mov.b64 %0, {%1, %2};" : "=l"(r) : "f"(lo), "f"(hi)); return r;
}
__device__ __forceinline__ void up2(u64 v, float& lo, float& hi) {
    asm("mov.b64 {%0, %1}, %2;" : "=f"(lo), "=f"(hi) : "l"(v));
}
__device__ __forceinline__ void fma2(u64& d, u64 a, u64 b) {
    asm("fma.rn.f32x2 %0, %1, %2, %0;" : "+l"(d) : "l"(a), "l"(b));
}

// ---------------- tf32 helpers ----------------
__device__ __forceinline__ float tf32_rna(float x) {
    u32 u; asm("cvt.rna.tf32.f32 %0, %1;" : "=r"(u) : "f"(x));
    return __uint_as_float(u);
}
__device__ __forceinline__ void mma_tf32(float* d, const u32* a, const u32* b) {
    asm("mma.sync.aligned.m16n8k8.row.col.f32.tf32.tf32.f32 "
        "{%0,%1,%2,%3},{%4,%5,%6,%7},{%8,%9},{%0,%1,%2,%3};"
        : "+f"(d[0]), "+f"(d[1]), "+f"(d[2]), "+f"(d[3])
        : "r"(a[0]), "r"(a[1]), "r"(a[2]), "r"(a[3]), "r"(b[0]), "r"(b[1]));
}

// ---------------- fast math ----------------
__device__ __forceinline__ float sigf(float x) {
    x = fminf(fmaxf(x, -30.f), 30.f);
    return __fdividef(1.f, 1.f + __expf(-x));
}
__device__ __forceinline__ float tanhfast(float x) {
    x = fminf(fmaxf(x, -15.f), 15.f);
    return __fdividef(2.f, 1.f + __expf(-2.f * x)) - 1.f;
}

// ============================================================
// K1: sentence input projection with tensor cores (3xTF32).
// (unchanged — validated)
// ============================================================
#define K1P 12
__global__ void __launch_bounds__(256) gemm_inproj_tc(
    const float* __restrict__ A,
    const float* __restrict__ B0, const float* __restrict__ B1,
    const float* __restrict__ bias0, const float* __restrict__ bias1)
{
    __shared__ float sAh[2][128 * K1P], sAl[2][128 * K1P];
    __shared__ float sBh[2][128 * K1P], sBl[2][128 * K1P];

    int m0 = blockIdx.x * 128;
    int nb = blockIdx.y;
    int dir = nb >> 2;
    int n0 = (nb & 3) * 128;
    const float* Bw = dir ? B1 : B0;
    const float* bias = dir ? bias1 : bias0;
    float* out = dir ? g_xp1 : g_xp0;

    int tid = threadIdx.x;
    int lane = tid & 31, warp = tid >> 5;
    int g = lane >> 2, tig = lane & 3;
    int wm = warp & 1, wn = warp >> 1;

    int srow = tid >> 1, shalf = tid & 1;
    const float* aP = A + (size_t)(m0 + srow) * 200 + shalf * 4;
    const float* bP = Bw + (size_t)(n0 + srow) * 200 + shalf * 4;

    float acc[4][4][4];
#pragma unroll
    for (int i = 0; i < 4; i++)
#pragma unroll
        for (int j = 0; j < 4; j++)
#pragma unroll
            for (int c = 0; c < 4; c++) acc[i][j][c] = 0.0f;

    float4 av = *(const float4*)aP;
    float4 bv = *(const float4*)bP;

    int soff = srow * K1P + shalf * 4;
#define K1_STAGE(buf, a4, b4) do {                                          \
        float4 _h, _l;                                                      \
        _h.x = tf32_rna(a4.x); _l.x = tf32_rna(a4.x - _h.x);                \
        _h.y = tf32_rna(a4.y); _l.y = tf32_rna(a4.y - _h.y);                \
        _h.z = tf32_rna(a4.z); _l.z = tf32_rna(a4.z - _h.z);                \
        _h.w = tf32_rna(a4.w); _l.w = tf32_rna(a4.w - _h.w);                \
        *(float4*)&sAh[buf][soff] = _h;                                     \
        *(float4*)&sAl[buf][soff] = _l;                                     \
        _h.x = tf32_rna(b4.x); _l.x = tf32_rna(b4.x - _h.x);                \
        _h.y = tf32_rna(b4.y); _l.y = tf32_rna(b4.y - _h.y);                \
        _h.z = tf32_rna(b4.z); _l.z = tf32_rna(b4.z - _h.z);                \
        _h.w = tf32_rna(b4.w); _l.w = tf32_rna(b4.w - _h.w);                \
        *(float4*)&sBh[buf][soff] = _h;                                     \
        *(float4*)&sBl[buf][soff] = _l;                                     \
    } while (0)

    K1_STAGE(0, av, bv);
    __syncthreads();

    for (int kt = 0; kt < 25; kt++) {
        int cur = kt & 1;
        if (kt < 24) {
            av = *(const float4*)(aP + (kt + 1) * 8);
            bv = *(const float4*)(bP + (kt + 1) * 8);
        }
        u32 bh[4][2], bl[4][2];
#pragma unroll
        for (int nt = 0; nt < 4; nt++) {
            int br = (wn * 32 + nt * 8 + g) * K1P;
            bh[nt][0] = __float_as_uint(sBh[cur][br + tig]);
            bh[nt][1] = __float_as_uint(sBh[cur][br + tig + 4]);
            bl[nt][0] = __float_as_uint(sBl[cur][br + tig]);
            bl[nt][1] = __float_as_uint(sBl[cur][br + tig + 4]);
        }
#pragma unroll
        for (int mt = 0; mt < 4; mt++) {
            int ar0 = (wm * 64 + mt * 16 + g) * K1P;
            int ar1 = ar0 + 8 * K1P;
            u32 ah[4], al[4];
            ah[0] = __float_as_uint(sAh[cur][ar0 + tig]);
            ah[1] = __float_as_uint(sAh[cur][ar1 + tig]);
            ah[2] = __float_as_uint(sAh[cur][ar0 + tig + 4]);
            ah[3] = __float_as_uint(sAh[cur][ar1 + tig + 4]);
            al[0] = __float_as_uint(sAl[cur][ar0 + tig]);
            al[1] = __float_as_uint(sAl[cur][ar1 + tig]);
            al[2] = __float_as_uint(sAl[cur][ar0 + tig + 4]);
            al[3] = __float_as_uint(sAl[cur][ar1 + tig + 4]);
#pragma unroll
            for (int nt = 0; nt < 4; nt++) {
                mma_tf32(acc[mt][nt], ah, bh[nt]);
                mma_tf32(acc[mt][nt], al, bh[nt]);
                mma_tf32(acc[mt][nt], ah, bl[nt]);
            }
        }
        __syncthreads();
        if (kt < 24) {
            K1_STAGE((kt + 1) & 1, av, bv);
            __syncthreads();
        }
    }

#pragma unroll
    for (int mt = 0; mt < 4; mt++) {
#pragma unroll
        for (int nt = 0; nt < 4; nt++) {
            int col = n0 + wn * 32 + nt * 8 + 2 * tig;
            float b0v = __ldg(bias + col), b1v = __ldg(bias + col + 1);
            int r0 = m0 + wm * 64 + mt * 16 + g;
            int p0 = r0 / 50, t0 = r0 - p0 * 50;
            float2 o0 = make_float2(acc[mt][nt][0] + b0v, acc[mt][nt][1] + b1v);
            *(float2*)(out + ((size_t)t0 * BN + p0) * 512 + col) = o0;
            int r1 = r0 + 8;
            int p1 = r1 / 50, t1 = r1 - p1 * 50;
            float2 o1 = make_float2(acc[mt][nt][2] + b0v, acc[mt][nt][3] + b1v);
            *(float2*)(out + ((size_t)t1 * BN + p1) * 512 + col) = o1;
        }
    }
}

// ============================================================
// Sentence LSTM: PERSISTENT tensor-core recurrence.
// 128 blocks (16 pch x 4 jch x 2 dir), all co-resident, loop s=0..49.
// W hi/lo staged in smem ONCE (stride 132). h chunks (K=32) hi/lo,
// double-buffered (stride 36), prefetch overlapped with mma.
// Group barrier: 4 blocks sharing (pch,dir) sync via g_sbar[pch*2+dir].
// smem: W 2*128*132 + h 2*2*128*36 floats = 208896 B.
// ============================================================
#define S5_WST   132
#define S5_HST   36
#define S5_WSZ   (128 * S5_WST)            // one W array (floats)
#define S5_HBUF  (2 * 128 * S5_HST)        // one h buffer hi+lo (floats)
#define S5_SMEM  ((2 * S5_WSZ + 2 * S5_HBUF) * 4)

__global__ void __launch_bounds__(256, 1) lstm_sent5(
    const float* __restrict__ W0, const float* __restrict__ W1)
{
    extern __shared__ __align__(16) float s5[];
    float* sWh = s5;
    float* sWl = s5 + S5_WSZ;
    float* sH  = s5 + 2 * S5_WSZ;          // [buf][hi(128*36) | lo(128*36)]
    float* gsm = sH;                        // aliased gate out [128][132]

    int bid = blockIdx.x;
    int dir = bid >> 6;
    int rem = bid & 63;
    int pch = rem >> 2;
    int jch = rem & 3;
    int p0 = pch * 128;
    int j0 = jch * 32;
    int barIdx = pch * 2 + dir;

    const float* W = dir ? W1 : W0;
    const float* xp = dir ? g_xp1 : g_xp0;
    float* cD = g_cst + (size_t)dir * BN * 128;
    float* hsD = g_hsum + (size_t)dir * BN * 128;

    int tid = threadIdx.x;
    int lane = tid & 31, warp = tid >> 5;
    int g = lane >> 2, tig = lane & 3;
    int wm = warp & 1, wn = warp >> 1;     // wn = gate

    // ---- stage W hi/lo ONCE ----
    {
        int row = tid >> 1;                 // 0..127 = gate*32 + jr
        int gg = row >> 5, jr = row & 31;
        int half = tid & 1;
        const float* wrow = W + (size_t)(gg * 128 + j0 + jr) * 128 + half * 64;
        int so = row * S5_WST + half * 64;
#pragma unroll
        for (int q = 0; q < 16; q++) {
            float4 v = *(const float4*)(wrow + q * 4);
            float4 h4, l4;
            h4.x = tf32_rna(v.x); l4.x = tf32_rna(v.x - h4.x);
            h4.y = tf32_rna(v.y); l4.y = tf32_rna(v.y - h4.y);
            h4.z = tf32_rna(v.z); l4.z = tf32_rna(v.z - h4.z);
            h4.w = tf32_rna(v.w); l4.w = tf32_rna(v.w - h4.w);
            *(float4*)&sWh[so + q * 4] = h4;
            *(float4*)&sWl[so + q * 4] = l4;
        }
    }
    __syncthreads();

    int srow = tid >> 1;                    // h stage row 0..127
    int shalf = tid & 1;                    // k offset 0/16

    for (int s = 0; s < TSEQ; s++) {
        int t = dir ? (TSEQ - 1 - s) : s;

        if (s > 0) {
            const float* hIn = g_hbuf[s & 1] + (size_t)dir * BN * 128;
            const float* aRow = hIn + (size_t)(p0 + srow) * 128 + shalf * 16;
            int hso = srow * S5_HST + shalf * 16;

            float acc[4][4][4];
#pragma unroll
            for (int i = 0; i < 4; i++)
#pragma unroll
                for (int j = 0; j < 4; j++)
#pragma unroll
                    for (int c = 0; c < 4; c++) acc[i][j][c] = 0.0f;

            // stage chunk 0 into buf 0
            {
                float* dh = sH + 0 * S5_HBUF;
                float* dl = dh + 128 * S5_HST;
#pragma unroll
                for (int q = 0; q < 4; q++) {
                    float4 v = *(const float4*)(aRow + q * 4);
                    float4 h4, l4;
                    h4.x = tf32_rna(v.x); l4.x = tf32_rna(v.x - h4.x);
                    h4.y = tf32_rna(v.y); l4.y = tf32_rna(v.y - h4.y);
                    h4.z = tf32_rna(v.z); l4.z = tf32_rna(v.z - h4.z);
                    h4.w = tf32_rna(v.w); l4.w = tf32_rna(v.w - h4.w);
                    *(float4*)&dh[hso + q * 4] = h4;
                    *(float4*)&dl[hso + q * 4] = l4;
                }
            }
            __syncthreads();

#pragma unroll
            for (int kc = 0; kc < 4; kc++) {
                int cur = kc & 1;
                // prefetch next chunk
                float4 pre[4];
                if (kc < 3) {
#pragma unroll
                    for (int q = 0; q < 4; q++)
                        pre[q] = *(const float4*)(aRow + (kc + 1) * 32 + q * 4);
                }
                // mma on chunk kc
                const float* bh_base = sWh;
                const float* bl_base = sWl;
                const float* ah_base = sH + cur * S5_HBUF;
                const float* al_base = ah_base + 128 * S5_HST;
#pragma unroll
                for (int kt = 0; kt < 4; kt++) {
                    int kbW = kc * 32 + kt * 8;
                    int kbH = kt * 8;
                    u32 bh[4][2], bl[4][2];
#pragma unroll
                    for (int nt = 0; nt < 4; nt++) {
                        int br = (wn * 32 + nt * 8 + g) * S5_WST + kbW;
                        bh[nt][0] = __float_as_uint(bh_base[br + tig]);
                        bh[nt][1] = __float_as_uint(bh_base[br + tig + 4]);
                        bl[nt][0] = __float_as_uint(bl_base[br + tig]);
                        bl[nt][1] = __float_as_uint(bl_base[br + tig + 4]);
                    }
#pragma unroll
                    for (int mt = 0; mt < 4; mt++) {
                        int ar0 = (wm * 64 + mt * 16 + g) * S5_HST + kbH;
                        int ar1 = ar0 + 8 * S5_HST;
                        u32 ah[4], al[4];
                        ah[0] = __float_as_uint(ah_base[ar0 + tig]);
                        ah[1] = __float_as_uint(ah_base[ar1 + tig]);
                        ah[2] = __float_as_uint(ah_base[ar0 + tig + 4]);
                        ah[3] = __float_as_uint(ah_base[ar1 + tig + 4]);
                        al[0] = __float_as_uint(al_base[ar0 + tig]);
                        al[1] = __float_as_uint(al_base[ar1 + tig]);
                        al[2] = __float_as_uint(al_base[ar0 + tig + 4]);
                        al[3] = __float_as_uint(al_base[ar1 + tig + 4]);
#pragma unroll
                        for (int nt = 0; nt < 4; nt++) {
                            mma_tf32(acc[mt][nt], ah, bh[nt]);
                            mma_tf32(acc[mt][nt], al, bh[nt]);
                            mma_tf32(acc[mt][nt], ah, bl[nt]);
                        }
                    }
                }
                // store prefetched chunk into other buffer
                if (kc < 3) {
                    float* dh = sH + (1 - cur) * S5_HBUF;
                    float* dl = dh + 128 * S5_HST;
#pragma unroll
                    for (int q = 0; q < 4; q++) {
                        float4 v = pre[q];
                        float4 h4, l4;
                        h4.x = tf32_rna(v.x); l4.x = tf32_rna(v.x - h4.x);
                        h4.y = tf32_rna(v.y); l4.y = tf32_rna(v.y - h4.y);
                        h4.z = tf32_rna(v.z); l4.z = tf32_rna(v.z - h4.z);
                        h4.w = tf32_rna(v.w); l4.w = tf32_rna(v.w - h4.w);
                        *(float4*)&dh[hso + q * 4] = h4;
                        *(float4*)&dl[hso + q * 4] = l4;
                    }
                }
                __syncthreads();
            }

            // write gates to gsm (aliases h buffers; all mma complete)
#pragma unroll
            for (int mt = 0; mt < 4; mt++) {
                int r0 = wm * 64 + mt * 16 + g;
#pragma unroll
                for (int nt = 0; nt < 4; nt++) {
                    int col = wn * 32 + nt * 8 + 2 * tig;
                    *(float2*)&gsm[r0 * 132 + col] =
                        make_float2(acc[mt][nt][0], acc[mt][nt][1]);
                    *(float2*)&gsm[(r0 + 8) * 132 + col] =
                        make_float2(acc[mt][nt][2], acc[mt][nt][3]);
                }
            }
            __syncthreads();
        }

        // ---- fused LSTM epilogue ----
        float* hOut = g_hbuf[(s + 1) & 1] + (size_t)dir * BN * 128;
        size_t xbase = (size_t)t * BN * 512;
#pragma unroll
        for (int i = 0; i < 16; i++) {
            int pj = tid + i * 256;
            int pp = pj >> 5, jj = pj & 31;
            int p = p0 + pp;
            int j = j0 + jj;
            const float* xr = xp + xbase + (size_t)p * 512 + j;
            float gi = xr[0], gf = xr[128], gg2 = xr[256], go = xr[384];
            if (s > 0) {
                gi  += gsm[pp * 132 + jj];
                gf  += gsm[pp * 132 + 32 + jj];
                gg2 += gsm[pp * 132 + 64 + jj];
                go  += gsm[pp * 132 + 96 + jj];
            }
            size_t hidx = (size_t)p * 128 + j;
            float cold = (s == 0) ? 0.0f : cD[hidx];
            float cn = sigf(gf) * cold + sigf(gi) * tanhfast(gg2);
            float hn = sigf(go) * tanhfast(cn);
            if (s == TSEQ - 1) {
                float hs = hsD[hidx] + hn;
                g_sentpres[(size_t)p * 256 + dir * 128 + j] =
                    tanhfast(hs * (1.0f / 50.0f));
            } else {
                cD[hidx] = cn;
                hOut[hidx] = hn;
                hsD[hidx] = (s == 0) ? hn : (hsD[hidx] + hn);
            }
        }

        if (s < TSEQ - 1) {
            // group barrier: 4 blocks sharing (pch, dir)
            __syncthreads();
            if (tid == 0) {
                __threadfence();
                atomicAdd(&g_sbar[barIdx], 1);
                int target = 4 * (s + 1);
                while (*(volatile int*)&g_sbar[barIdx] < target) { }
                __threadfence();
            }
            __syncthreads();
        }
    }

    // deterministic counter reset for next graph replay
    __syncthreads();
    if (tid == 0) {
        int old = atomicAdd(&g_sdone[barIdx], 1);
        if (old == 3) {
            g_sbar[barIdx] = 0;
            __threadfence();
            g_sdone[barIdx] = 0;
        }
    }
}

// ============================================================
// Dual-half GEMM with f32x2 (modes 1-4, unchanged)
// ============================================================
template <int MODE>
__global__ void __launch_bounds__(256) gemm_dual(
    const float* __restrict__ Aparam, int M, int K, int NB,
    const float* __restrict__ B0, const float* __restrict__ B1,
    const float* __restrict__ bias0, const float* __restrict__ bias1,
    float* __restrict__ outParam)
{
    __shared__ __align__(16) u64 As2[8][128];
    __shared__ __align__(16) float Bs[8][128];

    const float* A;
    if (MODE == 1 || MODE == 2) A = g_sentpres;
    else if (MODE == 3) A = g_tag_out;
    else A = g_agg;
    (void)Aparam;

    int hsel = (blockIdx.y * 128) / NB;
    int g0 = blockIdx.y * 128 - hsel * NB;
    int m0 = blockIdx.x * 128;

    const float* B = hsel ? B1 : B0;
    const float* bias = hsel ? bias1 : bias0;

    float* out;
    if (MODE == 1) out = hsel ? g_txp1 : g_txp0;
    else if (MODE == 2 || MODE == 3) out = hsel ? g_k : g_q;
    else out = outParam;

    int tid = threadIdx.x;
    int tx = tid & 15;
    int ty = tid >> 4;
    int lr = tid >> 1;
    int lc4 = tid & 1;

    u64 acc2[8][4];
#pragma unroll
    for (int i = 0; i < 8; i++)
#pragma unroll
        for (int j = 0; j < 4; j++) acc2[i][j] = 0ULL;

    int KT = K / 8;
    const float* aPtr = A + (size_t)(m0 + lr) * K + lc4 * 4;
    const float* bPtr = B + (size_t)(g0 + lr) * K + lc4 * 4;
    float4 av = *(const float4*)(aPtr);
    float4 bv = *(const float4*)(bPtr);

    for (int kt = 0; kt < KT; kt++) {
        As2[lc4 * 4 + 0][lr] = pk2(av.x, av.x);
        As2[lc4 * 4 + 1][lr] = pk2(av.y, av.y);
        As2[lc4 * 4 + 2][lr] = pk2(av.z, av.z);
        As2[lc4 * 4 + 3][lr] = pk2(av.w, av.w);
        Bs[lc4 * 4 + 0][lr] = bv.x; Bs[lc4 * 4 + 1][lr] = bv.y;
        Bs[lc4 * 4 + 2][lr] = bv.z; Bs[lc4 * 4 + 3][lr] = bv.w;
        __syncthreads();
        if (kt + 1 < KT) {
            av = *(const float4*)(aPtr + (kt + 1) * 8);
            bv = *(const float4*)(bPtr + (kt + 1) * 8);
        }
#pragma unroll
        for (int kk = 0; kk < 8; kk++) {
            u64 b2[4];
#pragma unroll
            for (int jq = 0; jq < 4; jq++)
                b2[jq] = *(const u64*)&Bs[kk][2 * (tx + 16 * jq)];
            u64 a2[8];
#pragma unroll
            for (int i = 0; i < 8; i++) a2[i] = As2[kk][ty * 8 + i];
#pragma unroll
            for (int i = 0; i < 8; i++)
#pragma unroll
                for (int jq = 0; jq < 4; jq++)
                    fma2(acc2[i][jq], a2[i], b2[jq]);
        }
        __syncthreads();
    }

#pragma unroll
    for (int i = 0; i < 8; i++) {
        int m = m0 + ty * 8 + i;
        size_t rowbase;
        if (MODE == 1) {
            int b = m >> 6; int n = m & 63;
            rowbase = ((size_t)n * BB + b) * 512;
        } else {
            rowbase = (size_t)m * 256;
        }
#pragma unroll
        for (int jq = 0; jq < 4; jq++) {
            int g = g0 + 2 * (tx + 16 * jq);
            float lo, hi;
            up2(acc2[i][jq], lo, hi);
            float2 bb = *(const float2*)(bias + g);
            float2 o;
            o.x = lo + bb.x;
            o.y = hi + bb.y;
            if (MODE == 4) { o.x = fmaxf(o.x, 0.f); o.y = fmaxf(o.y, 0.f); }
            *(float2*)(out + rowbase + g) = o;
        }
    }
}

// ============================================================
// Persistent tag BiLSTM (unchanged)
// ============================================================
#define TAG_NBLK 8
__global__ void __launch_bounds__(256) tag_persistent(
    const float* __restrict__ W0, const float* __restrict__ W1)
{
    extern __shared__ __align__(16) char sm[];
    u64 (*Wf)[32][65] = (u64 (*)[32][65])sm;
    float (*hsf)[128] = (float (*)[128])(sm + 4 * 32 * 65 * 8);

    int dir = blockIdx.x >> 2;
    int j0 = (blockIdx.x & 3) * 32;
    const float* W = dir ? W1 : W0;
    const float* xp = dir ? g_txp1 : g_txp0;
    int tid = threadIdx.x;
    int jj = tid & 31;
    int pg = tid >> 5;
    int j = j0 + jj;

    {
        int rowId = tid >> 1;
        int g = rowId >> 5, jr = rowId & 31;
        int half = tid & 1;
        const float* wrow = W + (size_t)(g * 128 + j0 + jr) * 128 + half * 64;
        u64* dst = &Wf[g][jr][half * 32];
#pragma unroll
        for (int q = 0; q < 16; q++) {
            float4 v = *(const float4*)(wrow + q * 4);
            dst[q * 2 + 0] = pk2(v.x, v.y);
            dst[q * 2 + 1] = pk2(v.z, v.w);
        }
    }

    float creg[4] = {0.f, 0.f, 0.f, 0.f};

    for (int s = 0; s < NSEQ; s++) {
        int t = dir ? (NSEQ - 1 - s) : s;
        u64 acc2[4][4];
#pragma unroll
        for (int a = 0; a < 4; a++)
#pragma unroll
            for (int b = 0; b < 4; b++) acc2[a][b] = 0ULL;

        if (s > 0) {
            const float* hIn = g_thbuf[s & 1] + (size_t)dir * BB * 128;
#pragma unroll
            for (int i = 0; i < 4; i++) {
                int idx = tid + i * 256;
                int r = idx >> 5, c4 = idx & 31;
                *(float4*)&hsf[r][c4 * 4] =
                    *(const float4*)(hIn + (size_t)r * 128 + c4 * 4);
            }
            __syncthreads();
#pragma unroll 4
            for (int kp = 0; kp < 64; kp++) {
                u64 w0 = Wf[0][jj][kp];
                u64 w1 = Wf[1][jj][kp];
                u64 w2 = Wf[2][jj][kp];
                u64 w3 = Wf[3][jj][kp];
#pragma unroll
                for (int bb = 0; bb < 4; bb++) {
                    u64 a2 = *(const u64*)&hsf[pg * 4 + bb][kp * 2];
                    fma2(acc2[bb][0], a2, w0);
                    fma2(acc2[bb][1], a2, w1);
                    fma2(acc2[bb][2], a2, w2);
                    fma2(acc2[bb][3], a2, w3);
                }
            }
        }

        float* hOut = g_thbuf[(s + 1) & 1] + (size_t)dir * BB * 128;
#pragma unroll
        for (int bb = 0; bb < 4; bb++) {
            int b = pg * 4 + bb;
            const float* xr = xp + ((size_t)t * BB + b) * 512 + j;
            float lo, hi;
            up2(acc2[bb][0], lo, hi); float gi = lo + hi + xr[0];
            up2(acc2[bb][1], lo, hi); float gf = lo + hi + xr[128];
            up2(acc2[bb][2], lo, hi); float gg = lo + hi + xr[256];
            up2(acc2[bb][3], lo, hi); float go = lo + hi + xr[384];
            float cn = sigf(gf) * creg[bb] + sigf(gi) * tanhfast(gg);
            float hn = sigf(go) * tanhfast(cn);
            creg[bb] = cn;
            hOut[(size_t)b * 128 + j] = hn;
            g_tag_out[((size_t)b * NSEQ + t) * 256 + dir * 128 + j] = tanhfast(hn);
        }

        if (s < NSEQ - 1) {
            __syncthreads();
            if (tid == 0) {
                __threadfence();
                atomicAdd(&g_tbar, 1);
                int target = TAG_NBLK * (s + 1);
                while (*(volatile int*)&g_tbar < target) { }
                __threadfence();
            }
            __syncthreads();
        }
    }

    __syncthreads();
    if (tid == 0) {
        int old = atomicAdd(&g_tdone, 1);
        if (old == TAG_NBLK - 1) {
            g_tbar = 0;
            __threadfence();
            g_tdone = 0;
        }
    }
}

// ---------------- SPP ----------------
__global__ void __launch_bounds__(256) spp_kernel(int which) {
    int b = blockIdx.x;
    int tid = threadIdx.x;
    __shared__ float qs[64][33];
    __shared__ float ks[64][33];
    __shared__ float segs[64][8];

    float acc[16];
#pragma unroll
    for (int i = 0; i < 16; i++) acc[i] = 0.0f;
    int n = tid >> 2;
    int mBase = (tid & 3) * 16;

    for (int d0 = 0; d0 < 256; d0 += 32) {
        __syncthreads();
        for (int idx = tid; idx < 64 * 32; idx += 256) {
            int r = idx >> 5, cc = idx & 31;
            size_t gi = ((size_t)(b * 64 + r)) * 256 + d0 + cc;
            qs[r][cc] = g_q[gi];
            ks[r][cc] = g_k[gi];
        }
        __syncthreads();
#pragma unroll 4
        for (int dd = 0; dd < 32; dd++) {
            float qv = qs[n][dd];
#pragma unroll
            for (int mm = 0; mm < 16; mm++)
                acc[mm] += qv * ks[mBase + mm][dd];
        }
    }
    float s8a = -3.4e38f, s8b = -3.4e38f;
#pragma unroll
    for (int mm = 0; mm < 8; mm++)  s8a = fmaxf(s8a, acc[mm]);
#pragma unroll
    for (int mm = 8; mm < 16; mm++) s8b = fmaxf(s8b, acc[mm]);
    segs[n][(tid & 3) * 2 + 0] = s8a * 0.0625f;
    segs[n][(tid & 3) * 2 + 1] = s8b * 0.0625f;
    __syncthreads();

    if (tid < 64) {
        float e[8];
#pragma unroll
        for (int i = 0; i < 8; i++) e[i] = segs[tid][i];
        float q4[4], h2[2];
#pragma unroll
        for (int i = 0; i < 4; i++) q4[i] = fmaxf(e[2 * i], e[2 * i + 1]);
        h2[0] = fmaxf(q4[0], q4[1]);
        h2[1] = fmaxf(q4[2], q4[3]);
        float a1 = fmaxf(h2[0], h2[1]);
        float* o = (which ? g_roleFt : g_sentFt) + (size_t)(b * 64 + tid) * 15;
        o[0] = a1;
        o[1] = h2[0]; o[2] = h2[1];
#pragma unroll
        for (int i = 0; i < 4; i++) o[3 + i] = q4[i];
#pragma unroll
        for (int i = 0; i < 8; i++) o[7 + i] = e[i];
    }
}

// ---------------- GCN pre ----------------
__global__ void __launch_bounds__(256) gcn_pre() {
    int b = blockIdx.x;
    int tid = threadIdx.x;
    __shared__ float cosm[64][65];
    __shared__ float xs[64][33];
    __shared__ float inv[64];

    if (tid < 64) {
        const float* xr = g_tag_out + (size_t)(b * 64 + tid) * 256;
        float s = 0.0f;
        for (int d = 0; d < 256; d++) { float v = xr[d]; s += v * v; }
        inv[tid] = 1.0f / (sqrtf(s) + 1e-8f);
    }

    float acc[16];
#pragma unroll
    for (int i = 0; i < 16; i++) acc[i] = 0.0f;
    int n = tid >> 2;
    int mBase = (tid & 3) * 16;

    for (int d0 = 0; d0 < 256; d0 += 32) {
        __syncthreads();
        for (int idx = tid; idx < 64 * 32; idx += 256) {
            int r = idx >> 5, cc = idx & 31;
            xs[r][cc] = g_tag_out[((size_t)(b * 64 + r)) * 256 + d0 + cc];
        }
        __syncthreads();
#pragma unroll 4
        for (int dd = 0; dd < 32; dd++) {
            float xv = xs[n][dd];
#pragma unroll
            for (int mm = 0; mm < 16; mm++)
                acc[mm] += xv * xs[mBase + mm][dd];
        }
    }
#pragma unroll
    for (int mm = 0; mm < 16; mm++)
        cosm[n][mBase + mm] = acc[mm] * inv[n] * inv[mBase + mm];

    int ddBase = (tid & 3) * 8;
    for (int d0 = 0; d0 < 256; d0 += 32) {
        __syncthreads();
        for (int idx = tid; idx < 64 * 32; idx += 256) {
            int r = idx >> 5, cc = idx & 31;
            xs[r][cc] = g_tag_out[((size_t)(b * 64 + r)) * 256 + d0 + cc];
        }
        __syncthreads();
        float r8[8];
#pragma unroll
        for (int i = 0; i < 8; i++) r8[i] = 0.0f;
        for (int m = 0; m < 64; m++) {
            float cv = cosm[n][m];
#pragma unroll
            for (int i = 0; i < 8; i++) r8[i] += cv * xs[m][ddBase + i];
        }
#pragma unroll
        for (int i = 0; i < 8; i++) {
            float v = (r8[i] + 2.0f * xs[n][ddBase + i]) * (1.0f / 66.0f);
            g_agg[(size_t)(b * 64 + n) * 256 + d0 + ddBase + i] = v;
        }
    }
}

// ---------------- classifier + log_softmax ----------------
__global__ void __launch_bounds__(256) cls_kernel(
    const float* __restrict__ W, const float* __restrict__ bias,
    float* __restrict__ out)
{
    __shared__ float Wsh[8][288];
    __shared__ float bsh[8];
    __shared__ float ftile[256][33];

    int tid = threadIdx.x;
    for (int i = tid; i < 8 * 286; i += 256) Wsh[i / 286][i % 286] = W[i];
    if (tid < 8) bsh[tid] = bias[tid];
    __syncthreads();

    int p0 = blockIdx.x * 256;
    int p = p0 + tid;
    float z[8];
#pragma unroll
    for (int c = 0; c < 8; c++) z[c] = bsh[c];

    for (int d0 = 0; d0 < 256; d0 += 32) {
        __syncthreads();
        for (int idx = tid; idx < 256 * 32; idx += 256) {
            int r = idx >> 5, cc = idx & 31;
            ftile[r][cc] = g_tag_out[(size_t)(p0 + r) * 256 + d0 + cc];
        }
        __syncthreads();
#pragma unroll 4
        for (int dd = 0; dd < 32; dd++) {
            float f = ftile[tid][dd];
#pragma unroll
            for (int c = 0; c < 8; c++) z[c] += f * Wsh[c][d0 + dd];
        }
    }
#pragma unroll
    for (int d = 0; d < 15; d++) {
        float f = g_sentFt[(size_t)p * 15 + d];
#pragma unroll
        for (int c = 0; c < 8; c++) z[c] += f * Wsh[c][256 + d];
    }
#pragma unroll
    for (int d = 0; d < 15; d++) {
        float f = g_roleFt[(size_t)p * 15 + d];
#pragma unroll
        for (int c = 0; c < 8; c++) z[c] += f * Wsh[c][271 + d];
    }
    float m = z[0];
#pragma unroll
    for (int c = 1; c < 8; c++) m = fmaxf(m, z[c]);
    float se = 0.0f;
#pragma unroll
    for (int c = 0; c < 8; c++) se += expf(z[c] - m);
    float lse = m + logf(se);
#pragma unroll
    for (int c = 0; c < 8; c++) out[(size_t)p * 8 + c] = z[c] - lse;
}

// ============================================================
extern "C" void kernel_launch(void* const* d_in, const int* in_sizes, int n_in,
                              void* d_out, int out_size)
{
    (void)in_sizes; (void)n_in; (void)out_size;
    const float* documents = (const float*)d_in[0];
    const float* sw_ih_f = (const float*)d_in[1];
    const float* sw_hh_f = (const float*)d_in[2];
    const float* sb_f    = (const float*)d_in[3];
    const float* sw_ih_b = (const float*)d_in[4];
    const float* sw_hh_b = (const float*)d_in[5];
    const float* sb_b    = (const float*)d_in[6];
    const float* sf_Wq   = (const float*)d_in[7];
    const float* sf_bq   = (const float*)d_in[8];
    const float* sf_Wk   = (const float*)d_in[9];
    const float* sf_bk   = (const float*)d_in[10];
    const float* rf_Wq   = (const float*)d_in[11];
    const float* rf_bq   = (const float*)d_in[12];
    const float* rf_Wk   = (const float*)d_in[13];
    const float* rf_bk   = (const float*)d_in[14];
    const float* tw_ih_f = (const float*)d_in[15];
    const float* tw_hh_f = (const float*)d_in[16];
    const float* tb_f    = (const float*)d_in[17];
    const float* tw_ih_b = (const float*)d_in[18];
    const float* tw_hh_b = (const float*)d_in[19];
    const float* tb_b    = (const float*)d_in[20];
    const float* sage_W  = (const float*)d_in[21];
    const float* sage_b  = (const float*)d_in[22];
    const float* cls_W   = (const float*)d_in[23];
    const float* cls_b   = (const float*)d_in[24];
    float* out = (float*)d_out;

    const int TAG_SMEM = 4 * 32 * 65 * 8 + 32 * 128 * 4;   // 82944
    cudaFuncSetAttribute(lstm_sent5, cudaFuncAttributeMaxDynamicSharedMemorySize, S5_SMEM);
    cudaFuncSetAttribute(tag_persistent, cudaFuncAttributeMaxDynamicSharedMemorySize, TAG_SMEM);

    // 1) sentence BiLSTM input projection: tensor cores, 3xTF32
    gemm_inproj_tc<<<dim3(800, 8), 256>>>(documents, sw_ih_f, sw_ih_b, sb_f, sb_b);
    // 2) sentence recurrence: ONE persistent tensor-core kernel
    lstm_sent5<<<128, 256, S5_SMEM>>>(sw_hh_f, sw_hh_b);
    // 3) tag BiLSTM input projection
    gemm_dual<1><<<dim3(16, 8), 256>>>(nullptr, 2048, 256, 512,
                                       tw_ih_f, tw_ih_b, tb_f, tb_b, nullptr);
    // 4) tag recurrence: persistent kernel
    tag_persistent<<<TAG_NBLK, 256, TAG_SMEM>>>(tw_hh_f, tw_hh_b);
    // 5) SPP on sentpres -> sentFt
    gemm_dual<2><<<dim3(16, 4), 256>>>(nullptr, 2048, 256, 256,
                                       sf_Wq, sf_Wk, sf_bq, sf_bk, nullptr);
    spp_kernel<<<32, 256>>>(0);
    // 6) SPP on tag_out -> roleFt
    gemm_dual<3><<<dim3(16, 4), 256>>>(nullptr, 2048, 256, 256,
                                       rf_Wq, rf_Wk, rf_bq, rf_bk, nullptr);
    spp_kernel<<<32, 256>>>(1);
    // 7) GCN
    gcn_pre<<<32, 256>>>();
    gemm_dual<4><<<dim3(16, 2), 256>>>(nullptr, 2048, 256, 256,
                                       sage_W, sage_W, sage_b, sage_b, out + 16384);
    // 8) classifier + log_softmax
    cls_kernel<<<8, 256>>>(cls_W, cls_b, out);
}

// round 8
// speedup vs baseline: 1.4715x; 1.0024x over previous
#include <cuda_runtime.h>
#include <math.h>
#include <stdint.h>

typedef unsigned long long u64;
typedef unsigned int u32;

// ---------------- problem constants ----------------
#define BN   2048
#define TSEQ 50
#define NSEQ 64
#define BB   32

// ---------------- device scratch ----------------
__device__ float g_xp0[(size_t)TSEQ * BN * 512];
__device__ float g_xp1[(size_t)TSEQ * BN * 512];
__device__ float g_hbuf[2][2 * BN * 128];
__device__ float g_cst[2 * BN * 128];
__device__ float g_hsum[2 * BN * 128];
__device__ float g_sentpres[(size_t)BN * 256];
__device__ float g_txp0[(size_t)NSEQ * BB * 512];
__device__ float g_txp1[(size_t)NSEQ * BB * 512];
__device__ float g_thbuf[2][2 * BB * 128];
__device__ float g_tag_out[(size_t)BN * 256];
__device__ float g_q[(size_t)BN * 256];
__device__ float g_k[(size_t)BN * 256];
__device__ float g_sentFt[(size_t)BN * 15];
__device__ float g_roleFt[(size_t)BN * 15];
__device__ float g_agg[(size_t)BN * 256];
__device__ int g_tbar2[2];
__device__ int g_tdone2[2];
__device__ int g_sbar[32];
__device__ int g_sdone[32];

// ---------------- f32x2 helpers ----------------
__device__ __forceinline__ u64 pk2(float lo, float hi) {
    u64 r; asm("mov.b64 %0, {%1, %2};" : "=l"(r) : "f"(lo), "f"(hi)); return r;
}
__device__ __forceinline__ void up2(u64 v, float& lo, float& hi) {
    asm("mov.b64 {%0, %1}, %2;" : "=f"(lo), "=f"(hi) : "l"(v));
}
__device__ __forceinline__ void fma2(u64& d, u64 a, u64 b) {
    asm("fma.rn.f32x2 %0, %1, %2, %0;" : "+l"(d) : "l"(a), "l"(b));
}

// ---------------- tf32 helpers ----------------
__device__ __forceinline__ float tf32_rna(float x) {
    u32 u; asm("cvt.rna.tf32.f32 %0, %1;" : "=r"(u) : "f"(x));
    return __uint_as_float(u);
}
__device__ __forceinline__ void mma_tf32(float* d, const u32* a, const u32* b) {
    asm("mma.sync.aligned.m16n8k8.row.col.f32.tf32.tf32.f32 "
        "{%0,%1,%2,%3},{%4,%5,%6,%7},{%8,%9},{%0,%1,%2,%3};"
        : "+f"(d[0]), "+f"(d[1]), "+f"(d[2]), "+f"(d[3])
        : "r"(a[0]), "r"(a[1]), "r"(a[2]), "r"(a[3]), "r"(b[0]), "r"(b[1]));
}

// ---------------- fast math ----------------
__device__ __forceinline__ float sigf(float x) {
    x = fminf(fmaxf(x, -30.f), 30.f);
    return __fdividef(1.f, 1.f + __expf(-x));
}
__device__ __forceinline__ float tanhfast(float x) {
    x = fminf(fmaxf(x, -15.f), 15.f);
    return __fdividef(2.f, 1.f + __expf(-2.f * x)) - 1.f;
}

// ============================================================
// K1: sentence input projection with tensor cores (3xTF32).
// (unchanged — validated)
// ============================================================
#define K1P 12
__global__ void __launch_bounds__(256) gemm_inproj_tc(
    const float* __restrict__ A,
    const float* __restrict__ B0, const float* __restrict__ B1,
    const float* __restrict__ bias0, const float* __restrict__ bias1)
{
    __shared__ float sAh[2][128 * K1P], sAl[2][128 * K1P];
    __shared__ float sBh[2][128 * K1P], sBl[2][128 * K1P];

    int m0 = blockIdx.x * 128;
    int nb = blockIdx.y;
    int dir = nb >> 2;
    int n0 = (nb & 3) * 128;
    const float* Bw = dir ? B1 : B0;
    const float* bias = dir ? bias1 : bias0;
    float* out = dir ? g_xp1 : g_xp0;

    int tid = threadIdx.x;
    int lane = tid & 31, warp = tid >> 5;
    int g = lane >> 2, tig = lane & 3;
    int wm = warp & 1, wn = warp >> 1;

    int srow = tid >> 1, shalf = tid & 1;
    const float* aP = A + (size_t)(m0 + srow) * 200 + shalf * 4;
    const float* bP = Bw + (size_t)(n0 + srow) * 200 + shalf * 4;

    float acc[4][4][4];
#pragma unroll
    for (int i = 0; i < 4; i++)
#pragma unroll
        for (int j = 0; j < 4; j++)
#pragma unroll
            for (int c = 0; c < 4; c++) acc[i][j][c] = 0.0f;

    float4 av = *(const float4*)aP;
    float4 bv = *(const float4*)bP;

    int soff = srow * K1P + shalf * 4;
#define K1_STAGE(buf, a4, b4) do {                                          \
        float4 _h, _l;                                                      \
        _h.x = tf32_rna(a4.x); _l.x = tf32_rna(a4.x - _h.x);                \
        _h.y = tf32_rna(a4.y); _l.y = tf32_rna(a4.y - _h.y);                \
        _h.z = tf32_rna(a4.z); _l.z = tf32_rna(a4.z - _h.z);                \
        _h.w = tf32_rna(a4.w); _l.w = tf32_rna(a4.w - _h.w);                \
        *(float4*)&sAh[buf][soff] = _h;                                     \
        *(float4*)&sAl[buf][soff] = _l;                                     \
        _h.x = tf32_rna(b4.x); _l.x = tf32_rna(b4.x - _h.x);                \
        _h.y = tf32_rna(b4.y); _l.y = tf32_rna(b4.y - _h.y);                \
        _h.z = tf32_rna(b4.z); _l.z = tf32_rna(b4.z - _h.z);                \
        _h.w = tf32_rna(b4.w); _l.w = tf32_rna(b4.w - _h.w);                \
        *(float4*)&sBh[buf][soff] = _h;                                     \
        *(float4*)&sBl[buf][soff] = _l;                                     \
    } while (0)

    K1_STAGE(0, av, bv);
    __syncthreads();

    for (int kt = 0; kt < 25; kt++) {
        int cur = kt & 1;
        if (kt < 24) {
            av = *(const float4*)(aP + (kt + 1) * 8);
            bv = *(const float4*)(bP + (kt + 1) * 8);
        }
        u32 bh[4][2], bl[4][2];
#pragma unroll
        for (int nt = 0; nt < 4; nt++) {
            int br = (wn * 32 + nt * 8 + g) * K1P;
            bh[nt][0] = __float_as_uint(sBh[cur][br + tig]);
            bh[nt][1] = __float_as_uint(sBh[cur][br + tig + 4]);
            bl[nt][0] = __float_as_uint(sBl[cur][br + tig]);
            bl[nt][1] = __float_as_uint(sBl[cur][br + tig + 4]);
        }
#pragma unroll
        for (int mt = 0; mt < 4; mt++) {
            int ar0 = (wm * 64 + mt * 16 + g) * K1P;
            int ar1 = ar0 + 8 * K1P;
            u32 ah[4], al[4];
            ah[0] = __float_as_uint(sAh[cur][ar0 + tig]);
            ah[1] = __float_as_uint(sAh[cur][ar1 + tig]);
            ah[2] = __float_as_uint(sAh[cur][ar0 + tig + 4]);
            ah[3] = __float_as_uint(sAh[cur][ar1 + tig + 4]);
            al[0] = __float_as_uint(sAl[cur][ar0 + tig]);
            al[1] = __float_as_uint(sAl[cur][ar1 + tig]);
            al[2] = __float_as_uint(sAl[cur][ar0 + tig + 4]);
            al[3] = __float_as_uint(sAl[cur][ar1 + tig + 4]);
#pragma unroll
            for (int nt = 0; nt < 4; nt++) {
                mma_tf32(acc[mt][nt], ah, bh[nt]);
                mma_tf32(acc[mt][nt], al, bh[nt]);
                mma_tf32(acc[mt][nt], ah, bl[nt]);
            }
        }
        __syncthreads();
        if (kt < 24) {
            K1_STAGE((kt + 1) & 1, av, bv);
            __syncthreads();
        }
    }

#pragma unroll
    for (int mt = 0; mt < 4; mt++) {
#pragma unroll
        for (int nt = 0; nt < 4; nt++) {
            int col = n0 + wn * 32 + nt * 8 + 2 * tig;
            float b0v = __ldg(bias + col), b1v = __ldg(bias + col + 1);
            int r0 = m0 + wm * 64 + mt * 16 + g;
            int p0 = r0 / 50, t0 = r0 - p0 * 50;
            float2 o0 = make_float2(acc[mt][nt][0] + b0v, acc[mt][nt][1] + b1v);
            *(float2*)(out + ((size_t)t0 * BN + p0) * 512 + col) = o0;
            int r1 = r0 + 8;
            int p1 = r1 / 50, t1 = r1 - p1 * 50;
            float2 o1 = make_float2(acc[mt][nt][2] + b0v, acc[mt][nt][3] + b1v);
            *(float2*)(out + ((size_t)t1 * BN + p1) * 512 + col) = o1;
        }
    }
}

// ============================================================
// Sentence LSTM: PERSISTENT tensor-core recurrence (unchanged)
// ============================================================
#define S5_WST   132
#define S5_HST   36
#define S5_WSZ   (128 * S5_WST)
#define S5_HBUF  (2 * 128 * S5_HST)
#define S5_SMEM  ((2 * S5_WSZ + 2 * S5_HBUF) * 4)

__global__ void __launch_bounds__(256, 1) lstm_sent5(
    const float* __restrict__ W0, const float* __restrict__ W1)
{
    extern __shared__ __align__(16) float s5[];
    float* sWh = s5;
    float* sWl = s5 + S5_WSZ;
    float* sH  = s5 + 2 * S5_WSZ;
    float* gsm = sH;

    int bid = blockIdx.x;
    int dir = bid >> 6;
    int rem = bid & 63;
    int pch = rem >> 2;
    int jch = rem & 3;
    int p0 = pch * 128;
    int j0 = jch * 32;
    int barIdx = pch * 2 + dir;

    const float* W = dir ? W1 : W0;
    const float* xp = dir ? g_xp1 : g_xp0;
    float* cD = g_cst + (size_t)dir * BN * 128;
    float* hsD = g_hsum + (size_t)dir * BN * 128;

    int tid = threadIdx.x;
    int lane = tid & 31, warp = tid >> 5;
    int g = lane >> 2, tig = lane & 3;
    int wm = warp & 1, wn = warp >> 1;

    {
        int row = tid >> 1;
        int gg = row >> 5, jr = row & 31;
        int half = tid & 1;
        const float* wrow = W + (size_t)(gg * 128 + j0 + jr) * 128 + half * 64;
        int so = row * S5_WST + half * 64;
#pragma unroll
        for (int q = 0; q < 16; q++) {
            float4 v = *(const float4*)(wrow + q * 4);
            float4 h4, l4;
            h4.x = tf32_rna(v.x); l4.x = tf32_rna(v.x - h4.x);
            h4.y = tf32_rna(v.y); l4.y = tf32_rna(v.y - h4.y);
            h4.z = tf32_rna(v.z); l4.z = tf32_rna(v.z - h4.z);
            h4.w = tf32_rna(v.w); l4.w = tf32_rna(v.w - h4.w);
            *(float4*)&sWh[so + q * 4] = h4;
            *(float4*)&sWl[so + q * 4] = l4;
        }
    }
    __syncthreads();

    int srow = tid >> 1;
    int shalf = tid & 1;

    for (int s = 0; s < TSEQ; s++) {
        int t = dir ? (TSEQ - 1 - s) : s;

        if (s > 0) {
            const float* hIn = g_hbuf[s & 1] + (size_t)dir * BN * 128;
            const float* aRow = hIn + (size_t)(p0 + srow) * 128 + shalf * 16;
            int hso = srow * S5_HST + shalf * 16;

            float acc[4][4][4];
#pragma unroll
            for (int i = 0; i < 4; i++)
#pragma unroll
                for (int j = 0; j < 4; j++)
#pragma unroll
                    for (int c = 0; c < 4; c++) acc[i][j][c] = 0.0f;

            {
                float* dh = sH + 0 * S5_HBUF;
                float* dl = dh + 128 * S5_HST;
#pragma unroll
                for (int q = 0; q < 4; q++) {
                    float4 v = *(const float4*)(aRow + q * 4);
                    float4 h4, l4;
                    h4.x = tf32_rna(v.x); l4.x = tf32_rna(v.x - h4.x);
                    h4.y = tf32_rna(v.y); l4.y = tf32_rna(v.y - h4.y);
                    h4.z = tf32_rna(v.z); l4.z = tf32_rna(v.z - h4.z);
                    h4.w = tf32_rna(v.w); l4.w = tf32_rna(v.w - h4.w);
                    *(float4*)&dh[hso + q * 4] = h4;
                    *(float4*)&dl[hso + q * 4] = l4;
                }
            }
            __syncthreads();

#pragma unroll
            for (int kc = 0; kc < 4; kc++) {
                int cur = kc & 1;
                float4 pre[4];
                if (kc < 3) {
#pragma unroll
                    for (int q = 0; q < 4; q++)
                        pre[q] = *(const float4*)(aRow + (kc + 1) * 32 + q * 4);
                }
                const float* bh_base = sWh;
                const float* bl_base = sWl;
                const float* ah_base = sH + cur * S5_HBUF;
                const float* al_base = ah_base + 128 * S5_HST;
#pragma unroll
                for (int kt = 0; kt < 4; kt++) {
                    int kbW = kc * 32 + kt * 8;
                    int kbH = kt * 8;
                    u32 bh[4][2], bl[4][2];
#pragma unroll
                    for (int nt = 0; nt < 4; nt++) {
                        int br = (wn * 32 + nt * 8 + g) * S5_WST + kbW;
                        bh[nt][0] = __float_as_uint(bh_base[br + tig]);
                        bh[nt][1] = __float_as_uint(bh_base[br + tig + 4]);
                        bl[nt][0] = __float_as_uint(bl_base[br + tig]);
                        bl[nt][1] = __float_as_uint(bl_base[br + tig + 4]);
                    }
#pragma unroll
                    for (int mt = 0; mt < 4; mt++) {
                        int ar0 = (wm * 64 + mt * 16 + g) * S5_HST + kbH;
                        int ar1 = ar0 + 8 * S5_HST;
                        u32 ah[4], al[4];
                        ah[0] = __float_as_uint(ah_base[ar0 + tig]);
                        ah[1] = __float_as_uint(ah_base[ar1 + tig]);
                        ah[2] = __float_as_uint(ah_base[ar0 + tig + 4]);
                        ah[3] = __float_as_uint(ah_base[ar1 + tig + 4]);
                        al[0] = __float_as_uint(al_base[ar0 + tig]);
                        al[1] = __float_as_uint(al_base[ar1 + tig]);
                        al[2] = __float_as_uint(al_base[ar0 + tig + 4]);
                        al[3] = __float_as_uint(al_base[ar1 + tig + 4]);
#pragma unroll
                        for (int nt = 0; nt < 4; nt++) {
                            mma_tf32(acc[mt][nt], ah, bh[nt]);
                            mma_tf32(acc[mt][nt], al, bh[nt]);
                            mma_tf32(acc[mt][nt], ah, bl[nt]);
                        }
                    }
                }
                if (kc < 3) {
                    float* dh = sH + (1 - cur) * S5_HBUF;
                    float* dl = dh + 128 * S5_HST;
#pragma unroll
                    for (int q = 0; q < 4; q++) {
                        float4 v = pre[q];
                        float4 h4, l4;
                        h4.x = tf32_rna(v.x); l4.x = tf32_rna(v.x - h4.x);
                        h4.y = tf32_rna(v.y); l4.y = tf32_rna(v.y - h4.y);
                        h4.z = tf32_rna(v.z); l4.z = tf32_rna(v.z - h4.z);
                        h4.w = tf32_rna(v.w); l4.w = tf32_rna(v.w - h4.w);
                        *(float4*)&dh[hso + q * 4] = h4;
                        *(float4*)&dl[hso + q * 4] = l4;
                    }
                }
                __syncthreads();
            }

#pragma unroll
            for (int mt = 0; mt < 4; mt++) {
                int r0 = wm * 64 + mt * 16 + g;
#pragma unroll
                for (int nt = 0; nt < 4; nt++) {
                    int col = wn * 32 + nt * 8 + 2 * tig;
                    *(float2*)&gsm[r0 * 132 + col] =
                        make_float2(acc[mt][nt][0], acc[mt][nt][1]);
                    *(float2*)&gsm[(r0 + 8) * 132 + col] =
                        make_float2(acc[mt][nt][2], acc[mt][nt][3]);
                }
            }
            __syncthreads();
        }

        float* hOut = g_hbuf[(s + 1) & 1] + (size_t)dir * BN * 128;
        size_t xbase = (size_t)t * BN * 512;
#pragma unroll
        for (int i = 0; i < 16; i++) {
            int pj = tid + i * 256;
            int pp = pj >> 5, jj = pj & 31;
            int p = p0 + pp;
            int j = j0 + jj;
            const float* xr = xp + xbase + (size_t)p * 512 + j;
            float gi = xr[0], gf = xr[128], gg2 = xr[256], go = xr[384];
            if (s > 0) {
                gi  += gsm[pp * 132 + jj];
                gf  += gsm[pp * 132 + 32 + jj];
                gg2 += gsm[pp * 132 + 64 + jj];
                go  += gsm[pp * 132 + 96 + jj];
            }
            size_t hidx = (size_t)p * 128 + j;
            float cold = (s == 0) ? 0.0f : cD[hidx];
            float cn = sigf(gf) * cold + sigf(gi) * tanhfast(gg2);
            float hn = sigf(go) * tanhfast(cn);
            if (s == TSEQ - 1) {
                float hs = hsD[hidx] + hn;
                g_sentpres[(size_t)p * 256 + dir * 128 + j] =
                    tanhfast(hs * (1.0f / 50.0f));
            } else {
                cD[hidx] = cn;
                hOut[hidx] = hn;
                hsD[hidx] = (s == 0) ? hn : (hsD[hidx] + hn);
            }
        }

        if (s < TSEQ - 1) {
            __syncthreads();
            if (tid == 0) {
                __threadfence();
                atomicAdd(&g_sbar[barIdx], 1);
                int target = 4 * (s + 1);
                while (*(volatile int*)&g_sbar[barIdx] < target) { }
                __threadfence();
            }
            __syncthreads();
        }
    }

    __syncthreads();
    if (tid == 0) {
        int old = atomicAdd(&g_sdone[barIdx], 1);
        if (old == 3) {
            g_sbar[barIdx] = 0;
            __threadfence();
            g_sdone[barIdx] = 0;
        }
    }
}

// ============================================================
// Dual-half GEMM with f32x2 (modes 1-4, unchanged)
// ============================================================
template <int MODE>
__global__ void __launch_bounds__(256) gemm_dual(
    const float* __restrict__ Aparam, int M, int K, int NB,
    const float* __restrict__ B0, const float* __restrict__ B1,
    const float* __restrict__ bias0, const float* __restrict__ bias1,
    float* __restrict__ outParam)
{
    __shared__ __align__(16) u64 As2[8][128];
    __shared__ __align__(16) float Bs[8][128];

    const float* A;
    if (MODE == 1 || MODE == 2) A = g_sentpres;
    else if (MODE == 3) A = g_tag_out;
    else A = g_agg;
    (void)Aparam;

    int hsel = (blockIdx.y * 128) / NB;
    int g0 = blockIdx.y * 128 - hsel * NB;
    int m0 = blockIdx.x * 128;

    const float* B = hsel ? B1 : B0;
    const float* bias = hsel ? bias1 : bias0;

    float* out;
    if (MODE == 1) out = hsel ? g_txp1 : g_txp0;
    else if (MODE == 2 || MODE == 3) out = hsel ? g_k : g_q;
    else out = outParam;

    int tid = threadIdx.x;
    int tx = tid & 15;
    int ty = tid >> 4;
    int lr = tid >> 1;
    int lc4 = tid & 1;

    u64 acc2[8][4];
#pragma unroll
    for (int i = 0; i < 8; i++)
#pragma unroll
        for (int j = 0; j < 4; j++) acc2[i][j] = 0ULL;

    int KT = K / 8;
    const float* aPtr = A + (size_t)(m0 + lr) * K + lc4 * 4;
    const float* bPtr = B + (size_t)(g0 + lr) * K + lc4 * 4;
    float4 av = *(const float4*)(aPtr);
    float4 bv = *(const float4*)(bPtr);

    for (int kt = 0; kt < KT; kt++) {
        As2[lc4 * 4 + 0][lr] = pk2(av.x, av.x);
        As2[lc4 * 4 + 1][lr] = pk2(av.y, av.y);
        As2[lc4 * 4 + 2][lr] = pk2(av.z, av.z);
        As2[lc4 * 4 + 3][lr] = pk2(av.w, av.w);
        Bs[lc4 * 4 + 0][lr] = bv.x; Bs[lc4 * 4 + 1][lr] = bv.y;
        Bs[lc4 * 4 + 2][lr] = bv.z; Bs[lc4 * 4 + 3][lr] = bv.w;
        __syncthreads();
        if (kt + 1 < KT) {
            av = *(const float4*)(aPtr + (kt + 1) * 8);
            bv = *(const float4*)(bPtr + (kt + 1) * 8);
        }
#pragma unroll
        for (int kk = 0; kk < 8; kk++) {
            u64 b2[4];
#pragma unroll
            for (int jq = 0; jq < 4; jq++)
                b2[jq] = *(const u64*)&Bs[kk][2 * (tx + 16 * jq)];
            u64 a2[8];
#pragma unroll
            for (int i = 0; i < 8; i++) a2[i] = As2[kk][ty * 8 + i];
#pragma unroll
            for (int i = 0; i < 8; i++)
#pragma unroll
                for (int jq = 0; jq < 4; jq++)
                    fma2(acc2[i][jq], a2[i], b2[jq]);
        }
        __syncthreads();
    }

#pragma unroll
    for (int i = 0; i < 8; i++) {
        int m = m0 + ty * 8 + i;
        size_t rowbase;
        if (MODE == 1) {
            int b = m >> 6; int n = m & 63;
            rowbase = ((size_t)n * BB + b) * 512;
        } else {
            rowbase = (size_t)m * 256;
        }
#pragma unroll
        for (int jq = 0; jq < 4; jq++) {
            int g = g0 + 2 * (tx + 16 * jq);
            float lo, hi;
            up2(acc2[i][jq], lo, hi);
            float2 bb = *(const float2*)(bias + g);
            float2 o;
            o.x = lo + bb.x;
            o.y = hi + bb.y;
            if (MODE == 4) { o.x = fmaxf(o.x, 0.f); o.y = fmaxf(o.y, 0.f); }
            *(float2*)(out + rowbase + g) = o;
        }
    }
}

// ============================================================
// Persistent tag BiLSTM v2: conflict-free W (stride-129 floats).
// 8 blocks (2 dir x 4 jch), per-dir barrier (4 arrivals).
// Per thread: 4 b x 1 j x 4 gates. W read as 2x LDS.32 (bank jj+c:
// conflict-free) + pack; h read as broadcast LDS.64.
// smem: sW float[128*129] (66048 B) + hsf float[32][128] (16384 B).
// ============================================================
#define TG_WST  129
#define TG_SMEM (128 * TG_WST * 4 + 32 * 128 * 4)

__global__ void __launch_bounds__(256) tag_persistent(
    const float* __restrict__ W0, const float* __restrict__ W1)
{
    extern __shared__ __align__(16) float tgs[];
    float* sW = tgs;                             // [g*32+jj][129]
    float (*hsf)[128] = (float (*)[128])(tgs + 128 * TG_WST);

    int dir = blockIdx.x >> 2;
    int j0 = (blockIdx.x & 3) * 32;
    const float* W = dir ? W1 : W0;
    const float* xp = dir ? g_txp1 : g_txp0;
    int tid = threadIdx.x;
    int jj = tid & 31;
    int pg = tid >> 5;
    int j = j0 + jj;

    // stage W once: row = g*32+jr (128 rows), 128 k each, stride 129
    for (int idx = tid; idx < 128 * 128; idx += 256) {
        int row = idx >> 7;           // g*32 + jr
        int k = idx & 127;
        int gg = row >> 5, jr = row & 31;
        sW[row * TG_WST + k] = W[(size_t)(gg * 128 + j0 + jr) * 128 + k];
    }

    float creg[4] = {0.f, 0.f, 0.f, 0.f};
    int* bar = &g_tbar2[dir];

    for (int s = 0; s < NSEQ; s++) {
        int t = dir ? (NSEQ - 1 - s) : s;
        u64 acc2[4][4];
#pragma unroll
        for (int a = 0; a < 4; a++)
#pragma unroll
            for (int b = 0; b < 4; b++) acc2[a][b] = 0ULL;

        if (s > 0) {
            const float* hIn = g_thbuf[s & 1] + (size_t)dir * BB * 128;
#pragma unroll
            for (int i = 0; i < 4; i++) {
                int idx = tid + i * 256;
                int r = idx >> 5, c4 = idx & 31;
                *(float4*)&hsf[r][c4 * 4] =
                    *(const float4*)(hIn + (size_t)r * 128 + c4 * 4);
            }
            __syncthreads();

            const float* w0r = sW + (0 * 32 + jj) * TG_WST;
            const float* w1r = sW + (1 * 32 + jj) * TG_WST;
            const float* w2r = sW + (2 * 32 + jj) * TG_WST;
            const float* w3r = sW + (3 * 32 + jj) * TG_WST;
#pragma unroll 4
            for (int kp = 0; kp < 64; kp++) {
                u64 w0 = pk2(w0r[kp * 2], w0r[kp * 2 + 1]);
                u64 w1 = pk2(w1r[kp * 2], w1r[kp * 2 + 1]);
                u64 w2 = pk2(w2r[kp * 2], w2r[kp * 2 + 1]);
                u64 w3 = pk2(w3r[kp * 2], w3r[kp * 2 + 1]);
#pragma unroll
                for (int bb = 0; bb < 4; bb++) {
                    u64 a2 = *(const u64*)&hsf[pg * 4 + bb][kp * 2];
                    fma2(acc2[bb][0], a2, w0);
                    fma2(acc2[bb][1], a2, w1);
                    fma2(acc2[bb][2], a2, w2);
                    fma2(acc2[bb][3], a2, w3);
                }
            }
        } else {
            __syncthreads();   // cover W staging before first use next steps
        }

        float* hOut = g_thbuf[(s + 1) & 1] + (size_t)dir * BB * 128;
#pragma unroll
        for (int bb = 0; bb < 4; bb++) {
            int b = pg * 4 + bb;
            const float* xr = xp + ((size_t)t * BB + b) * 512 + j;
            float lo, hi;
            up2(acc2[bb][0], lo, hi); float gi = lo + hi + xr[0];
            up2(acc2[bb][1], lo, hi); float gf = lo + hi + xr[128];
            up2(acc2[bb][2], lo, hi); float gg = lo + hi + xr[256];
            up2(acc2[bb][3], lo, hi); float go = lo + hi + xr[384];
            float cn = sigf(gf) * creg[bb] + sigf(gi) * tanhfast(gg);
            float hn = sigf(go) * tanhfast(cn);
            creg[bb] = cn;
            hOut[(size_t)b * 128 + j] = hn;
            g_tag_out[((size_t)b * NSEQ + t) * 256 + dir * 128 + j] = tanhfast(hn);
        }

        if (s < NSEQ - 1) {
            __syncthreads();
            if (tid == 0) {
                __threadfence();
                atomicAdd(bar, 1);
                int target = 4 * (s + 1);
                while (*(volatile int*)bar < target) { }
                __threadfence();
            }
            __syncthreads();
        }
    }

    __syncthreads();
    if (tid == 0) {
        int old = atomicAdd(&g_tdone2[dir], 1);
        if (old == 3) {
            g_tbar2[dir] = 0;
            __threadfence();
            g_tdone2[dir] = 0;
        }
    }
}

// ---------------- SPP ----------------
__global__ void __launch_bounds__(256) spp_kernel(int which) {
    int b = blockIdx.x;
    int tid = threadIdx.x;
    __shared__ float qs[64][33];
    __shared__ float ks[64][33];
    __shared__ float segs[64][8];

    float acc[16];
#pragma unroll
    for (int i = 0; i < 16; i++) acc[i] = 0.0f;
    int n = tid >> 2;
    int mBase = (tid & 3) * 16;

    for (int d0 = 0; d0 < 256; d0 += 32) {
        __syncthreads();
        for (int idx = tid; idx < 64 * 32; idx += 256) {
            int r = idx >> 5, cc = idx & 31;
            size_t gi = ((size_t)(b * 64 + r)) * 256 + d0 + cc;
            qs[r][cc] = g_q[gi];
            ks[r][cc] = g_k[gi];
        }
        __syncthreads();
#pragma unroll 4
        for (int dd = 0; dd < 32; dd++) {
            float qv = qs[n][dd];
#pragma unroll
            for (int mm = 0; mm < 16; mm++)
                acc[mm] += qv * ks[mBase + mm][dd];
        }
    }
    float s8a = -3.4e38f, s8b = -3.4e38f;
#pragma unroll
    for (int mm = 0; mm < 8; mm++)  s8a = fmaxf(s8a, acc[mm]);
#pragma unroll
    for (int mm = 8; mm < 16; mm++) s8b = fmaxf(s8b, acc[mm]);
    segs[n][(tid & 3) * 2 + 0] = s8a * 0.0625f;
    segs[n][(tid & 3) * 2 + 1] = s8b * 0.0625f;
    __syncthreads();

    if (tid < 64) {
        float e[8];
#pragma unroll
        for (int i = 0; i < 8; i++) e[i] = segs[tid][i];
        float q4[4], h2[2];
#pragma unroll
        for (int i = 0; i < 4; i++) q4[i] = fmaxf(e[2 * i], e[2 * i + 1]);
        h2[0] = fmaxf(q4[0], q4[1]);
        h2[1] = fmaxf(q4[2], q4[3]);
        float a1 = fmaxf(h2[0], h2[1]);
        float* o = (which ? g_roleFt : g_sentFt) + (size_t)(b * 64 + tid) * 15;
        o[0] = a1;
        o[1] = h2[0]; o[2] = h2[1];
#pragma unroll
        for (int i = 0; i < 4; i++) o[3 + i] = q4[i];
#pragma unroll
        for (int i = 0; i < 8; i++) o[7 + i] = e[i];
    }
}

// ---------------- GCN pre ----------------
__global__ void __launch_bounds__(256) gcn_pre() {
    int b = blockIdx.x;
    int tid = threadIdx.x;
    __shared__ float cosm[64][65];
    __shared__ float xs[64][33];
    __shared__ float inv[64];

    if (tid < 64) {
        const float* xr = g_tag_out + (size_t)(b * 64 + tid) * 256;
        float s = 0.0f;
        for (int d = 0; d < 256; d++) { float v = xr[d]; s += v * v; }
        inv[tid] = 1.0f / (sqrtf(s) + 1e-8f);
    }

    float acc[16];
#pragma unroll
    for (int i = 0; i < 16; i++) acc[i] = 0.0f;
    int n = tid >> 2;
    int mBase = (tid & 3) * 16;

    for (int d0 = 0; d0 < 256; d0 += 32) {
        __syncthreads();
        for (int idx = tid; idx < 64 * 32; idx += 256) {
            int r = idx >> 5, cc = idx & 31;
            xs[r][cc] = g_tag_out[((size_t)(b * 64 + r)) * 256 + d0 + cc];
        }
        __syncthreads();
#pragma unroll 4
        for (int dd = 0; dd < 32; dd++) {
            float xv = xs[n][dd];
#pragma unroll
            for (int mm = 0; mm < 16; mm++)
                acc[mm] += xv * xs[mBase + mm][dd];
        }
    }
#pragma unroll
    for (int mm = 0; mm < 16; mm++)
        cosm[n][mBase + mm] = acc[mm] * inv[n] * inv[mBase + mm];

    int ddBase = (tid & 3) * 8;
    for (int d0 = 0; d0 < 256; d0 += 32) {
        __syncthreads();
        for (int idx = tid; idx < 64 * 32; idx += 256) {
            int r = idx >> 5, cc = idx & 31;
            xs[r][cc] = g_tag_out[((size_t)(b * 64 + r)) * 256 + d0 + cc];
        }
        __syncthreads();
        float r8[8];
#pragma unroll
        for (int i = 0; i < 8; i++) r8[i] = 0.0f;
        for (int m = 0; m < 64; m++) {
            float cv = cosm[n][m];
#pragma unroll
            for (int i = 0; i < 8; i++) r8[i] += cv * xs[m][ddBase + i];
        }
#pragma unroll
        for (int i = 0; i < 8; i++) {
            float v = (r8[i] + 2.0f * xs[n][ddBase + i]) * (1.0f / 66.0f);
            g_agg[(size_t)(b * 64 + n) * 256 + d0 + ddBase + i] = v;
        }
    }
}

// ---------------- classifier + log_softmax ----------------
__global__ void __launch_bounds__(256) cls_kernel(
    const float* __restrict__ W, const float* __restrict__ bias,
    float* __restrict__ out)
{
    __shared__ float Wsh[8][288];
    __shared__ float bsh[8];
    __shared__ float ftile[256][33];

    int tid = threadIdx.x;
    for (int i = tid; i < 8 * 286; i += 256) Wsh[i / 286][i % 286] = W[i];
    if (tid < 8) bsh[tid] = bias[tid];
    __syncthreads();

    int p0 = blockIdx.x * 256;
    int p = p0 + tid;
    float z[8];
#pragma unroll
    for (int c = 0; c < 8; c++) z[c] = bsh[c];

    for (int d0 = 0; d0 < 256; d0 += 32) {
        __syncthreads();
        for (int idx = tid; idx < 256 * 32; idx += 256) {
            int r = idx >> 5, cc = idx & 31;
            ftile[r][cc] = g_tag_out[(size_t)(p0 + r) * 256 + d0 + cc];
        }
        __syncthreads();
#pragma unroll 4
        for (int dd = 0; dd < 32; dd++) {
            float f = ftile[tid][dd];
#pragma unroll
            for (int c = 0; c < 8; c++) z[c] += f * Wsh[c][d0 + dd];
        }
    }
#pragma unroll
    for (int d = 0; d < 15; d++) {
        float f = g_sentFt[(size_t)p * 15 + d];
#pragma unroll
        for (int c = 0; c < 8; c++) z[c] += f * Wsh[c][256 + d];
    }
#pragma unroll
    for (int d = 0; d < 15; d++) {
        float f = g_roleFt[(size_t)p * 15 + d];
#pragma unroll
        for (int c = 0; c < 8; c++) z[c] += f * Wsh[c][271 + d];
    }
    float m = z[0];
#pragma unroll
    for (int c = 1; c < 8; c++) m = fmaxf(m, z[c]);
    float se = 0.0f;
#pragma unroll
    for (int c = 0; c < 8; c++) se += expf(z[c] - m);
    float lse = m + logf(se);
#pragma unroll
    for (int c = 0; c < 8; c++) out[(size_t)p * 8 + c] = z[c] - lse;
}

// ============================================================
extern "C" void kernel_launch(void* const* d_in, const int* in_sizes, int n_in,
                              void* d_out, int out_size)
{
    (void)in_sizes; (void)n_in; (void)out_size;
    const float* documents = (const float*)d_in[0];
    const float* sw_ih_f = (const float*)d_in[1];
    const float* sw_hh_f = (const float*)d_in[2];
    const float* sb_f    = (const float*)d_in[3];
    const float* sw_ih_b = (const float*)d_in[4];
    const float* sw_hh_b = (const float*)d_in[5];
    const float* sb_b    = (const float*)d_in[6];
    const float* sf_Wq   = (const float*)d_in[7];
    const float* sf_bq   = (const float*)d_in[8];
    const float* sf_Wk   = (const float*)d_in[9];
    const float* sf_bk   = (const float*)d_in[10];
    const float* rf_Wq   = (const float*)d_in[11];
    const float* rf_bq   = (const float*)d_in[12];
    const float* rf_Wk   = (const float*)d_in[13];
    const float* rf_bk   = (const float*)d_in[14];
    const float* tw_ih_f = (const float*)d_in[15];
    const float* tw_hh_f = (const float*)d_in[16];
    const float* tb_f    = (const float*)d_in[17];
    const float* tw_ih_b = (const float*)d_in[18];
    const float* tw_hh_b = (const float*)d_in[19];
    const float* tb_b    = (const float*)d_in[20];
    const float* sage_W  = (const float*)d_in[21];
    const float* sage_b  = (const float*)d_in[22];
    const float* cls_W   = (const float*)d_in[23];
    const float* cls_b   = (const float*)d_in[24];
    float* out = (float*)d_out;

    cudaFuncSetAttribute(lstm_sent5, cudaFuncAttributeMaxDynamicSharedMemorySize, S5_SMEM);
    cudaFuncSetAttribute(tag_persistent, cudaFuncAttributeMaxDynamicSharedMemorySize, TG_SMEM);

    // 1) sentence BiLSTM input projection: tensor cores, 3xTF32
    gemm_inproj_tc<<<dim3(800, 8), 256>>>(documents, sw_ih_f, sw_ih_b, sb_f, sb_b);
    // 2) sentence recurrence: ONE persistent tensor-core kernel
    lstm_sent5<<<128, 256, S5_SMEM>>>(sw_hh_f, sw_hh_b);
    // 3) tag BiLSTM input projection
    gemm_dual<1><<<dim3(16, 8), 256>>>(nullptr, 2048, 256, 512,
                                       tw_ih_f, tw_ih_b, tb_f, tb_b, nullptr);
    // 4) tag recurrence: persistent kernel (conflict-free W)
    tag_persistent<<<8, 256, TG_SMEM>>>(tw_hh_f, tw_hh_b);
    // 5) SPP on sentpres -> sentFt
    gemm_dual<2><<<dim3(16, 4), 256>>>(nullptr, 2048, 256, 256,
                                       sf_Wq, sf_Wk, sf_bq, sf_bk, nullptr);
    spp_kernel<<<32, 256>>>(0);
    // 6) SPP on tag_out -> roleFt
    gemm_dual<3><<<dim3(16, 4), 256>>>(nullptr, 2048, 256, 256,
                                       rf_Wq, rf_Wk, rf_bq, rf_bk, nullptr);
    spp_kernel<<<32, 256>>>(1);
    // 7) GCN
    gcn_pre<<<32, 256>>>();
    gemm_dual<4><<<dim3(16, 2), 256>>>(nullptr, 2048, 256, 256,
                                       sage_W, sage_W, sage_b, sage_b, out + 16384);
    // 8) classifier + log_softmax
    cls_kernel<<<8, 256>>>(cls_W, cls_b, out);
}

// round 10
// speedup vs baseline: 1.5594x; 1.0597x over previous
#include <cuda_runtime.h>
#include <math.h>
#include <stdint.h>

typedef unsigned long long u64;
typedef unsigned int u32;

// ---------------- problem constants ----------------
#define BN   2048
#define TSEQ 50
#define NSEQ 64
#define BB   32

// ---------------- device scratch ----------------
__device__ float g_xp0[(size_t)TSEQ * BN * 512];
__device__ float g_xp1[(size_t)TSEQ * BN * 512];
__device__ float g_hbuf[2][2 * BN * 128];
__device__ float g_cst[2 * BN * 128];
__device__ float g_hsum[2 * BN * 128];
__device__ float g_sentpres[(size_t)BN * 256];
__device__ float g_txp0[(size_t)NSEQ * BB * 512];
__device__ float g_txp1[(size_t)NSEQ * BB * 512];
__device__ float g_thbuf[2][2 * BB * 128];
__device__ float g_tag_out[(size_t)BN * 256];
__device__ float g_q[(size_t)BN * 256];
__device__ float g_k[(size_t)BN * 256];
__device__ float g_sentFt[(size_t)BN * 15];
__device__ float g_roleFt[(size_t)BN * 15];
__device__ float g_agg[(size_t)BN * 256];
__device__ int g_tbar2[2];
__device__ int g_tdone2[2];
__device__ int g_sbar[32];
__device__ int g_sdone[32];

// ---------------- f32x2 helpers ----------------
__device__ __forceinline__ u64 pk2(float lo, float hi) {
    u64 r; asm("mov.b64 %0, {%1, %2};" : "=l"(r) : "f"(lo), "f"(hi)); return r;
}
__device__ __forceinline__ void up2(u64 v, float& lo, float& hi) {
    asm("mov.b64 {%0, %1}, %2;" : "=f"(lo), "=f"(hi) : "l"(v));
}
__device__ __forceinline__ void fma2(u64& d, u64 a, u64 b) {
    asm("fma.rn.f32x2 %0, %1, %2, %0;" : "+l"(d) : "l"(a), "l"(b));
}

// ---------------- tf32 helpers ----------------
__device__ __forceinline__ float tf32_rna(float x) {
    u32 u; asm("cvt.rna.tf32.f32 %0, %1;" : "=r"(u) : "f"(x));
    return __uint_as_float(u);
}
__device__ __forceinline__ void mma_tf32(float* d, const u32* a, const u32* b) {
    asm("mma.sync.aligned.m16n8k8.row.col.f32.tf32.tf32.f32 "
        "{%0,%1,%2,%3},{%4,%5,%6,%7},{%8,%9},{%0,%1,%2,%3};"
        : "+f"(d[0]), "+f"(d[1]), "+f"(d[2]), "+f"(d[3])
        : "r"(a[0]), "r"(a[1]), "r"(a[2]), "r"(a[3]), "r"(b[0]), "r"(b[1]));
}

// ---------------- fast math ----------------
__device__ __forceinline__ float sigf(float x) {
    x = fminf(fmaxf(x, -30.f), 30.f);
    return __fdividef(1.f, 1.f + __expf(-x));
}
__device__ __forceinline__ float tanhfast(float x) {
    x = fminf(fmaxf(x, -15.f), 15.f);
    return __fdividef(2.f, 1.f + __expf(-2.f * x)) - 1.f;
}

// ============================================================
// K1: sentence input projection with tensor cores (3xTF32).
// (unchanged — validated)
// ============================================================
#define K1P 12
__global__ void __launch_bounds__(256) gemm_inproj_tc(
    const float* __restrict__ A,
    const float* __restrict__ B0, const float* __restrict__ B1,
    const float* __restrict__ bias0, const float* __restrict__ bias1)
{
    __shared__ float sAh[2][128 * K1P], sAl[2][128 * K1P];
    __shared__ float sBh[2][128 * K1P], sBl[2][128 * K1P];

    int m0 = blockIdx.x * 128;
    int nb = blockIdx.y;
    int dir = nb >> 2;
    int n0 = (nb & 3) * 128;
    const float* Bw = dir ? B1 : B0;
    const float* bias = dir ? bias1 : bias0;
    float* out = dir ? g_xp1 : g_xp0;

    int tid = threadIdx.x;
    int lane = tid & 31, warp = tid >> 5;
    int g = lane >> 2, tig = lane & 3;
    int wm = warp & 1, wn = warp >> 1;

    int srow = tid >> 1, shalf = tid & 1;
    const float* aP = A + (size_t)(m0 + srow) * 200 + shalf * 4;
    const float* bP = Bw + (size_t)(n0 + srow) * 200 + shalf * 4;

    float acc[4][4][4];
#pragma unroll
    for (int i = 0; i < 4; i++)
#pragma unroll
        for (int j = 0; j < 4; j++)
#pragma unroll
            for (int c = 0; c < 4; c++) acc[i][j][c] = 0.0f;

    float4 av = *(const float4*)aP;
    float4 bv = *(const float4*)bP;

    int soff = srow * K1P + shalf * 4;
#define K1_STAGE(buf, a4, b4) do {                                          \
        float4 _h, _l;                                                      \
        _h.x = tf32_rna(a4.x); _l.x = tf32_rna(a4.x - _h.x);                \
        _h.y = tf32_rna(a4.y); _l.y = tf32_rna(a4.y - _h.y);                \
        _h.z = tf32_rna(a4.z); _l.z = tf32_rna(a4.z - _h.z);                \
        _h.w = tf32_rna(a4.w); _l.w = tf32_rna(a4.w - _h.w);                \
        *(float4*)&sAh[buf][soff] = _h;                                     \
        *(float4*)&sAl[buf][soff] = _l;                                     \
        _h.x = tf32_rna(b4.x); _l.x = tf32_rna(b4.x - _h.x);                \
        _h.y = tf32_rna(b4.y); _l.y = tf32_rna(b4.y - _h.y);                \
        _h.z = tf32_rna(b4.z); _l.z = tf32_rna(b4.z - _h.z);                \
        _h.w = tf32_rna(b4.w); _l.w = tf32_rna(b4.w - _h.w);                \
        *(float4*)&sBh[buf][soff] = _h;                                     \
        *(float4*)&sBl[buf][soff] = _l;                                     \
    } while (0)

    K1_STAGE(0, av, bv);
    __syncthreads();

    for (int kt = 0; kt < 25; kt++) {
        int cur = kt & 1;
        if (kt < 24) {
            av = *(const float4*)(aP + (kt + 1) * 8);
            bv = *(const float4*)(bP + (kt + 1) * 8);
        }
        u32 bh[4][2], bl[4][2];
#pragma unroll
        for (int nt = 0; nt < 4; nt++) {
            int br = (wn * 32 + nt * 8 + g) * K1P;
            bh[nt][0] = __float_as_uint(sBh[cur][br + tig]);
            bh[nt][1] = __float_as_uint(sBh[cur][br + tig + 4]);
            bl[nt][0] = __float_as_uint(sBl[cur][br + tig]);
            bl[nt][1] = __float_as_uint(sBl[cur][br + tig + 4]);
        }
#pragma unroll
        for (int mt = 0; mt < 4; mt++) {
            int ar0 = (wm * 64 + mt * 16 + g) * K1P;
            int ar1 = ar0 + 8 * K1P;
            u32 ah[4], al[4];
            ah[0] = __float_as_uint(sAh[cur][ar0 + tig]);
            ah[1] = __float_as_uint(sAh[cur][ar1 + tig]);
            ah[2] = __float_as_uint(sAh[cur][ar0 + tig + 4]);
            ah[3] = __float_as_uint(sAh[cur][ar1 + tig + 4]);
            al[0] = __float_as_uint(sAl[cur][ar0 + tig]);
            al[1] = __float_as_uint(sAl[cur][ar1 + tig]);
            al[2] = __float_as_uint(sAl[cur][ar0 + tig + 4]);
            al[3] = __float_as_uint(sAl[cur][ar1 + tig + 4]);
#pragma unroll
            for (int nt = 0; nt < 4; nt++) {
                mma_tf32(acc[mt][nt], ah, bh[nt]);
                mma_tf32(acc[mt][nt], al, bh[nt]);
                mma_tf32(acc[mt][nt], ah, bl[nt]);
            }
        }
        __syncthreads();
        if (kt < 24) {
            K1_STAGE((kt + 1) & 1, av, bv);
            __syncthreads();
        }
    }

#pragma unroll
    for (int mt = 0; mt < 4; mt++) {
#pragma unroll
        for (int nt = 0; nt < 4; nt++) {
            int col = n0 + wn * 32 + nt * 8 + 2 * tig;
            float b0v = __ldg(bias + col), b1v = __ldg(bias + col + 1);
            int r0 = m0 + wm * 64 + mt * 16 + g;
            int p0 = r0 / 50, t0 = r0 - p0 * 50;
            float2 o0 = make_float2(acc[mt][nt][0] + b0v, acc[mt][nt][1] + b1v);
            *(float2*)(out + ((size_t)t0 * BN + p0) * 512 + col) = o0;
            int r1 = r0 + 8;
            int p1 = r1 / 50, t1 = r1 - p1 * 50;
            float2 o1 = make_float2(acc[mt][nt][2] + b0v, acc[mt][nt][3] + b1v);
            *(float2*)(out + ((size_t)t1 * BN + p1) * 512 + col) = o1;
        }
    }
}

// ============================================================
// Sentence LSTM: PERSISTENT tensor-core recurrence (unchanged)
// ============================================================
#define S5_WST   132
#define S5_HST   36
#define S5_WSZ   (128 * S5_WST)
#define S5_HBUF  (2 * 128 * S5_HST)
#define S5_SMEM  ((2 * S5_WSZ + 2 * S5_HBUF) * 4)

__global__ void __launch_bounds__(256, 1) lstm_sent5(
    const float* __restrict__ W0, const float* __restrict__ W1)
{
    extern __shared__ __align__(16) float s5[];
    float* sWh = s5;
    float* sWl = s5 + S5_WSZ;
    float* sH  = s5 + 2 * S5_WSZ;
    float* gsm = sH;

    int bid = blockIdx.x;
    int dir = bid >> 6;
    int rem = bid & 63;
    int pch = rem >> 2;
    int jch = rem & 3;
    int p0 = pch * 128;
    int j0 = jch * 32;
    int barIdx = pch * 2 + dir;

    const float* W = dir ? W1 : W0;
    const float* xp = dir ? g_xp1 : g_xp0;
    float* cD = g_cst + (size_t)dir * BN * 128;
    float* hsD = g_hsum + (size_t)dir * BN * 128;

    int tid = threadIdx.x;
    int lane = tid & 31, warp = tid >> 5;
    int g = lane >> 2, tig = lane & 3;
    int wm = warp & 1, wn = warp >> 1;

    {
        int row = tid >> 1;
        int gg = row >> 5, jr = row & 31;
        int half = tid & 1;
        const float* wrow = W + (size_t)(gg * 128 + j0 + jr) * 128 + half * 64;
        int so = row * S5_WST + half * 64;
#pragma unroll
        for (int q = 0; q < 16; q++) {
            float4 v = *(const float4*)(wrow + q * 4);
            float4 h4, l4;
            h4.x = tf32_rna(v.x); l4.x = tf32_rna(v.x - h4.x);
            h4.y = tf32_rna(v.y); l4.y = tf32_rna(v.y - h4.y);
            h4.z = tf32_rna(v.z); l4.z = tf32_rna(v.z - h4.z);
            h4.w = tf32_rna(v.w); l4.w = tf32_rna(v.w - h4.w);
            *(float4*)&sWh[so + q * 4] = h4;
            *(float4*)&sWl[so + q * 4] = l4;
        }
    }
    __syncthreads();

    int srow = tid >> 1;
    int shalf = tid & 1;

    for (int s = 0; s < TSEQ; s++) {
        int t = dir ? (TSEQ - 1 - s) : s;

        if (s > 0) {
            const float* hIn = g_hbuf[s & 1] + (size_t)dir * BN * 128;
            const float* aRow = hIn + (size_t)(p0 + srow) * 128 + shalf * 16;
            int hso = srow * S5_HST + shalf * 16;

            float acc[4][4][4];
#pragma unroll
            for (int i = 0; i < 4; i++)
#pragma unroll
                for (int j = 0; j < 4; j++)
#pragma unroll
                    for (int c = 0; c < 4; c++) acc[i][j][c] = 0.0f;

            {
                float* dh = sH + 0 * S5_HBUF;
                float* dl = dh + 128 * S5_HST;
#pragma unroll
                for (int q = 0; q < 4; q++) {
                    float4 v = *(const float4*)(aRow + q * 4);
                    float4 h4, l4;
                    h4.x = tf32_rna(v.x); l4.x = tf32_rna(v.x - h4.x);
                    h4.y = tf32_rna(v.y); l4.y = tf32_rna(v.y - h4.y);
                    h4.z = tf32_rna(v.z); l4.z = tf32_rna(v.z - h4.z);
                    h4.w = tf32_rna(v.w); l4.w = tf32_rna(v.w - h4.w);
                    *(float4*)&dh[hso + q * 4] = h4;
                    *(float4*)&dl[hso + q * 4] = l4;
                }
            }
            __syncthreads();

#pragma unroll
            for (int kc = 0; kc < 4; kc++) {
                int cur = kc & 1;
                float4 pre[4];
                if (kc < 3) {
#pragma unroll
                    for (int q = 0; q < 4; q++)
                        pre[q] = *(const float4*)(aRow + (kc + 1) * 32 + q * 4);
                }
                const float* bh_base = sWh;
                const float* bl_base = sWl;
                const float* ah_base = sH + cur * S5_HBUF;
                const float* al_base = ah_base + 128 * S5_HST;
#pragma unroll
                for (int kt = 0; kt < 4; kt++) {
                    int kbW = kc * 32 + kt * 8;
                    int kbH = kt * 8;
                    u32 bh[4][2], bl[4][2];
#pragma unroll
                    for (int nt = 0; nt < 4; nt++) {
                        int br = (wn * 32 + nt * 8 + g) * S5_WST + kbW;
                        bh[nt][0] = __float_as_uint(bh_base[br + tig]);
                        bh[nt][1] = __float_as_uint(bh_base[br + tig + 4]);
                        bl[nt][0] = __float_as_uint(bl_base[br + tig]);
                        bl[nt][1] = __float_as_uint(bl_base[br + tig + 4]);
                    }
#pragma unroll
                    for (int mt = 0; mt < 4; mt++) {
                        int ar0 = (wm * 64 + mt * 16 + g) * S5_HST + kbH;
                        int ar1 = ar0 + 8 * S5_HST;
                        u32 ah[4], al[4];
                        ah[0] = __float_as_uint(ah_base[ar0 + tig]);
                        ah[1] = __float_as_uint(ah_base[ar1 + tig]);
                        ah[2] = __float_as_uint(ah_base[ar0 + tig + 4]);
                        ah[3] = __float_as_uint(ah_base[ar1 + tig + 4]);
                        al[0] = __float_as_uint(al_base[ar0 + tig]);
                        al[1] = __float_as_uint(al_base[ar1 + tig]);
                        al[2] = __float_as_uint(al_base[ar0 + tig + 4]);
                        al[3] = __float_as_uint(al_base[ar1 + tig + 4]);
#pragma unroll
                        for (int nt = 0; nt < 4; nt++) {
                            mma_tf32(acc[mt][nt], ah, bh[nt]);
                            mma_tf32(acc[mt][nt], al, bh[nt]);
                            mma_tf32(acc[mt][nt], ah, bl[nt]);
                        }
                    }
                }
                if (kc < 3) {
                    float* dh = sH + (1 - cur) * S5_HBUF;
                    float* dl = dh + 128 * S5_HST;
#pragma unroll
                    for (int q = 0; q < 4; q++) {
                        float4 v = pre[q];
                        float4 h4, l4;
                        h4.x = tf32_rna(v.x); l4.x = tf32_rna(v.x - h4.x);
                        h4.y = tf32_rna(v.y); l4.y = tf32_rna(v.y - h4.y);
                        h4.z = tf32_rna(v.z); l4.z = tf32_rna(v.z - h4.z);
                        h4.w = tf32_rna(v.w); l4.w = tf32_rna(v.w - h4.w);
                        *(float4*)&dh[hso + q * 4] = h4;
                        *(float4*)&dl[hso + q * 4] = l4;
                    }
                }
                __syncthreads();
            }

#pragma unroll
            for (int mt = 0; mt < 4; mt++) {
                int r0 = wm * 64 + mt * 16 + g;
#pragma unroll
                for (int nt = 0; nt < 4; nt++) {
                    int col = wn * 32 + nt * 8 + 2 * tig;
                    *(float2*)&gsm[r0 * 132 + col] =
                        make_float2(acc[mt][nt][0], acc[mt][nt][1]);
                    *(float2*)&gsm[(r0 + 8) * 132 + col] =
                        make_float2(acc[mt][nt][2], acc[mt][nt][3]);
                }
            }
            __syncthreads();
        }

        float* hOut = g_hbuf[(s + 1) & 1] + (size_t)dir * BN * 128;
        size_t xbase = (size_t)t * BN * 512;
#pragma unroll
        for (int i = 0; i < 16; i++) {
            int pj = tid + i * 256;
            int pp = pj >> 5, jj = pj & 31;
            int p = p0 + pp;
            int j = j0 + jj;
            const float* xr = xp + xbase + (size_t)p * 512 + j;
            float gi = xr[0], gf = xr[128], gg2 = xr[256], go = xr[384];
            if (s > 0) {
                gi  += gsm[pp * 132 + jj];
                gf  += gsm[pp * 132 + 32 + jj];
                gg2 += gsm[pp * 132 + 64 + jj];
                go  += gsm[pp * 132 + 96 + jj];
            }
            size_t hidx = (size_t)p * 128 + j;
            float cold = (s == 0) ? 0.0f : cD[hidx];
            float cn = sigf(gf) * cold + sigf(gi) * tanhfast(gg2);
            float hn = sigf(go) * tanhfast(cn);
            if (s == TSEQ - 1) {
                float hs = hsD[hidx] + hn;
                g_sentpres[(size_t)p * 256 + dir * 128 + j] =
                    tanhfast(hs * (1.0f / 50.0f));
            } else {
                cD[hidx] = cn;
                hOut[hidx] = hn;
                hsD[hidx] = (s == 0) ? hn : (hsD[hidx] + hn);
            }
        }

        if (s < TSEQ - 1) {
            __syncthreads();
            if (tid == 0) {
                __threadfence();
                atomicAdd(&g_sbar[barIdx], 1);
                int target = 4 * (s + 1);
                while (*(volatile int*)&g_sbar[barIdx] < target) { }
                __threadfence();
            }
            __syncthreads();
        }
    }

    __syncthreads();
    if (tid == 0) {
        int old = atomicAdd(&g_sdone[barIdx], 1);
        if (old == 3) {
            g_sbar[barIdx] = 0;
            __threadfence();
            g_sdone[barIdx] = 0;
        }
    }
}

// ============================================================
// Dual-half GEMM with f32x2 (modes 1-4, unchanged)
// ============================================================
template <int MODE>
__global__ void __launch_bounds__(256) gemm_dual(
    const float* __restrict__ Aparam, int M, int K, int NB,
    const float* __restrict__ B0, const float* __restrict__ B1,
    const float* __restrict__ bias0, const float* __restrict__ bias1,
    float* __restrict__ outParam)
{
    __shared__ __align__(16) u64 As2[8][128];
    __shared__ __align__(16) float Bs[8][128];

    const float* A;
    if (MODE == 1 || MODE == 2) A = g_sentpres;
    else if (MODE == 3) A = g_tag_out;
    else A = g_agg;
    (void)Aparam;

    int hsel = (blockIdx.y * 128) / NB;
    int g0 = blockIdx.y * 128 - hsel * NB;
    int m0 = blockIdx.x * 128;

    const float* B = hsel ? B1 : B0;
    const float* bias = hsel ? bias1 : bias0;

    float* out;
    if (MODE == 1) out = hsel ? g_txp1 : g_txp0;
    else if (MODE == 2 || MODE == 3) out = hsel ? g_k : g_q;
    else out = outParam;

    int tid = threadIdx.x;
    int tx = tid & 15;
    int ty = tid >> 4;
    int lr = tid >> 1;
    int lc4 = tid & 1;

    u64 acc2[8][4];
#pragma unroll
    for (int i = 0; i < 8; i++)
#pragma unroll
        for (int j = 0; j < 4; j++) acc2[i][j] = 0ULL;

    int KT = K / 8;
    const float* aPtr = A + (size_t)(m0 + lr) * K + lc4 * 4;
    const float* bPtr = B + (size_t)(g0 + lr) * K + lc4 * 4;
    float4 av = *(const float4*)(aPtr);
    float4 bv = *(const float4*)(bPtr);

    for (int kt = 0; kt < KT; kt++) {
        As2[lc4 * 4 + 0][lr] = pk2(av.x, av.x);
        As2[lc4 * 4 + 1][lr] = pk2(av.y, av.y);
        As2[lc4 * 4 + 2][lr] = pk2(av.z, av.z);
        As2[lc4 * 4 + 3][lr] = pk2(av.w, av.w);
        Bs[lc4 * 4 + 0][lr] = bv.x; Bs[lc4 * 4 + 1][lr] = bv.y;
        Bs[lc4 * 4 + 2][lr] = bv.z; Bs[lc4 * 4 + 3][lr] = bv.w;
        __syncthreads();
        if (kt + 1 < KT) {
            av = *(const float4*)(aPtr + (kt + 1) * 8);
            bv = *(const float4*)(bPtr + (kt + 1) * 8);
        }
#pragma unroll
        for (int kk = 0; kk < 8; kk++) {
            u64 b2[4];
#pragma unroll
            for (int jq = 0; jq < 4; jq++)
                b2[jq] = *(const u64*)&Bs[kk][2 * (tx + 16 * jq)];
            u64 a2[8];
#pragma unroll
            for (int i = 0; i < 8; i++) a2[i] = As2[kk][ty * 8 + i];
#pragma unroll
            for (int i = 0; i < 8; i++)
#pragma unroll
                for (int jq = 0; jq < 4; jq++)
                    fma2(acc2[i][jq], a2[i], b2[jq]);
        }
        __syncthreads();
    }

#pragma unroll
    for (int i = 0; i < 8; i++) {
        int m = m0 + ty * 8 + i;
        size_t rowbase;
        if (MODE == 1) {
            int b = m >> 6; int n = m & 63;
            rowbase = ((size_t)n * BB + b) * 512;
        } else {
            rowbase = (size_t)m * 256;
        }
#pragma unroll
        for (int jq = 0; jq < 4; jq++) {
            int g = g0 + 2 * (tx + 16 * jq);
            float lo, hi;
            up2(acc2[i][jq], lo, hi);
            float2 bb = *(const float2*)(bias + g);
            float2 o;
            o.x = lo + bb.x;
            o.y = hi + bb.y;
            if (MODE == 4) { o.x = fmaxf(o.x, 0.f); o.y = fmaxf(o.y, 0.f); }
            *(float2*)(out + rowbase + g) = o;
        }
    }
}

// ============================================================
// Persistent tag BiLSTM v3: TENSOR CORES (3xTF32).
// 16 blocks (2 dir x 8 j-chunks of 16). Per block: m=32 (batch),
// n=64 (4 gates x 16 j), k=128. W hi/lo staged ONCE (stride 132);
// h hi/lo staged per step (stride 132 — FULL 128-k rows, R9 bug was
// stride 36 overflow); gates via separate smem tile.
// Per-dir barrier: 8 arrivals. c state in 2 regs/thread.
// smem: W 2*64*132 + h 2*32*132 + gates 32*68 = 110080 B.
// ============================================================
#define TG2_WST  132
#define TG2_HST  132
#define TG2_WSZ  (64 * TG2_WST)
#define TG2_HSZ  (32 * TG2_HST)
#define TG2_SMEM ((2 * TG2_WSZ + 2 * TG2_HSZ + 32 * 68) * 4)

__global__ void __launch_bounds__(256) tag_persistent_tc(
    const float* __restrict__ W0, const float* __restrict__ W1)
{
    extern __shared__ __align__(16) float tg2[];
    float* sWh = tg2;
    float* sWl = tg2 + TG2_WSZ;
    float* sHh = tg2 + 2 * TG2_WSZ;
    float* sHl = sHh + TG2_HSZ;
    float* gsm = sHl + TG2_HSZ;            // [32][68]

    int dir = blockIdx.x >> 3;
    int jc = blockIdx.x & 7;
    int j0 = jc * 16;
    const float* W = dir ? W1 : W0;
    const float* xp = dir ? g_txp1 : g_txp0;

    int tid = threadIdx.x;
    int lane = tid & 31, warp = tid >> 5;
    int g = lane >> 2, tig = lane & 3;

    // ---- stage W hi/lo ONCE: 64 rows (gate*16+jr) x 128 k ----
    {
        int row = tid >> 2;               // 0..63
        int gg = row >> 4, jr = row & 15;
        int kq = (tid & 3) * 32;
        const float* wrow = W + (size_t)(gg * 128 + j0 + jr) * 128 + kq;
        int so = row * TG2_WST + kq;
#pragma unroll
        for (int q = 0; q < 8; q++) {
            float4 v = *(const float4*)(wrow + q * 4);
            float4 h4, l4;
            h4.x = tf32_rna(v.x); l4.x = tf32_rna(v.x - h4.x);
            h4.y = tf32_rna(v.y); l4.y = tf32_rna(v.y - h4.y);
            h4.z = tf32_rna(v.z); l4.z = tf32_rna(v.z - h4.z);
            h4.w = tf32_rna(v.w); l4.w = tf32_rna(v.w - h4.w);
            *(float4*)&sWh[so + q * 4] = h4;
            *(float4*)&sWl[so + q * 4] = l4;
        }
    }
    __syncthreads();

    float creg[2] = {0.f, 0.f};
    int* bar = &g_tbar2[dir];

    for (int s = 0; s < NSEQ; s++) {
        int t = dir ? (NSEQ - 1 - s) : s;

        if (s > 0) {
            // ---- stage h hi/lo: 32 rows x 128 k (stride 132) ----
            const float* hIn = g_thbuf[s & 1] + (size_t)dir * BB * 128;
            {
                int row = tid >> 3;        // 0..31
                int kq = (tid & 7) * 16;
                const float* hrow = hIn + (size_t)row * 128 + kq;
                int so = row * TG2_HST + kq;
#pragma unroll
                for (int q = 0; q < 4; q++) {
                    float4 v = *(const float4*)(hrow + q * 4);
                    float4 h4, l4;
                    h4.x = tf32_rna(v.x); l4.x = tf32_rna(v.x - h4.x);
                    h4.y = tf32_rna(v.y); l4.y = tf32_rna(v.y - h4.y);
                    h4.z = tf32_rna(v.z); l4.z = tf32_rna(v.z - h4.z);
                    h4.w = tf32_rna(v.w); l4.w = tf32_rna(v.w - h4.w);
                    *(float4*)&sHh[so + q * 4] = h4;
                    *(float4*)&sHl[so + q * 4] = l4;
                }
            }
            __syncthreads();

            // ---- mma: warp = n-tile (cols warp*8..+7), m tiles 0,1 ----
            float acc[2][4];
#pragma unroll
            for (int mt = 0; mt < 2; mt++)
#pragma unroll
                for (int c = 0; c < 4; c++) acc[mt][c] = 0.0f;

#pragma unroll
            for (int kt = 0; kt < 16; kt++) {
                int kb = kt * 8;
                int br = (warp * 8 + g) * TG2_WST + kb;
                u32 bh[2], bl[2];
                bh[0] = __float_as_uint(sWh[br + tig]);
                bh[1] = __float_as_uint(sWh[br + tig + 4]);
                bl[0] = __float_as_uint(sWl[br + tig]);
                bl[1] = __float_as_uint(sWl[br + tig + 4]);
#pragma unroll
                for (int mt = 0; mt < 2; mt++) {
                    int ar0 = (mt * 16 + g) * TG2_HST + kb;
                    int ar1 = ar0 + 8 * TG2_HST;
                    u32 ah[4], al[4];
                    ah[0] = __float_as_uint(sHh[ar0 + tig]);
                    ah[1] = __float_as_uint(sHh[ar1 + tig]);
                    ah[2] = __float_as_uint(sHh[ar0 + tig + 4]);
                    ah[3] = __float_as_uint(sHh[ar1 + tig + 4]);
                    al[0] = __float_as_uint(sHl[ar0 + tig]);
                    al[1] = __float_as_uint(sHl[ar1 + tig]);
                    al[2] = __float_as_uint(sHl[ar0 + tig + 4]);
                    al[3] = __float_as_uint(sHl[ar1 + tig + 4]);
                    mma_tf32(acc[mt], ah, bh);
                    mma_tf32(acc[mt], al, bh);
                    mma_tf32(acc[mt], ah, bl);
                }
            }

            // ---- gates to gsm [32][68] ----
#pragma unroll
            for (int mt = 0; mt < 2; mt++) {
                int r0 = mt * 16 + g;
                int col = warp * 8 + 2 * tig;
                *(float2*)&gsm[r0 * 68 + col] = make_float2(acc[mt][0], acc[mt][1]);
                *(float2*)&gsm[(r0 + 8) * 68 + col] = make_float2(acc[mt][2], acc[mt][3]);
            }
            __syncthreads();
        }

        // ---- fused LSTM epilogue: 32 b x 16 j = 512 outputs ----
        float* hOut = g_thbuf[(s + 1) & 1] + (size_t)dir * BB * 128;
#pragma unroll
        for (int u = 0; u < 2; u++) {
            int idx = tid + u * 256;
            int b = idx >> 4, jj = idx & 15;
            const float* xr = xp + ((size_t)t * BB + b) * 512 + j0 + jj;
            float gi = xr[0], gf = xr[128], gg2 = xr[256], go = xr[384];
            if (s > 0) {
                gi  += gsm[b * 68 + jj];
                gf  += gsm[b * 68 + 16 + jj];
                gg2 += gsm[b * 68 + 32 + jj];
                go  += gsm[b * 68 + 48 + jj];
            }
            float cn = sigf(gf) * creg[u] + sigf(gi) * tanhfast(gg2);
            float hn = sigf(go) * tanhfast(cn);
            creg[u] = cn;
            hOut[(size_t)b * 128 + j0 + jj] = hn;
            g_tag_out[((size_t)b * NSEQ + t) * 256 + dir * 128 + j0 + jj] = tanhfast(hn);
        }

        if (s < NSEQ - 1) {
            __syncthreads();
            if (tid == 0) {
                __threadfence();
                atomicAdd(bar, 1);
                int target = 8 * (s + 1);
                while (*(volatile int*)bar < target) { }
                __threadfence();
            }
            __syncthreads();
        }
    }

    // deterministic counter reset for next graph replay
    __syncthreads();
    if (tid == 0) {
        int old = atomicAdd(&g_tdone2[dir], 1);
        if (old == 7) {
            g_tbar2[dir] = 0;
            __threadfence();
            g_tdone2[dir] = 0;
        }
    }
}

// ---------------- SPP ----------------
__global__ void __launch_bounds__(256) spp_kernel(int which) {
    int b = blockIdx.x;
    int tid = threadIdx.x;
    __shared__ float qs[64][33];
    __shared__ float ks[64][33];
    __shared__ float segs[64][8];

    float acc[16];
#pragma unroll
    for (int i = 0; i < 16; i++) acc[i] = 0.0f;
    int n = tid >> 2;
    int mBase = (tid & 3) * 16;

    for (int d0 = 0; d0 < 256; d0 += 32) {
        __syncthreads();
        for (int idx = tid; idx < 64 * 32; idx += 256) {
            int r = idx >> 5, cc = idx & 31;
            size_t gi = ((size_t)(b * 64 + r)) * 256 + d0 + cc;
            qs[r][cc] = g_q[gi];
            ks[r][cc] = g_k[gi];
        }
        __syncthreads();
#pragma unroll 4
        for (int dd = 0; dd < 32; dd++) {
            float qv = qs[n][dd];
#pragma unroll
            for (int mm = 0; mm < 16; mm++)
                acc[mm] += qv * ks[mBase + mm][dd];
        }
    }
    float s8a = -3.4e38f, s8b = -3.4e38f;
#pragma unroll
    for (int mm = 0; mm < 8; mm++)  s8a = fmaxf(s8a, acc[mm]);
#pragma unroll
    for (int mm = 8; mm < 16; mm++) s8b = fmaxf(s8b, acc[mm]);
    segs[n][(tid & 3) * 2 + 0] = s8a * 0.0625f;
    segs[n][(tid & 3) * 2 + 1] = s8b * 0.0625f;
    __syncthreads();

    if (tid < 64) {
        float e[8];
#pragma unroll
        for (int i = 0; i < 8; i++) e[i] = segs[tid][i];
        float q4[4], h2[2];
#pragma unroll
        for (int i = 0; i < 4; i++) q4[i] = fmaxf(e[2 * i], e[2 * i + 1]);
        h2[0] = fmaxf(q4[0], q4[1]);
        h2[1] = fmaxf(q4[2], q4[3]);
        float a1 = fmaxf(h2[0], h2[1]);
        float* o = (which ? g_roleFt : g_sentFt) + (size_t)(b * 64 + tid) * 15;
        o[0] = a1;
        o[1] = h2[0]; o[2] = h2[1];
#pragma unroll
        for (int i = 0; i < 4; i++) o[3 + i] = q4[i];
#pragma unroll
        for (int i = 0; i < 8; i++) o[7 + i] = e[i];
    }
}

// ---------------- GCN pre ----------------
__global__ void __launch_bounds__(256) gcn_pre() {
    int b = blockIdx.x;
    int tid = threadIdx.x;
    __shared__ float cosm[64][65];
    __shared__ float xs[64][33];
    __shared__ float inv[64];

    if (tid < 64) {
        const float* xr = g_tag_out + (size_t)(b * 64 + tid) * 256;
        float s = 0.0f;
        for (int d = 0; d < 256; d++) { float v = xr[d]; s += v * v; }
        inv[tid] = 1.0f / (sqrtf(s) + 1e-8f);
    }

    float acc[16];
#pragma unroll
    for (int i = 0; i < 16; i++) acc[i] = 0.0f;
    int n = tid >> 2;
    int mBase = (tid & 3) * 16;

    for (int d0 = 0; d0 < 256; d0 += 32) {
        __syncthreads();
        for (int idx = tid; idx < 64 * 32; idx += 256) {
            int r = idx >> 5, cc = idx & 31;
            xs[r][cc] = g_tag_out[((size_t)(b * 64 + r)) * 256 + d0 + cc];
        }
        __syncthreads();
#pragma unroll 4
        for (int dd = 0; dd < 32; dd++) {
            float xv = xs[n][dd];
#pragma unroll
            for (int mm = 0; mm < 16; mm++)
                acc[mm] += xv * xs[mBase + mm][dd];
        }
    }
#pragma unroll
    for (int mm = 0; mm < 16; mm++)
        cosm[n][mBase + mm] = acc[mm] * inv[n] * inv[mBase + mm];

    int ddBase = (tid & 3) * 8;
    for (int d0 = 0; d0 < 256; d0 += 32) {
        __syncthreads();
        for (int idx = tid; idx < 64 * 32; idx += 256) {
            int r = idx >> 5, cc = idx & 31;
            xs[r][cc] = g_tag_out[((size_t)(b * 64 + r)) * 256 + d0 + cc];
        }
        __syncthreads();
        float r8[8];
#pragma unroll
        for (int i = 0; i < 8; i++) r8[i] = 0.0f;
        for (int m = 0; m < 64; m++) {
            float cv = cosm[n][m];
#pragma unroll
            for (int i = 0; i < 8; i++) r8[i] += cv * xs[m][ddBase + i];
        }
#pragma unroll
        for (int i = 0; i < 8; i++) {
            float v = (r8[i] + 2.0f * xs[n][ddBase + i]) * (1.0f / 66.0f);
            g_agg[(size_t)(b * 64 + n) * 256 + d0 + ddBase + i] = v;
        }
    }
}

// ---------------- classifier + log_softmax ----------------
__global__ void __launch_bounds__(256) cls_kernel(
    const float* __restrict__ W, const float* __restrict__ bias,
    float* __restrict__ out)
{
    __shared__ float Wsh[8][288];
    __shared__ float bsh[8];
    __shared__ float ftile[256][33];

    int tid = threadIdx.x;
    for (int i = tid; i < 8 * 286; i += 256) Wsh[i / 286][i % 286] = W[i];
    if (tid < 8) bsh[tid] = bias[tid];
    __syncthreads();

    int p0 = blockIdx.x * 256;
    int p = p0 + tid;
    float z[8];
#pragma unroll
    for (int c = 0; c < 8; c++) z[c] = bsh[c];

    for (int d0 = 0; d0 < 256; d0 += 32) {
        __syncthreads();
        for (int idx = tid; idx < 256 * 32; idx += 256) {
            int r = idx >> 5, cc = idx & 31;
            ftile[r][cc] = g_tag_out[(size_t)(p0 + r) * 256 + d0 + cc];
        }
        __syncthreads();
#pragma unroll 4
        for (int dd = 0; dd < 32; dd++) {
            float f = ftile[tid][dd];
#pragma unroll
            for (int c = 0; c < 8; c++) z[c] += f * Wsh[c][d0 + dd];
        }
    }
#pragma unroll
    for (int d = 0; d < 15; d++) {
        float f = g_sentFt[(size_t)p * 15 + d];
#pragma unroll
        for (int c = 0; c < 8; c++) z[c] += f * Wsh[c][256 + d];
    }
#pragma unroll
    for (int d = 0; d < 15; d++) {
        float f = g_roleFt[(size_t)p * 15 + d];
#pragma unroll
        for (int c = 0; c < 8; c++) z[c] += f * Wsh[c][271 + d];
    }
    float m = z[0];
#pragma unroll
    for (int c = 1; c < 8; c++) m = fmaxf(m, z[c]);
    float se = 0.0f;
#pragma unroll
    for (int c = 0; c < 8; c++) se += expf(z[c] - m);
    float lse = m + logf(se);
#pragma unroll
    for (int c = 0; c < 8; c++) out[(size_t)p * 8 + c] = z[c] - lse;
}

// ============================================================
extern "C" void kernel_launch(void* const* d_in, const int* in_sizes, int n_in,
                              void* d_out, int out_size)
{
    (void)in_sizes; (void)n_in; (void)out_size;
    const float* documents = (const float*)d_in[0];
    const float* sw_ih_f = (const float*)d_in[1];
    const float* sw_hh_f = (const float*)d_in[2];
    const float* sb_f    = (const float*)d_in[3];
    const float* sw_ih_b = (const float*)d_in[4];
    const float* sw_hh_b = (const float*)d_in[5];
    const float* sb_b    = (const float*)d_in[6];
    const float* sf_Wq   = (const float*)d_in[7];
    const float* sf_bq   = (const float*)d_in[8];
    const float* sf_Wk   = (const float*)d_in[9];
    const float* sf_bk   = (const float*)d_in[10];
    const float* rf_Wq   = (const float*)d_in[11];
    const float* rf_bq   = (const float*)d_in[12];
    const float* rf_Wk   = (const float*)d_in[13];
    const float* rf_bk   = (const float*)d_in[14];
    const float* tw_ih_f = (const float*)d_in[15];
    const float* tw_hh_f = (const float*)d_in[16];
    const float* tb_f    = (const float*)d_in[17];
    const float* tw_ih_b = (const float*)d_in[18];
    const float* tw_hh_b = (const float*)d_in[19];
    const float* tb_b    = (const float*)d_in[20];
    const float* sage_W  = (const float*)d_in[21];
    const float* sage_b  = (const float*)d_in[22];
    const float* cls_W   = (const float*)d_in[23];
    const float* cls_b   = (const float*)d_in[24];
    float* out = (float*)d_out;

    cudaFuncSetAttribute(lstm_sent5, cudaFuncAttributeMaxDynamicSharedMemorySize, S5_SMEM);
    cudaFuncSetAttribute(tag_persistent_tc, cudaFuncAttributeMaxDynamicSharedMemorySize, TG2_SMEM);

    // 1) sentence BiLSTM input projection: tensor cores, 3xTF32
    gemm_inproj_tc<<<dim3(800, 8), 256>>>(documents, sw_ih_f, sw_ih_b, sb_f, sb_b);
    // 2) sentence recurrence: ONE persistent tensor-core kernel
    lstm_sent5<<<128, 256, S5_SMEM>>>(sw_hh_f, sw_hh_b);
    // 3) tag BiLSTM input projection
    gemm_dual<1><<<dim3(16, 8), 256>>>(nullptr, 2048, 256, 512,
                                       tw_ih_f, tw_ih_b, tb_f, tb_b, nullptr);
    // 4) tag recurrence: persistent TENSOR-CORE kernel
    tag_persistent_tc<<<16, 256, TG2_SMEM>>>(tw_hh_f, tw_hh_b);
    // 5) SPP on sentpres -> sentFt
    gemm_dual<2><<<dim3(16, 4), 256>>>(nullptr, 2048, 256, 256,
                                       sf_Wq, sf_Wk, sf_bq, sf_bk, nullptr);
    spp_kernel<<<32, 256>>>(0);
    // 6) SPP on tag_out -> roleFt
    gemm_dual<3><<<dim3(16, 4), 256>>>(nullptr, 2048, 256, 256,
                                       rf_Wq, rf_Wk, rf_bq, rf_bk, nullptr);
    spp_kernel<<<32, 256>>>(1);
    // 7) GCN
    gcn_pre<<<32, 256>>>();
    gemm_dual<4><<<dim3(16, 2), 256>>>(nullptr, 2048, 256, 256,
                                       sage_W, sage_W, sage_b, sage_b, out + 16384);
    // 8) classifier + log_softmax
    cls_kernel<<<8, 256>>>(cls_W, cls_b, out);
}

// round 11
// speedup vs baseline: 1.5647x; 1.0034x over previous
#include <cuda_runtime.h>
#include <math.h>
#include <stdint.h>

typedef unsigned long long u64;
typedef unsigned int u32;

// ---------------- problem constants ----------------
#define BN   2048
#define TSEQ 50
#define NSEQ 64
#define BB   32

// ---------------- device scratch ----------------
__device__ float g_xp0[(size_t)TSEQ * BN * 512];
__device__ float g_xp1[(size_t)TSEQ * BN * 512];
__device__ float g_hbuf[2][2 * BN * 128];
__device__ float g_cst[2 * BN * 128];
__device__ float g_hsum[2 * BN * 128];
__device__ float g_sentpres[(size_t)BN * 256];
__device__ float g_txp0[(size_t)NSEQ * BB * 512];
__device__ float g_txp1[(size_t)NSEQ * BB * 512];
__device__ float g_thbuf[2][2 * BB * 128];
__device__ float g_tag_out[(size_t)BN * 256];
__device__ float g_q[(size_t)BN * 256];
__device__ float g_k[(size_t)BN * 256];
__device__ float g_sentFt[(size_t)BN * 15];
__device__ float g_roleFt[(size_t)BN * 15];
__device__ float g_agg[(size_t)BN * 256];
// Barrier counters: ONE PER 128-BYTE LINE (32 ints) — packed counters
// caused LTS line ping-pong that serialized every persistent-kernel step.
__device__ int g_tbar2[2 * 32];
__device__ int g_tdone2[2 * 32];
__device__ int g_sbar[32 * 32];
__device__ int g_sdone[32 * 32];

// ---------------- f32x2 helpers ----------------
__device__ __forceinline__ u64 pk2(float lo, float hi) {
    u64 r; asm("mov.b64 %0, {%1, %2};" : "=l"(r) : "f"(lo), "f"(hi)); return r;
}
__device__ __forceinline__ void up2(u64 v, float& lo, float& hi) {
    asm("mov.b64 {%0, %1}, %2;" : "=f"(lo), "=f"(hi) : "l"(v));
}
__device__ __forceinline__ void fma2(u64& d, u64 a, u64 b) {
    asm("fma.rn.f32x2 %0, %1, %2, %0;" : "+l"(d) : "l"(a), "l"(b));
}

// ---------------- tf32 helpers ----------------
__device__ __forceinline__ float tf32_rna(float x) {
    u32 u; asm("cvt.rna.tf32.f32 %0, %1;" : "=r"(u) : "f"(x));
    return __uint_as_float(u);
}
__device__ __forceinline__ void mma_tf32(float* d, const u32* a, const u32* b) {
    asm("mma.sync.aligned.m16n8k8.row.col.f32.tf32.tf32.f32 "
        "{%0,%1,%2,%3},{%4,%5,%6,%7},{%8,%9},{%0,%1,%2,%3};"
        : "+f"(d[0]), "+f"(d[1]), "+f"(d[2]), "+f"(d[3])
        : "r"(a[0]), "r"(a[1]), "r"(a[2]), "r"(a[3]), "r"(b[0]), "r"(b[1]));
}

// ---------------- fast math ----------------
__device__ __forceinline__ float sigf(float x) {
    x = fminf(fmaxf(x, -30.f), 30.f);
    return __fdividef(1.f, 1.f + __expf(-x));
}
__device__ __forceinline__ float tanhfast(float x) {
    x = fminf(fmaxf(x, -15.f), 15.f);
    return __fdividef(2.f, 1.f + __expf(-2.f * x)) - 1.f;
}

// ============================================================
// K1: sentence input projection with tensor cores (3xTF32).
// (unchanged — validated)
// ============================================================
#define K1P 12
__global__ void __launch_bounds__(256) gemm_inproj_tc(
    const float* __restrict__ A,
    const float* __restrict__ B0, const float* __restrict__ B1,
    const float* __restrict__ bias0, const float* __restrict__ bias1)
{
    __shared__ float sAh[2][128 * K1P], sAl[2][128 * K1P];
    __shared__ float sBh[2][128 * K1P], sBl[2][128 * K1P];

    int m0 = blockIdx.x * 128;
    int nb = blockIdx.y;
    int dir = nb >> 2;
    int n0 = (nb & 3) * 128;
    const float* Bw = dir ? B1 : B0;
    const float* bias = dir ? bias1 : bias0;
    float* out = dir ? g_xp1 : g_xp0;

    int tid = threadIdx.x;
    int lane = tid & 31, warp = tid >> 5;
    int g = lane >> 2, tig = lane & 3;
    int wm = warp & 1, wn = warp >> 1;

    int srow = tid >> 1, shalf = tid & 1;
    const float* aP = A + (size_t)(m0 + srow) * 200 + shalf * 4;
    const float* bP = Bw + (size_t)(n0 + srow) * 200 + shalf * 4;

    float acc[4][4][4];
#pragma unroll
    for (int i = 0; i < 4; i++)
#pragma unroll
        for (int j = 0; j < 4; j++)
#pragma unroll
            for (int c = 0; c < 4; c++) acc[i][j][c] = 0.0f;

    float4 av = *(const float4*)aP;
    float4 bv = *(const float4*)bP;

    int soff = srow * K1P + shalf * 4;
#define K1_STAGE(buf, a4, b4) do {                                          \
        float4 _h, _l;                                                      \
        _h.x = tf32_rna(a4.x); _l.x = tf32_rna(a4.x - _h.x);                \
        _h.y = tf32_rna(a4.y); _l.y = tf32_rna(a4.y - _h.y);                \
        _h.z = tf32_rna(a4.z); _l.z = tf32_rna(a4.z - _h.z);                \
        _h.w = tf32_rna(a4.w); _l.w = tf32_rna(a4.w - _h.w);                \
        *(float4*)&sAh[buf][soff] = _h;                                     \
        *(float4*)&sAl[buf][soff] = _l;                                     \
        _h.x = tf32_rna(b4.x); _l.x = tf32_rna(b4.x - _h.x);                \
        _h.y = tf32_rna(b4.y); _l.y = tf32_rna(b4.y - _h.y);                \
        _h.z = tf32_rna(b4.z); _l.z = tf32_rna(b4.z - _h.z);                \
        _h.w = tf32_rna(b4.w); _l.w = tf32_rna(b4.w - _h.w);                \
        *(float4*)&sBh[buf][soff] = _h;                                     \
        *(float4*)&sBl[buf][soff] = _l;                                     \
    } while (0)

    K1_STAGE(0, av, bv);
    __syncthreads();

    for (int kt = 0; kt < 25; kt++) {
        int cur = kt & 1;
        if (kt < 24) {
            av = *(const float4*)(aP + (kt + 1) * 8);
            bv = *(const float4*)(bP + (kt + 1) * 8);
        }
        u32 bh[4][2], bl[4][2];
#pragma unroll
        for (int nt = 0; nt < 4; nt++) {
            int br = (wn * 32 + nt * 8 + g) * K1P;
            bh[nt][0] = __float_as_uint(sBh[cur][br + tig]);
            bh[nt][1] = __float_as_uint(sBh[cur][br + tig + 4]);
            bl[nt][0] = __float_as_uint(sBl[cur][br + tig]);
            bl[nt][1] = __float_as_uint(sBl[cur][br + tig + 4]);
        }
#pragma unroll
        for (int mt = 0; mt < 4; mt++) {
            int ar0 = (wm * 64 + mt * 16 + g) * K1P;
            int ar1 = ar0 + 8 * K1P;
            u32 ah[4], al[4];
            ah[0] = __float_as_uint(sAh[cur][ar0 + tig]);
            ah[1] = __float_as_uint(sAh[cur][ar1 + tig]);
            ah[2] = __float_as_uint(sAh[cur][ar0 + tig + 4]);
            ah[3] = __float_as_uint(sAh[cur][ar1 + tig + 4]);
            al[0] = __float_as_uint(sAl[cur][ar0 + tig]);
            al[1] = __float_as_uint(sAl[cur][ar1 + tig]);
            al[2] = __float_as_uint(sAl[cur][ar0 + tig + 4]);
            al[3] = __float_as_uint(sAl[cur][ar1 + tig + 4]);
#pragma unroll
            for (int nt = 0; nt < 4; nt++) {
                mma_tf32(acc[mt][nt], ah, bh[nt]);
                mma_tf32(acc[mt][nt], al, bh[nt]);
                mma_tf32(acc[mt][nt], ah, bl[nt]);
            }
        }
        __syncthreads();
        if (kt < 24) {
            K1_STAGE((kt + 1) & 1, av, bv);
            __syncthreads();
        }
    }

#pragma unroll
    for (int mt = 0; mt < 4; mt++) {
#pragma unroll
        for (int nt = 0; nt < 4; nt++) {
            int col = n0 + wn * 32 + nt * 8 + 2 * tig;
            float b0v = __ldg(bias + col), b1v = __ldg(bias + col + 1);
            int r0 = m0 + wm * 64 + mt * 16 + g;
            int p0 = r0 / 50, t0 = r0 - p0 * 50;
            float2 o0 = make_float2(acc[mt][nt][0] + b0v, acc[mt][nt][1] + b1v);
            *(float2*)(out + ((size_t)t0 * BN + p0) * 512 + col) = o0;
            int r1 = r0 + 8;
            int p1 = r1 / 50, t1 = r1 - p1 * 50;
            float2 o1 = make_float2(acc[mt][nt][2] + b0v, acc[mt][nt][3] + b1v);
            *(float2*)(out + ((size_t)t1 * BN + p1) * 512 + col) = o1;
        }
    }
}

// ============================================================
// Sentence LSTM: PERSISTENT tensor-core recurrence.
// (identical to R10 except barrier indices are line-padded)
// ============================================================
#define S5_WST   132
#define S5_HST   36
#define S5_WSZ   (128 * S5_WST)
#define S5_HBUF  (2 * 128 * S5_HST)
#define S5_SMEM  ((2 * S5_WSZ + 2 * S5_HBUF) * 4)

__global__ void __launch_bounds__(256, 1) lstm_sent5(
    const float* __restrict__ W0, const float* __restrict__ W1)
{
    extern __shared__ __align__(16) float s5[];
    float* sWh = s5;
    float* sWl = s5 + S5_WSZ;
    float* sH  = s5 + 2 * S5_WSZ;
    float* gsm = sH;

    int bid = blockIdx.x;
    int dir = bid >> 6;
    int rem = bid & 63;
    int pch = rem >> 2;
    int jch = rem & 3;
    int p0 = pch * 128;
    int j0 = jch * 32;
    int barIdx = (pch * 2 + dir) * 32;     // one counter per 128B line

    const float* W = dir ? W1 : W0;
    const float* xp = dir ? g_xp1 : g_xp0;
    float* cD = g_cst + (size_t)dir * BN * 128;
    float* hsD = g_hsum + (size_t)dir * BN * 128;

    int tid = threadIdx.x;
    int lane = tid & 31, warp = tid >> 5;
    int g = lane >> 2, tig = lane & 3;
    int wm = warp & 1, wn = warp >> 1;

    {
        int row = tid >> 1;
        int gg = row >> 5, jr = row & 31;
        int half = tid & 1;
        const float* wrow = W + (size_t)(gg * 128 + j0 + jr) * 128 + half * 64;
        int so = row * S5_WST + half * 64;
#pragma unroll
        for (int q = 0; q < 16; q++) {
            float4 v = *(const float4*)(wrow + q * 4);
            float4 h4, l4;
            h4.x = tf32_rna(v.x); l4.x = tf32_rna(v.x - h4.x);
            h4.y = tf32_rna(v.y); l4.y = tf32_rna(v.y - h4.y);
            h4.z = tf32_rna(v.z); l4.z = tf32_rna(v.z - h4.z);
            h4.w = tf32_rna(v.w); l4.w = tf32_rna(v.w - h4.w);
            *(float4*)&sWh[so + q * 4] = h4;
            *(float4*)&sWl[so + q * 4] = l4;
        }
    }
    __syncthreads();

    int srow = tid >> 1;
    int shalf = tid & 1;

    for (int s = 0; s < TSEQ; s++) {
        int t = dir ? (TSEQ - 1 - s) : s;

        if (s > 0) {
            const float* hIn = g_hbuf[s & 1] + (size_t)dir * BN * 128;
            const float* aRow = hIn + (size_t)(p0 + srow) * 128 + shalf * 16;
            int hso = srow * S5_HST + shalf * 16;

            float acc[4][4][4];
#pragma unroll
            for (int i = 0; i < 4; i++)
#pragma unroll
                for (int j = 0; j < 4; j++)
#pragma unroll
                    for (int c = 0; c < 4; c++) acc[i][j][c] = 0.0f;

            {
                float* dh = sH + 0 * S5_HBUF;
                float* dl = dh + 128 * S5_HST;
#pragma unroll
                for (int q = 0; q < 4; q++) {
                    float4 v = *(const float4*)(aRow + q * 4);
                    float4 h4, l4;
                    h4.x = tf32_rna(v.x); l4.x = tf32_rna(v.x - h4.x);
                    h4.y = tf32_rna(v.y); l4.y = tf32_rna(v.y - h4.y);
                    h4.z = tf32_rna(v.z); l4.z = tf32_rna(v.z - h4.z);
                    h4.w = tf32_rna(v.w); l4.w = tf32_rna(v.w - h4.w);
                    *(float4*)&dh[hso + q * 4] = h4;
                    *(float4*)&dl[hso + q * 4] = l4;
                }
            }
            __syncthreads();

#pragma unroll
            for (int kc = 0; kc < 4; kc++) {
                int cur = kc & 1;
                float4 pre[4];
                if (kc < 3) {
#pragma unroll
                    for (int q = 0; q < 4; q++)
                        pre[q] = *(const float4*)(aRow + (kc + 1) * 32 + q * 4);
                }
                const float* bh_base = sWh;
                const float* bl_base = sWl;
                const float* ah_base = sH + cur * S5_HBUF;
                const float* al_base = ah_base + 128 * S5_HST;
#pragma unroll
                for (int kt = 0; kt < 4; kt++) {
                    int kbW = kc * 32 + kt * 8;
                    int kbH = kt * 8;
                    u32 bh[4][2], bl[4][2];
#pragma unroll
                    for (int nt = 0; nt < 4; nt++) {
                        int br = (wn * 32 + nt * 8 + g) * S5_WST + kbW;
                        bh[nt][0] = __float_as_uint(bh_base[br + tig]);
                        bh[nt][1] = __float_as_uint(bh_base[br + tig + 4]);
                        bl[nt][0] = __float_as_uint(bl_base[br + tig]);
                        bl[nt][1] = __float_as_uint(bl_base[br + tig + 4]);
                    }
#pragma unroll
                    for (int mt = 0; mt < 4; mt++) {
                        int ar0 = (wm * 64 + mt * 16 + g) * S5_HST + kbH;
                        int ar1 = ar0 + 8 * S5_HST;
                        u32 ah[4], al[4];
                        ah[0] = __float_as_uint(ah_base[ar0 + tig]);
                        ah[1] = __float_as_uint(ah_base[ar1 + tig]);
                        ah[2] = __float_as_uint(ah_base[ar0 + tig + 4]);
                        ah[3] = __float_as_uint(ah_base[ar1 + tig + 4]);
                        al[0] = __float_as_uint(al_base[ar0 + tig]);
                        al[1] = __float_as_uint(al_base[ar1 + tig]);
                        al[2] = __float_as_uint(al_base[ar0 + tig + 4]);
                        al[3] = __float_as_uint(al_base[ar1 + tig + 4]);
#pragma unroll
                        for (int nt = 0; nt < 4; nt++) {
                            mma_tf32(acc[mt][nt], ah, bh[nt]);
                            mma_tf32(acc[mt][nt], al, bh[nt]);
                            mma_tf32(acc[mt][nt], ah, bl[nt]);
                        }
                    }
                }
                if (kc < 3) {
                    float* dh = sH + (1 - cur) * S5_HBUF;
                    float* dl = dh + 128 * S5_HST;
#pragma unroll
                    for (int q = 0; q < 4; q++) {
                        float4 v = pre[q];
                        float4 h4, l4;
                        h4.x = tf32_rna(v.x); l4.x = tf32_rna(v.x - h4.x);
                        h4.y = tf32_rna(v.y); l4.y = tf32_rna(v.y - h4.y);
                        h4.z = tf32_rna(v.z); l4.z = tf32_rna(v.z - h4.z);
                        h4.w = tf32_rna(v.w); l4.w = tf32_rna(v.w - h4.w);
                        *(float4*)&dh[hso + q * 4] = h4;
                        *(float4*)&dl[hso + q * 4] = l4;
                    }
                }
                __syncthreads();
            }

#pragma unroll
            for (int mt = 0; mt < 4; mt++) {
                int r0 = wm * 64 + mt * 16 + g;
#pragma unroll
                for (int nt = 0; nt < 4; nt++) {
                    int col = wn * 32 + nt * 8 + 2 * tig;
                    *(float2*)&gsm[r0 * 132 + col] =
                        make_float2(acc[mt][nt][0], acc[mt][nt][1]);
                    *(float2*)&gsm[(r0 + 8) * 132 + col] =
                        make_float2(acc[mt][nt][2], acc[mt][nt][3]);
                }
            }
            __syncthreads();
        }

        float* hOut = g_hbuf[(s + 1) & 1] + (size_t)dir * BN * 128;
        size_t xbase = (size_t)t * BN * 512;
#pragma unroll
        for (int i = 0; i < 16; i++) {
            int pj = tid + i * 256;
            int pp = pj >> 5, jj = pj & 31;
            int p = p0 + pp;
            int j = j0 + jj;
            const float* xr = xp + xbase + (size_t)p * 512 + j;
            float gi = xr[0], gf = xr[128], gg2 = xr[256], go = xr[384];
            if (s > 0) {
                gi  += gsm[pp * 132 + jj];
                gf  += gsm[pp * 132 + 32 + jj];
                gg2 += gsm[pp * 132 + 64 + jj];
                go  += gsm[pp * 132 + 96 + jj];
            }
            size_t hidx = (size_t)p * 128 + j;
            float cold = (s == 0) ? 0.0f : cD[hidx];
            float cn = sigf(gf) * cold + sigf(gi) * tanhfast(gg2);
            float hn = sigf(go) * tanhfast(cn);
            if (s == TSEQ - 1) {
                float hs = hsD[hidx] + hn;
                g_sentpres[(size_t)p * 256 + dir * 128 + j] =
                    tanhfast(hs * (1.0f / 50.0f));
            } else {
                cD[hidx] = cn;
                hOut[hidx] = hn;
                hsD[hidx] = (s == 0) ? hn : (hsD[hidx] + hn);
            }
        }

        if (s < TSEQ - 1) {
            __syncthreads();
            if (tid == 0) {
                __threadfence();
                atomicAdd(&g_sbar[barIdx], 1);
                int target = 4 * (s + 1);
                while (*(volatile int*)&g_sbar[barIdx] < target) { }
                __threadfence();
            }
            __syncthreads();
        }
    }

    __syncthreads();
    if (tid == 0) {
        int old = atomicAdd(&g_sdone[barIdx], 1);
        if (old == 3) {
            g_sbar[barIdx] = 0;
            __threadfence();
            g_sdone[barIdx] = 0;
        }
    }
}

// ============================================================
// Dual-half GEMM with f32x2 (modes 1-4, unchanged)
// ============================================================
template <int MODE>
__global__ void __launch_bounds__(256) gemm_dual(
    const float* __restrict__ Aparam, int M, int K, int NB,
    const float* __restrict__ B0, const float* __restrict__ B1,
    const float* __restrict__ bias0, const float* __restrict__ bias1,
    float* __restrict__ outParam)
{
    __shared__ __align__(16) u64 As2[8][128];
    __shared__ __align__(16) float Bs[8][128];

    const float* A;
    if (MODE == 1 || MODE == 2) A = g_sentpres;
    else if (MODE == 3) A = g_tag_out;
    else A = g_agg;
    (void)Aparam;

    int hsel = (blockIdx.y * 128) / NB;
    int g0 = blockIdx.y * 128 - hsel * NB;
    int m0 = blockIdx.x * 128;

    const float* B = hsel ? B1 : B0;
    const float* bias = hsel ? bias1 : bias0;

    float* out;
    if (MODE == 1) out = hsel ? g_txp1 : g_txp0;
    else if (MODE == 2 || MODE == 3) out = hsel ? g_k : g_q;
    else out = outParam;

    int tid = threadIdx.x;
    int tx = tid & 15;
    int ty = tid >> 4;
    int lr = tid >> 1;
    int lc4 = tid & 1;

    u64 acc2[8][4];
#pragma unroll
    for (int i = 0; i < 8; i++)
#pragma unroll
        for (int j = 0; j < 4; j++) acc2[i][j] = 0ULL;

    int KT = K / 8;
    const float* aPtr = A + (size_t)(m0 + lr) * K + lc4 * 4;
    const float* bPtr = B + (size_t)(g0 + lr) * K + lc4 * 4;
    float4 av = *(const float4*)(aPtr);
    float4 bv = *(const float4*)(bPtr);

    for (int kt = 0; kt < KT; kt++) {
        As2[lc4 * 4 + 0][lr] = pk2(av.x, av.x);
        As2[lc4 * 4 + 1][lr] = pk2(av.y, av.y);
        As2[lc4 * 4 + 2][lr] = pk2(av.z, av.z);
        As2[lc4 * 4 + 3][lr] = pk2(av.w, av.w);
        Bs[lc4 * 4 + 0][lr] = bv.x; Bs[lc4 * 4 + 1][lr] = bv.y;
        Bs[lc4 * 4 + 2][lr] = bv.z; Bs[lc4 * 4 + 3][lr] = bv.w;
        __syncthreads();
        if (kt + 1 < KT) {
            av = *(const float4*)(aPtr + (kt + 1) * 8);
            bv = *(const float4*)(bPtr + (kt + 1) * 8);
        }
#pragma unroll
        for (int kk = 0; kk < 8; kk++) {
            u64 b2[4];
#pragma unroll
            for (int jq = 0; jq < 4; jq++)
                b2[jq] = *(const u64*)&Bs[kk][2 * (tx + 16 * jq)];
            u64 a2[8];
#pragma unroll
            for (int i = 0; i < 8; i++) a2[i] = As2[kk][ty * 8 + i];
#pragma unroll
            for (int i = 0; i < 8; i++)
#pragma unroll
                for (int jq = 0; jq < 4; jq++)
                    fma2(acc2[i][jq], a2[i], b2[jq]);
        }
        __syncthreads();
    }

#pragma unroll
    for (int i = 0; i < 8; i++) {
        int m = m0 + ty * 8 + i;
        size_t rowbase;
        if (MODE == 1) {
            int b = m >> 6; int n = m & 63;
            rowbase = ((size_t)n * BB + b) * 512;
        } else {
            rowbase = (size_t)m * 256;
        }
#pragma unroll
        for (int jq = 0; jq < 4; jq++) {
            int g = g0 + 2 * (tx + 16 * jq);
            float lo, hi;
            up2(acc2[i][jq], lo, hi);
            float2 bb = *(const float2*)(bias + g);
            float2 o;
            o.x = lo + bb.x;
            o.y = hi + bb.y;
            if (MODE == 4) { o.x = fmaxf(o.x, 0.f); o.y = fmaxf(o.y, 0.f); }
            *(float2*)(out + rowbase + g) = o;
        }
    }
}

// ============================================================
// Persistent tag BiLSTM v3: TENSOR CORES (3xTF32).
// (identical to R10 except barrier indices are line-padded)
// ============================================================
#define TG2_WST  132
#define TG2_HST  132
#define TG2_WSZ  (64 * TG2_WST)
#define TG2_HSZ  (32 * TG2_HST)
#define TG2_SMEM ((2 * TG2_WSZ + 2 * TG2_HSZ + 32 * 68) * 4)

__global__ void __launch_bounds__(256) tag_persistent_tc(
    const float* __restrict__ W0, const float* __restrict__ W1)
{
    extern __shared__ __align__(16) float tg2[];
    float* sWh = tg2;
    float* sWl = tg2 + TG2_WSZ;
    float* sHh = tg2 + 2 * TG2_WSZ;
    float* sHl = sHh + TG2_HSZ;
    float* gsm = sHl + TG2_HSZ;            // [32][68]

    int dir = blockIdx.x >> 3;
    int jc = blockIdx.x & 7;
    int j0 = jc * 16;
    const float* W = dir ? W1 : W0;
    const float* xp = dir ? g_txp1 : g_txp0;

    int tid = threadIdx.x;
    int lane = tid & 31, warp = tid >> 5;
    int g = lane >> 2, tig = lane & 3;

    // ---- stage W hi/lo ONCE ----
    {
        int row = tid >> 2;               // 0..63
        int gg = row >> 4, jr = row & 15;
        int kq = (tid & 3) * 32;
        const float* wrow = W + (size_t)(gg * 128 + j0 + jr) * 128 + kq;
        int so = row * TG2_WST + kq;
#pragma unroll
        for (int q = 0; q < 8; q++) {
            float4 v = *(const float4*)(wrow + q * 4);
            float4 h4, l4;
            h4.x = tf32_rna(v.x); l4.x = tf32_rna(v.x - h4.x);
            h4.y = tf32_rna(v.y); l4.y = tf32_rna(v.y - h4.y);
            h4.z = tf32_rna(v.z); l4.z = tf32_rna(v.z - h4.z);
            h4.w = tf32_rna(v.w); l4.w = tf32_rna(v.w - h4.w);
            *(float4*)&sWh[so + q * 4] = h4;
            *(float4*)&sWl[so + q * 4] = l4;
        }
    }
    __syncthreads();

    float creg[2] = {0.f, 0.f};
    int* bar = &g_tbar2[dir * 32];

    for (int s = 0; s < NSEQ; s++) {
        int t = dir ? (NSEQ - 1 - s) : s;

        if (s > 0) {
            const float* hIn = g_thbuf[s & 1] + (size_t)dir * BB * 128;
            {
                int row = tid >> 3;        // 0..31
                int kq = (tid & 7) * 16;
                const float* hrow = hIn + (size_t)row * 128 + kq;
                int so = row * TG2_HST + kq;
#pragma unroll
                for (int q = 0; q < 4; q++) {
                    float4 v = *(const float4*)(hrow + q * 4);
                    float4 h4, l4;
                    h4.x = tf32_rna(v.x); l4.x = tf32_rna(v.x - h4.x);
                    h4.y = tf32_rna(v.y); l4.y = tf32_rna(v.y - h4.y);
                    h4.z = tf32_rna(v.z); l4.z = tf32_rna(v.z - h4.z);
                    h4.w = tf32_rna(v.w); l4.w = tf32_rna(v.w - h4.w);
                    *(float4*)&sHh[so + q * 4] = h4;
                    *(float4*)&sHl[so + q * 4] = l4;
                }
            }
            __syncthreads();

            float acc[2][4];
#pragma unroll
            for (int mt = 0; mt < 2; mt++)
#pragma unroll
                for (int c = 0; c < 4; c++) acc[mt][c] = 0.0f;

#pragma unroll
            for (int kt = 0; kt < 16; kt++) {
                int kb = kt * 8;
                int br = (warp * 8 + g) * TG2_WST + kb;
                u32 bh[2], bl[2];
                bh[0] = __float_as_uint(sWh[br + tig]);
                bh[1] = __float_as_uint(sWh[br + tig + 4]);
                bl[0] = __float_as_uint(sWl[br + tig]);
                bl[1] = __float_as_uint(sWl[br + tig + 4]);
#pragma unroll
                for (int mt = 0; mt < 2; mt++) {
                    int ar0 = (mt * 16 + g) * TG2_HST + kb;
                    int ar1 = ar0 + 8 * TG2_HST;
                    u32 ah[4], al[4];
                    ah[0] = __float_as_uint(sHh[ar0 + tig]);
                    ah[1] = __float_as_uint(sHh[ar1 + tig]);
                    ah[2] = __float_as_uint(sHh[ar0 + tig + 4]);
                    ah[3] = __float_as_uint(sHh[ar1 + tig + 4]);
                    al[0] = __float_as_uint(sHl[ar0 + tig]);
                    al[1] = __float_as_uint(sHl[ar1 + tig]);
                    al[2] = __float_as_uint(sHl[ar0 + tig + 4]);
                    al[3] = __float_as_uint(sHl[ar1 + tig + 4]);
                    mma_tf32(acc[mt], ah, bh);
                    mma_tf32(acc[mt], al, bh);
                    mma_tf32(acc[mt], ah, bl);
                }
            }

#pragma unroll
            for (int mt = 0; mt < 2; mt++) {
                int r0 = mt * 16 + g;
                int col = warp * 8 + 2 * tig;
                *(float2*)&gsm[r0 * 68 + col] = make_float2(acc[mt][0], acc[mt][1]);
                *(float2*)&gsm[(r0 + 8) * 68 + col] = make_float2(acc[mt][2], acc[mt][3]);
            }
            __syncthreads();
        }

        float* hOut = g_thbuf[(s + 1) & 1] + (size_t)dir * BB * 128;
#pragma unroll
        for (int u = 0; u < 2; u++) {
            int idx = tid + u * 256;
            int b = idx >> 4, jj = idx & 15;
            const float* xr = xp + ((size_t)t * BB + b) * 512 + j0 + jj;
            float gi = xr[0], gf = xr[128], gg2 = xr[256], go = xr[384];
            if (s > 0) {
                gi  += gsm[b * 68 + jj];
                gf  += gsm[b * 68 + 16 + jj];
                gg2 += gsm[b * 68 + 32 + jj];
                go  += gsm[b * 68 + 48 + jj];
            }
            float cn = sigf(gf) * creg[u] + sigf(gi) * tanhfast(gg2);
            float hn = sigf(go) * tanhfast(cn);
            creg[u] = cn;
            hOut[(size_t)b * 128 + j0 + jj] = hn;
            g_tag_out[((size_t)b * NSEQ + t) * 256 + dir * 128 + j0 + jj] = tanhfast(hn);
        }

        if (s < NSEQ - 1) {
            __syncthreads();
            if (tid == 0) {
                __threadfence();
                atomicAdd(bar, 1);
                int target = 8 * (s + 1);
                while (*(volatile int*)bar < target) { }
                __threadfence();
            }
            __syncthreads();
        }
    }

    __syncthreads();
    if (tid == 0) {
        int old = atomicAdd(&g_tdone2[dir * 32], 1);
        if (old == 7) {
            g_tbar2[dir * 32] = 0;
            __threadfence();
            g_tdone2[dir * 32] = 0;
        }
    }
}

// ---------------- SPP ----------------
__global__ void __launch_bounds__(256) spp_kernel(int which) {
    int b = blockIdx.x;
    int tid = threadIdx.x;
    __shared__ float qs[64][33];
    __shared__ float ks[64][33];
    __shared__ float segs[64][8];

    float acc[16];
#pragma unroll
    for (int i = 0; i < 16; i++) acc[i] = 0.0f;
    int n = tid >> 2;
    int mBase = (tid & 3) * 16;

    for (int d0 = 0; d0 < 256; d0 += 32) {
        __syncthreads();
        for (int idx = tid; idx < 64 * 32; idx += 256) {
            int r = idx >> 5, cc = idx & 31;
            size_t gi = ((size_t)(b * 64 + r)) * 256 + d0 + cc;
            qs[r][cc] = g_q[gi];
            ks[r][cc] = g_k[gi];
        }
        __syncthreads();
#pragma unroll 4
        for (int dd = 0; dd < 32; dd++) {
            float qv = qs[n][dd];
#pragma unroll
            for (int mm = 0; mm < 16; mm++)
                acc[mm] += qv * ks[mBase + mm][dd];
        }
    }
    float s8a = -3.4e38f, s8b = -3.4e38f;
#pragma unroll
    for (int mm = 0; mm < 8; mm++)  s8a = fmaxf(s8a, acc[mm]);
#pragma unroll
    for (int mm = 8; mm < 16; mm++) s8b = fmaxf(s8b, acc[mm]);
    segs[n][(tid & 3) * 2 + 0] = s8a * 0.0625f;
    segs[n][(tid & 3) * 2 + 1] = s8b * 0.0625f;
    __syncthreads();

    if (tid < 64) {
        float e[8];
#pragma unroll
        for (int i = 0; i < 8; i++) e[i] = segs[tid][i];
        float q4[4], h2[2];
#pragma unroll
        for (int i = 0; i < 4; i++) q4[i] = fmaxf(e[2 * i], e[2 * i + 1]);
        h2[0] = fmaxf(q4[0], q4[1]);
        h2[1] = fmaxf(q4[2], q4[3]);
        float a1 = fmaxf(h2[0], h2[1]);
        float* o = (which ? g_roleFt : g_sentFt) + (size_t)(b * 64 + tid) * 15;
        o[0] = a1;
        o[1] = h2[0]; o[2] = h2[1];
#pragma unroll
        for (int i = 0; i < 4; i++) o[3 + i] = q4[i];
#pragma unroll
        for (int i = 0; i < 8; i++) o[7 + i] = e[i];
    }
}

// ---------------- GCN pre ----------------
__global__ void __launch_bounds__(256) gcn_pre() {
    int b = blockIdx.x;
    int tid = threadIdx.x;
    __shared__ float cosm[64][65];
    __shared__ float xs[64][33];
    __shared__ float inv[64];

    if (tid < 64) {
        const float* xr = g_tag_out + (size_t)(b * 64 + tid) * 256;
        float s = 0.0f;
        for (int d = 0; d < 256; d++) { float v = xr[d]; s += v * v; }
        inv[tid] = 1.0f / (sqrtf(s) + 1e-8f);
    }

    float acc[16];
#pragma unroll
    for (int i = 0; i < 16; i++) acc[i] = 0.0f;
    int n = tid >> 2;
    int mBase = (tid & 3) * 16;

    for (int d0 = 0; d0 < 256; d0 += 32) {
        __syncthreads();
        for (int idx = tid; idx < 64 * 32; idx += 256) {
            int r = idx >> 5, cc = idx & 31;
            xs[r][cc] = g_tag_out[((size_t)(b * 64 + r)) * 256 + d0 + cc];
        }
        __syncthreads();
#pragma unroll 4
        for (int dd = 0; dd < 32; dd++) {
            float xv = xs[n][dd];
#pragma unroll
            for (int mm = 0; mm < 16; mm++)
                acc[mm] += xv * xs[mBase + mm][dd];
        }
    }
#pragma unroll
    for (int mm = 0; mm < 16; mm++)
        cosm[n][mBase + mm] = acc[mm] * inv[n] * inv[mBase + mm];

    int ddBase = (tid & 3) * 8;
    for (int d0 = 0; d0 < 256; d0 += 32) {
        __syncthreads();
        for (int idx = tid; idx < 64 * 32; idx += 256) {
            int r = idx >> 5, cc = idx & 31;
            xs[r][cc] = g_tag_out[((size_t)(b * 64 + r)) * 256 + d0 + cc];
        }
        __syncthreads();
        float r8[8];
#pragma unroll
        for (int i = 0; i < 8; i++) r8[i] = 0.0f;
        for (int m = 0; m < 64; m++) {
            float cv = cosm[n][m];
#pragma unroll
            for (int i = 0; i < 8; i++) r8[i] += cv * xs[m][ddBase + i];
        }
#pragma unroll
        for (int i = 0; i < 8; i++) {
            float v = (r8[i] + 2.0f * xs[n][ddBase + i]) * (1.0f / 66.0f);
            g_agg[(size_t)(b * 64 + n) * 256 + d0 + ddBase + i] = v;
        }
    }
}

// ---------------- classifier + log_softmax ----------------
__global__ void __launch_bounds__(256) cls_kernel(
    const float* __restrict__ W, const float* __restrict__ bias,
    float* __restrict__ out)
{
    __shared__ float Wsh[8][288];
    __shared__ float bsh[8];
    __shared__ float ftile[256][33];

    int tid = threadIdx.x;
    for (int i = tid; i < 8 * 286; i += 256) Wsh[i / 286][i % 286] = W[i];
    if (tid < 8) bsh[tid] = bias[tid];
    __syncthreads();

    int p0 = blockIdx.x * 256;
    int p = p0 + tid;
    float z[8];
#pragma unroll
    for (int c = 0; c < 8; c++) z[c] = bsh[c];

    for (int d0 = 0; d0 < 256; d0 += 32) {
        __syncthreads();
        for (int idx = tid; idx < 256 * 32; idx += 256) {
            int r = idx >> 5, cc = idx & 31;
            ftile[r][cc] = g_tag_out[(size_t)(p0 + r) * 256 + d0 + cc];
        }
        __syncthreads();
#pragma unroll 4
        for (int dd = 0; dd < 32; dd++) {
            float f = ftile[tid][dd];
#pragma unroll
            for (int c = 0; c < 8; c++) z[c] += f * Wsh[c][d0 + dd];
        }
    }
#pragma unroll
    for (int d = 0; d < 15; d++) {
        float f = g_sentFt[(size_t)p * 15 + d];
#pragma unroll
        for (int c = 0; c < 8; c++) z[c] += f * Wsh[c][256 + d];
    }
#pragma unroll
    for (int d = 0; d < 15; d++) {
        float f = g_roleFt[(size_t)p * 15 + d];
#pragma unroll
        for (int c = 0; c < 8; c++) z[c] += f * Wsh[c][271 + d];
    }
    float m = z[0];
#pragma unroll
    for (int c = 1; c < 8; c++) m = fmaxf(m, z[c]);
    float se = 0.0f;
#pragma unroll
    for (int c = 0; c < 8; c++) se += expf(z[c] - m);
    float lse = m + logf(se);
#pragma unroll
    for (int c = 0; c < 8; c++) out[(size_t)p * 8 + c] = z[c] - lse;
}

// ============================================================
extern "C" void kernel_launch(void* const* d_in, const int* in_sizes, int n_in,
                              void* d_out, int out_size)
{
    (void)in_sizes; (void)n_in; (void)out_size;
    const float* documents = (const float*)d_in[0];
    const float* sw_ih_f = (const float*)d_in[1];
    const float* sw_hh_f = (const float*)d_in[2];
    const float* sb_f    = (const float*)d_in[3];
    const float* sw_ih_b = (const float*)d_in[4];
    const float* sw_hh_b = (const float*)d_in[5];
    const float* sb_b    = (const float*)d_in[6];
    const float* sf_Wq   = (const float*)d_in[7];
    const float* sf_bq   = (const float*)d_in[8];
    const float* sf_Wk   = (const float*)d_in[9];
    const float* sf_bk   = (const float*)d_in[10];
    const float* rf_Wq   = (const float*)d_in[11];
    const float* rf_bq   = (const float*)d_in[12];
    const float* rf_Wk   = (const float*)d_in[13];
    const float* rf_bk   = (const float*)d_in[14];
    const float* tw_ih_f = (const float*)d_in[15];
    const float* tw_hh_f = (const float*)d_in[16];
    const float* tb_f    = (const float*)d_in[17];
    const float* tw_ih_b = (const float*)d_in[18];
    const float* tw_hh_b = (const float*)d_in[19];
    const float* tb_b    = (const float*)d_in[20];
    const float* sage_W  = (const float*)d_in[21];
    const float* sage_b  = (const float*)d_in[22];
    const float* cls_W   = (const float*)d_in[23];
    const float* cls_b   = (const float*)d_in[24];
    float* out = (float*)d_out;

    cudaFuncSetAttribute(lstm_sent5, cudaFuncAttributeMaxDynamicSharedMemorySize, S5_SMEM);
    cudaFuncSetAttribute(tag_persistent_tc, cudaFuncAttributeMaxDynamicSharedMemorySize, TG2_SMEM);

    // 1) sentence BiLSTM input projection: tensor cores, 3xTF32
    gemm_inproj_tc<<<dim3(800, 8), 256>>>(documents, sw_ih_f, sw_ih_b, sb_f, sb_b);
    // 2) sentence recurrence: ONE persistent tensor-core kernel
    lstm_sent5<<<128, 256, S5_SMEM>>>(sw_hh_f, sw_hh_b);
    // 3) tag BiLSTM input projection
    gemm_dual<1><<<dim3(16, 8), 256>>>(nullptr, 2048, 256, 512,
                                       tw_ih_f, tw_ih_b, tb_f, tb_b, nullptr);
    // 4) tag recurrence: persistent TENSOR-CORE kernel
    tag_persistent_tc<<<16, 256, TG2_SMEM>>>(tw_hh_f, tw_hh_b);
    // 5) SPP on sentpres -> sentFt
    gemm_dual<2><<<dim3(16, 4), 256>>>(nullptr, 2048, 256, 256,
                                       sf_Wq, sf_Wk, sf_bq, sf_bk, nullptr);
    spp_kernel<<<32, 256>>>(0);
    // 6) SPP on tag_out -> roleFt
    gemm_dual<3><<<dim3(16, 4), 256>>>(nullptr, 2048, 256, 256,
                                       rf_Wq, rf_Wk, rf_bq, rf_bk, nullptr);
    spp_kernel<<<32, 256>>>(1);
    // 7) GCN
    gcn_pre<<<32, 256>>>();
    gemm_dual<4><<<dim3(16, 2), 256>>>(nullptr, 2048, 256, 256,
                                       sage_W, sage_W, sage_b, sage_b, out + 16384);
    // 8) classifier + log_softmax
    cls_kernel<<<8, 256>>>(cls_W, cls_b, out);
}

// round 12
// speedup vs baseline: 1.7598x; 1.1247x over previous
#include <cuda_runtime.h>
#include <math.h>
#include <stdint.h>

typedef unsigned long long u64;
typedef unsigned int u32;

// ---------------- problem constants ----------------
#define BN   2048
#define TSEQ 50
#define NSEQ 64
#define BB   32

// ---------------- device scratch ----------------
__device__ float g_xp0[(size_t)TSEQ * BN * 512];
__device__ float g_xp1[(size_t)TSEQ * BN * 512];
__device__ float g_hbuf[2][2 * BN * 128];
__device__ float g_cst[2 * BN * 128];
__device__ float g_hsum[2 * BN * 128];
__device__ float g_sentpres[(size_t)BN * 256];
__device__ float g_txp0[(size_t)NSEQ * BB * 512];
__device__ float g_txp1[(size_t)NSEQ * BB * 512];
__device__ float g_thbuf[2][2 * BB * 128];
__device__ float g_tag_out[(size_t)BN * 256];
__device__ float g_q[(size_t)BN * 256];
__device__ float g_k[(size_t)BN * 256];
__device__ float g_sentFt[(size_t)BN * 15];
__device__ float g_roleFt[(size_t)BN * 15];
__device__ float g_agg[(size_t)BN * 256];
__device__ int g_tbar2[2 * 32];
__device__ int g_tdone2[2 * 32];
__device__ int g_sbar[32 * 32];
__device__ int g_sdone[32 * 32];

// ---------------- f32x2 helpers ----------------
__device__ __forceinline__ u64 pk2(float lo, float hi) {
    u64 r; asm("mov.b64 %0, {%1, %2};" : "=l"(r) : "f"(lo), "f"(hi)); return r;
}
__device__ __forceinline__ void up2(u64 v, float& lo, float& hi) {
    asm("mov.b64 {%0, %1}, %2;" : "=f"(lo), "=f"(hi) : "l"(v));
}
__device__ __forceinline__ void fma2(u64& d, u64 a, u64 b) {
    asm("fma.rn.f32x2 %0, %1, %2, %0;" : "+l"(d) : "l"(a), "l"(b));
}

// ---------------- tf32 helpers ----------------
__device__ __forceinline__ float tf32_rna(float x) {
    u32 u; asm("cvt.rna.tf32.f32 %0, %1;" : "=r"(u) : "f"(x));
    return __uint_as_float(u);
}
__device__ __forceinline__ void mma_tf32(float* d, const u32* a, const u32* b) {
    asm("mma.sync.aligned.m16n8k8.row.col.f32.tf32.tf32.f32 "
        "{%0,%1,%2,%3},{%4,%5,%6,%7},{%8,%9},{%0,%1,%2,%3};"
        : "+f"(d[0]), "+f"(d[1]), "+f"(d[2]), "+f"(d[3])
        : "r"(a[0]), "r"(a[1]), "r"(a[2]), "r"(a[3]), "r"(b[0]), "r"(b[1]));
}

// ---------------- fast math ----------------
__device__ __forceinline__ float sigf(float x) {
    x = fminf(fmaxf(x, -30.f), 30.f);
    return __fdividef(1.f, 1.f + __expf(-x));
}
__device__ __forceinline__ float tanhfast(float x) {
    x = fminf(fmaxf(x, -15.f), 15.f);
    return __fdividef(2.f, 1.f + __expf(-2.f * x)) - 1.f;
}

// ============================================================
// K1: sentence input projection with tensor cores (3xTF32).
// (unchanged — validated)
// ============================================================
#define K1P 12
__global__ void __launch_bounds__(256) gemm_inproj_tc(
    const float* __restrict__ A,
    const float* __restrict__ B0, const float* __restrict__ B1,
    const float* __restrict__ bias0, const float* __restrict__ bias1)
{
    __shared__ float sAh[2][128 * K1P], sAl[2][128 * K1P];
    __shared__ float sBh[2][128 * K1P], sBl[2][128 * K1P];

    int m0 = blockIdx.x * 128;
    int nb = blockIdx.y;
    int dir = nb >> 2;
    int n0 = (nb & 3) * 128;
    const float* Bw = dir ? B1 : B0;
    const float* bias = dir ? bias1 : bias0;
    float* out = dir ? g_xp1 : g_xp0;

    int tid = threadIdx.x;
    int lane = tid & 31, warp = tid >> 5;
    int g = lane >> 2, tig = lane & 3;
    int wm = warp & 1, wn = warp >> 1;

    int srow = tid >> 1, shalf = tid & 1;
    const float* aP = A + (size_t)(m0 + srow) * 200 + shalf * 4;
    const float* bP = Bw + (size_t)(n0 + srow) * 200 + shalf * 4;

    float acc[4][4][4];
#pragma unroll
    for (int i = 0; i < 4; i++)
#pragma unroll
        for (int j = 0; j < 4; j++)
#pragma unroll
            for (int c = 0; c < 4; c++) acc[i][j][c] = 0.0f;

    float4 av = *(const float4*)aP;
    float4 bv = *(const float4*)bP;

    int soff = srow * K1P + shalf * 4;
#define K1_STAGE(buf, a4, b4) do {                                          \
        float4 _h, _l;                                                      \
        _h.x = tf32_rna(a4.x); _l.x = tf32_rna(a4.x - _h.x);                \
        _h.y = tf32_rna(a4.y); _l.y = tf32_rna(a4.y - _h.y);                \
        _h.z = tf32_rna(a4.z); _l.z = tf32_rna(a4.z - _h.z);                \
        _h.w = tf32_rna(a4.w); _l.w = tf32_rna(a4.w - _h.w);                \
        *(float4*)&sAh[buf][soff] = _h;                                     \
        *(float4*)&sAl[buf][soff] = _l;                                     \
        _h.x = tf32_rna(b4.x); _l.x = tf32_rna(b4.x - _h.x);                \
        _h.y = tf32_rna(b4.y); _l.y = tf32_rna(b4.y - _h.y);                \
        _h.z = tf32_rna(b4.z); _l.z = tf32_rna(b4.z - _h.z);                \
        _h.w = tf32_rna(b4.w); _l.w = tf32_rna(b4.w - _h.w);                \
        *(float4*)&sBh[buf][soff] = _h;                                     \
        *(float4*)&sBl[buf][soff] = _l;                                     \
    } while (0)

    K1_STAGE(0, av, bv);
    __syncthreads();

    for (int kt = 0; kt < 25; kt++) {
        int cur = kt & 1;
        if (kt < 24) {
            av = *(const float4*)(aP + (kt + 1) * 8);
            bv = *(const float4*)(bP + (kt + 1) * 8);
        }
        u32 bh[4][2], bl[4][2];
#pragma unroll
        for (int nt = 0; nt < 4; nt++) {
            int br = (wn * 32 + nt * 8 + g) * K1P;
            bh[nt][0] = __float_as_uint(sBh[cur][br + tig]);
            bh[nt][1] = __float_as_uint(sBh[cur][br + tig + 4]);
            bl[nt][0] = __float_as_uint(sBl[cur][br + tig]);
            bl[nt][1] = __float_as_uint(sBl[cur][br + tig + 4]);
        }
#pragma unroll
        for (int mt = 0; mt < 4; mt++) {
            int ar0 = (wm * 64 + mt * 16 + g) * K1P;
            int ar1 = ar0 + 8 * K1P;
            u32 ah[4], al[4];
            ah[0] = __float_as_uint(sAh[cur][ar0 + tig]);
            ah[1] = __float_as_uint(sAh[cur][ar1 + tig]);
            ah[2] = __float_as_uint(sAh[cur][ar0 + tig + 4]);
            ah[3] = __float_as_uint(sAh[cur][ar1 + tig + 4]);
            al[0] = __float_as_uint(sAl[cur][ar0 + tig]);
            al[1] = __float_as_uint(sAl[cur][ar1 + tig]);
            al[2] = __float_as_uint(sAl[cur][ar0 + tig + 4]);
            al[3] = __float_as_uint(sAl[cur][ar1 + tig + 4]);
#pragma unroll
            for (int nt = 0; nt < 4; nt++) {
                mma_tf32(acc[mt][nt], ah, bh[nt]);
                mma_tf32(acc[mt][nt], al, bh[nt]);
                mma_tf32(acc[mt][nt], ah, bl[nt]);
            }
        }
        __syncthreads();
        if (kt < 24) {
            K1_STAGE((kt + 1) & 1, av, bv);
            __syncthreads();
        }
    }

#pragma unroll
    for (int mt = 0; mt < 4; mt++) {
#pragma unroll
        for (int nt = 0; nt < 4; nt++) {
            int col = n0 + wn * 32 + nt * 8 + 2 * tig;
            float b0v = __ldg(bias + col), b1v = __ldg(bias + col + 1);
            int r0 = m0 + wm * 64 + mt * 16 + g;
            int p0 = r0 / 50, t0 = r0 - p0 * 50;
            float2 o0 = make_float2(acc[mt][nt][0] + b0v, acc[mt][nt][1] + b1v);
            *(float2*)(out + ((size_t)t0 * BN + p0) * 512 + col) = o0;
            int r1 = r0 + 8;
            int p1 = r1 / 50, t1 = r1 - p1 * 50;
            float2 o1 = make_float2(acc[mt][nt][2] + b0v, acc[mt][nt][3] + b1v);
            *(float2*)(out + ((size_t)t1 * BN + p1) * 512 + col) = o1;
        }
    }
}

// ============================================================
// Sentence LSTM: PERSISTENT tensor-core recurrence, 512 THREADS.
// 128 blocks (16 pch x 4 jch x 2 dir), 16 warps (4m x 4n),
// warp tile m32 x n32 — 4 warps/SMSP for latency hiding.
// smem unchanged: W 2*128*132 + h 2*2*128*36 floats = 208896 B.
// ============================================================
#define S5_WST   132
#define S5_HST   36
#define S5_WSZ   (128 * S5_WST)
#define S5_HBUF  (2 * 128 * S5_HST)
#define S5_SMEM  ((2 * S5_WSZ + 2 * S5_HBUF) * 4)

__global__ void __launch_bounds__(512, 1) lstm_sent5(
    const float* __restrict__ W0, const float* __restrict__ W1)
{
    extern __shared__ __align__(16) float s5[];
    float* sWh = s5;
    float* sWl = s5 + S5_WSZ;
    float* sH  = s5 + 2 * S5_WSZ;
    float* gsm = sH;

    int bid = blockIdx.x;
    int dir = bid >> 6;
    int rem = bid & 63;
    int pch = rem >> 2;
    int jch = rem & 3;
    int p0 = pch * 128;
    int j0 = jch * 32;
    int barIdx = (pch * 2 + dir) * 32;

    const float* W = dir ? W1 : W0;
    const float* xp = dir ? g_xp1 : g_xp0;
    float* cD = g_cst + (size_t)dir * BN * 128;
    float* hsD = g_hsum + (size_t)dir * BN * 128;

    int tid = threadIdx.x;
    int lane = tid & 31, warp = tid >> 5;
    int g = lane >> 2, tig = lane & 3;
    int wm = warp & 3, wn = warp >> 2;    // 4m x 4n warps

    // ---- stage W hi/lo ONCE: 128 rows x 128 k, 512 threads ----
    {
        int row = tid >> 2;                 // 0..127 = gate*32 + jr
        int gg = row >> 5, jr = row & 31;
        int kq = (tid & 3) * 32;
        const float* wrow = W + (size_t)(gg * 128 + j0 + jr) * 128 + kq;
        int so = row * S5_WST + kq;
#pragma unroll
        for (int q = 0; q < 8; q++) {
            float4 v = *(const float4*)(wrow + q * 4);
            float4 h4, l4;
            h4.x = tf32_rna(v.x); l4.x = tf32_rna(v.x - h4.x);
            h4.y = tf32_rna(v.y); l4.y = tf32_rna(v.y - h4.y);
            h4.z = tf32_rna(v.z); l4.z = tf32_rna(v.z - h4.z);
            h4.w = tf32_rna(v.w); l4.w = tf32_rna(v.w - h4.w);
            *(float4*)&sWh[so + q * 4] = h4;
            *(float4*)&sWl[so + q * 4] = l4;
        }
    }
    __syncthreads();

    int srow = tid >> 2;                    // h stage row 0..127
    int sq8 = (tid & 3) * 8;                // 8-k slice within 32-k chunk

    for (int s = 0; s < TSEQ; s++) {
        int t = dir ? (TSEQ - 1 - s) : s;

        if (s > 0) {
            const float* hIn = g_hbuf[s & 1] + (size_t)dir * BN * 128;
            const float* aRow = hIn + (size_t)(p0 + srow) * 128 + sq8;
            int hso = srow * S5_HST + sq8;

            float acc[2][4][4];
#pragma unroll
            for (int i = 0; i < 2; i++)
#pragma unroll
                for (int j = 0; j < 4; j++)
#pragma unroll
                    for (int c = 0; c < 4; c++) acc[i][j][c] = 0.0f;

            // stage chunk 0 into buf 0
            {
                float* dh = sH + 0 * S5_HBUF;
                float* dl = dh + 128 * S5_HST;
#pragma unroll
                for (int q = 0; q < 2; q++) {
                    float4 v = *(const float4*)(aRow + q * 4);
                    float4 h4, l4;
                    h4.x = tf32_rna(v.x); l4.x = tf32_rna(v.x - h4.x);
                    h4.y = tf32_rna(v.y); l4.y = tf32_rna(v.y - h4.y);
                    h4.z = tf32_rna(v.z); l4.z = tf32_rna(v.z - h4.z);
                    h4.w = tf32_rna(v.w); l4.w = tf32_rna(v.w - h4.w);
                    *(float4*)&dh[hso + q * 4] = h4;
                    *(float4*)&dl[hso + q * 4] = l4;
                }
            }
            __syncthreads();

#pragma unroll
            for (int kc = 0; kc < 4; kc++) {
                int cur = kc & 1;
                float4 pre[2];
                if (kc < 3) {
#pragma unroll
                    for (int q = 0; q < 2; q++)
                        pre[q] = *(const float4*)(aRow + (kc + 1) * 32 + q * 4);
                }
                const float* bh_base = sWh;
                const float* bl_base = sWl;
                const float* ah_base = sH + cur * S5_HBUF;
                const float* al_base = ah_base + 128 * S5_HST;
#pragma unroll
                for (int kt = 0; kt < 4; kt++) {
                    int kbW = kc * 32 + kt * 8;
                    int kbH = kt * 8;
                    u32 bh[4][2], bl[4][2];
#pragma unroll
                    for (int nt = 0; nt < 4; nt++) {
                        int br = (wn * 32 + nt * 8 + g) * S5_WST + kbW;
                        bh[nt][0] = __float_as_uint(bh_base[br + tig]);
                        bh[nt][1] = __float_as_uint(bh_base[br + tig + 4]);
                        bl[nt][0] = __float_as_uint(bl_base[br + tig]);
                        bl[nt][1] = __float_as_uint(bl_base[br + tig + 4]);
                    }
#pragma unroll
                    for (int mt = 0; mt < 2; mt++) {
                        int ar0 = (wm * 32 + mt * 16 + g) * S5_HST + kbH;
                        int ar1 = ar0 + 8 * S5_HST;
                        u32 ah[4], al[4];
                        ah[0] = __float_as_uint(ah_base[ar0 + tig]);
                        ah[1] = __float_as_uint(ah_base[ar1 + tig]);
                        ah[2] = __float_as_uint(ah_base[ar0 + tig + 4]);
                        ah[3] = __float_as_uint(ah_base[ar1 + tig + 4]);
                        al[0] = __float_as_uint(al_base[ar0 + tig]);
                        al[1] = __float_as_uint(al_base[ar1 + tig]);
                        al[2] = __float_as_uint(al_base[ar0 + tig + 4]);
                        al[3] = __float_as_uint(al_base[ar1 + tig + 4]);
#pragma unroll
                        for (int nt = 0; nt < 4; nt++) {
                            mma_tf32(acc[mt][nt], ah, bh[nt]);
                            mma_tf32(acc[mt][nt], al, bh[nt]);
                            mma_tf32(acc[mt][nt], ah, bl[nt]);
                        }
                    }
                }
                if (kc < 3) {
                    float* dh = sH + (1 - cur) * S5_HBUF;
                    float* dl = dh + 128 * S5_HST;
#pragma unroll
                    for (int q = 0; q < 2; q++) {
                        float4 v = pre[q];
                        float4 h4, l4;
                        h4.x = tf32_rna(v.x); l4.x = tf32_rna(v.x - h4.x);
                        h4.y = tf32_rna(v.y); l4.y = tf32_rna(v.y - h4.y);
                        h4.z = tf32_rna(v.z); l4.z = tf32_rna(v.z - h4.z);
                        h4.w = tf32_rna(v.w); l4.w = tf32_rna(v.w - h4.w);
                        *(float4*)&dh[hso + q * 4] = h4;
                        *(float4*)&dl[hso + q * 4] = l4;
                    }
                }
                __syncthreads();
            }

            // gates to gsm (aliases h buffers; all mma complete)
#pragma unroll
            for (int mt = 0; mt < 2; mt++) {
                int r0 = wm * 32 + mt * 16 + g;
#pragma unroll
                for (int nt = 0; nt < 4; nt++) {
                    int col = wn * 32 + nt * 8 + 2 * tig;
                    *(float2*)&gsm[r0 * 132 + col] =
                        make_float2(acc[mt][nt][0], acc[mt][nt][1]);
                    *(float2*)&gsm[(r0 + 8) * 132 + col] =
                        make_float2(acc[mt][nt][2], acc[mt][nt][3]);
                }
            }
            __syncthreads();
        }

        // ---- fused LSTM epilogue: 128 p x 32 j, 512 threads ----
        float* hOut = g_hbuf[(s + 1) & 1] + (size_t)dir * BN * 128;
        size_t xbase = (size_t)t * BN * 512;
#pragma unroll
        for (int i = 0; i < 8; i++) {
            int pj = tid + i * 512;
            int pp = pj >> 5, jj = pj & 31;
            int p = p0 + pp;
            int j = j0 + jj;
            const float* xr = xp + xbase + (size_t)p * 512 + j;
            float gi = xr[0], gf = xr[128], gg2 = xr[256], go = xr[384];
            if (s > 0) {
                gi  += gsm[pp * 132 + jj];
                gf  += gsm[pp * 132 + 32 + jj];
                gg2 += gsm[pp * 132 + 64 + jj];
                go  += gsm[pp * 132 + 96 + jj];
            }
            size_t hidx = (size_t)p * 128 + j;
            float cold = (s == 0) ? 0.0f : cD[hidx];
            float cn = sigf(gf) * cold + sigf(gi) * tanhfast(gg2);
            float hn = sigf(go) * tanhfast(cn);
            if (s == TSEQ - 1) {
                float hs = hsD[hidx] + hn;
                g_sentpres[(size_t)p * 256 + dir * 128 + j] =
                    tanhfast(hs * (1.0f / 50.0f));
            } else {
                cD[hidx] = cn;
                hOut[hidx] = hn;
                hsD[hidx] = (s == 0) ? hn : (hsD[hidx] + hn);
            }
        }

        if (s < TSEQ - 1) {
            __syncthreads();
            if (tid == 0) {
                __threadfence();
                atomicAdd(&g_sbar[barIdx], 1);
                int target = 4 * (s + 1);
                while (*(volatile int*)&g_sbar[barIdx] < target) { }
                __threadfence();
            }
            __syncthreads();
        }
    }

    __syncthreads();
    if (tid == 0) {
        int old = atomicAdd(&g_sdone[barIdx], 1);
        if (old == 3) {
            g_sbar[barIdx] = 0;
            __threadfence();
            g_sdone[barIdx] = 0;
        }
    }
}

// ============================================================
// Dual-half GEMM with f32x2 (modes 1-4, unchanged)
// ============================================================
template <int MODE>
__global__ void __launch_bounds__(256) gemm_dual(
    const float* __restrict__ Aparam, int M, int K, int NB,
    const float* __restrict__ B0, const float* __restrict__ B1,
    const float* __restrict__ bias0, const float* __restrict__ bias1,
    float* __restrict__ outParam)
{
    __shared__ __align__(16) u64 As2[8][128];
    __shared__ __align__(16) float Bs[8][128];

    const float* A;
    if (MODE == 1 || MODE == 2) A = g_sentpres;
    else if (MODE == 3) A = g_tag_out;
    else A = g_agg;
    (void)Aparam;

    int hsel = (blockIdx.y * 128) / NB;
    int g0 = blockIdx.y * 128 - hsel * NB;
    int m0 = blockIdx.x * 128;

    const float* B = hsel ? B1 : B0;
    const float* bias = hsel ? bias1 : bias0;

    float* out;
    if (MODE == 1) out = hsel ? g_txp1 : g_txp0;
    else if (MODE == 2 || MODE == 3) out = hsel ? g_k : g_q;
    else out = outParam;

    int tid = threadIdx.x;
    int tx = tid & 15;
    int ty = tid >> 4;
    int lr = tid >> 1;
    int lc4 = tid & 1;

    u64 acc2[8][4];
#pragma unroll
    for (int i = 0; i < 8; i++)
#pragma unroll
        for (int j = 0; j < 4; j++) acc2[i][j] = 0ULL;

    int KT = K / 8;
    const float* aPtr = A + (size_t)(m0 + lr) * K + lc4 * 4;
    const float* bPtr = B + (size_t)(g0 + lr) * K + lc4 * 4;
    float4 av = *(const float4*)(aPtr);
    float4 bv = *(const float4*)(bPtr);

    for (int kt = 0; kt < KT; kt++) {
        As2[lc4 * 4 + 0][lr] = pk2(av.x, av.x);
        As2[lc4 * 4 + 1][lr] = pk2(av.y, av.y);
        As2[lc4 * 4 + 2][lr] = pk2(av.z, av.z);
        As2[lc4 * 4 + 3][lr] = pk2(av.w, av.w);
        Bs[lc4 * 4 + 0][lr] = bv.x; Bs[lc4 * 4 + 1][lr] = bv.y;
        Bs[lc4 * 4 + 2][lr] = bv.z; Bs[lc4 * 4 + 3][lr] = bv.w;
        __syncthreads();
        if (kt + 1 < KT) {
            av = *(const float4*)(aPtr + (kt + 1) * 8);
            bv = *(const float4*)(bPtr + (kt + 1) * 8);
        }
#pragma unroll
        for (int kk = 0; kk < 8; kk++) {
            u64 b2[4];
#pragma unroll
            for (int jq = 0; jq < 4; jq++)
                b2[jq] = *(const u64*)&Bs[kk][2 * (tx + 16 * jq)];
            u64 a2[8];
#pragma unroll
            for (int i = 0; i < 8; i++) a2[i] = As2[kk][ty * 8 + i];
#pragma unroll
            for (int i = 0; i < 8; i++)
#pragma unroll
                for (int jq = 0; jq < 4; jq++)
                    fma2(acc2[i][jq], a2[i], b2[jq]);
        }
        __syncthreads();
    }

#pragma unroll
    for (int i = 0; i < 8; i++) {
        int m = m0 + ty * 8 + i;
        size_t rowbase;
        if (MODE == 1) {
            int b = m >> 6; int n = m & 63;
            rowbase = ((size_t)n * BB + b) * 512;
        } else {
            rowbase = (size_t)m * 256;
        }
#pragma unroll
        for (int jq = 0; jq < 4; jq++) {
            int g = g0 + 2 * (tx + 16 * jq);
            float lo, hi;
            up2(acc2[i][jq], lo, hi);
            float2 bb = *(const float2*)(bias + g);
            float2 o;
            o.x = lo + bb.x;
            o.y = hi + bb.y;
            if (MODE == 4) { o.x = fmaxf(o.x, 0.f); o.y = fmaxf(o.y, 0.f); }
            *(float2*)(out + rowbase + g) = o;
        }
    }
}

// ============================================================
// Persistent tag BiLSTM v3: TENSOR CORES (3xTF32). (unchanged)
// ============================================================
#define TG2_WST  132
#define TG2_HST  132
#define TG2_WSZ  (64 * TG2_WST)
#define TG2_HSZ  (32 * TG2_HST)
#define TG2_SMEM ((2 * TG2_WSZ + 2 * TG2_HSZ + 32 * 68) * 4)

__global__ void __launch_bounds__(256) tag_persistent_tc(
    const float* __restrict__ W0, const float* __restrict__ W1)
{
    extern __shared__ __align__(16) float tg2[];
    float* sWh = tg2;
    float* sWl = tg2 + TG2_WSZ;
    float* sHh = tg2 + 2 * TG2_WSZ;
    float* sHl = sHh + TG2_HSZ;
    float* gsm = sHl + TG2_HSZ;

    int dir = blockIdx.x >> 3;
    int jc = blockIdx.x & 7;
    int j0 = jc * 16;
    const float* W = dir ? W1 : W0;
    const float* xp = dir ? g_txp1 : g_txp0;

    int tid = threadIdx.x;
    int lane = tid & 31, warp = tid >> 5;
    int g = lane >> 2, tig = lane & 3;

    {
        int row = tid >> 2;
        int gg = row >> 4, jr = row & 15;
        int kq = (tid & 3) * 32;
        const float* wrow = W + (size_t)(gg * 128 + j0 + jr) * 128 + kq;
        int so = row * TG2_WST + kq;
#pragma unroll
        for (int q = 0; q < 8; q++) {
            float4 v = *(const float4*)(wrow + q * 4);
            float4 h4, l4;
            h4.x = tf32_rna(v.x); l4.x = tf32_rna(v.x - h4.x);
            h4.y = tf32_rna(v.y); l4.y = tf32_rna(v.y - h4.y);
            h4.z = tf32_rna(v.z); l4.z = tf32_rna(v.z - h4.z);
            h4.w = tf32_rna(v.w); l4.w = tf32_rna(v.w - h4.w);
            *(float4*)&sWh[so + q * 4] = h4;
            *(float4*)&sWl[so + q * 4] = l4;
        }
    }
    __syncthreads();

    float creg[2] = {0.f, 0.f};
    int* bar = &g_tbar2[dir * 32];

    for (int s = 0; s < NSEQ; s++) {
        int t = dir ? (NSEQ - 1 - s) : s;

        if (s > 0) {
            const float* hIn = g_thbuf[s & 1] + (size_t)dir * BB * 128;
            {
                int row = tid >> 3;
                int kq = (tid & 7) * 16;
                const float* hrow = hIn + (size_t)row * 128 + kq;
                int so = row * TG2_HST + kq;
#pragma unroll
                for (int q = 0; q < 4; q++) {
                    float4 v = *(const float4*)(hrow + q * 4);
                    float4 h4, l4;
                    h4.x = tf32_rna(v.x); l4.x = tf32_rna(v.x - h4.x);
                    h4.y = tf32_rna(v.y); l4.y = tf32_rna(v.y - h4.y);
                    h4.z = tf32_rna(v.z); l4.z = tf32_rna(v.z - h4.z);
                    h4.w = tf32_rna(v.w); l4.w = tf32_rna(v.w - h4.w);
                    *(float4*)&sHh[so + q * 4] = h4;
                    *(float4*)&sHl[so + q * 4] = l4;
                }
            }
            __syncthreads();

            float acc[2][4];
#pragma unroll
            for (int mt = 0; mt < 2; mt++)
#pragma unroll
                for (int c = 0; c < 4; c++) acc[mt][c] = 0.0f;

#pragma unroll
            for (int kt = 0; kt < 16; kt++) {
                int kb = kt * 8;
                int br = (warp * 8 + g) * TG2_WST + kb;
                u32 bh[2], bl[2];
                bh[0] = __float_as_uint(sWh[br + tig]);
                bh[1] = __float_as_uint(sWh[br + tig + 4]);
                bl[0] = __float_as_uint(sWl[br + tig]);
                bl[1] = __float_as_uint(sWl[br + tig + 4]);
#pragma unroll
                for (int mt = 0; mt < 2; mt++) {
                    int ar0 = (mt * 16 + g) * TG2_HST + kb;
                    int ar1 = ar0 + 8 * TG2_HST;
                    u32 ah[4], al[4];
                    ah[0] = __float_as_uint(sHh[ar0 + tig]);
                    ah[1] = __float_as_uint(sHh[ar1 + tig]);
                    ah[2] = __float_as_uint(sHh[ar0 + tig + 4]);
                    ah[3] = __float_as_uint(sHh[ar1 + tig + 4]);
                    al[0] = __float_as_uint(sHl[ar0 + tig]);
                    al[1] = __float_as_uint(sHl[ar1 + tig]);
                    al[2] = __float_as_uint(sHl[ar0 + tig + 4]);
                    al[3] = __float_as_uint(sHl[ar1 + tig + 4]);
                    mma_tf32(acc[mt], ah, bh);
                    mma_tf32(acc[mt], al, bh);
                    mma_tf32(acc[mt], ah, bl);
                }
            }

#pragma unroll
            for (int mt = 0; mt < 2; mt++) {
                int r0 = mt * 16 + g;
                int col = warp * 8 + 2 * tig;
                *(float2*)&gsm[r0 * 68 + col] = make_float2(acc[mt][0], acc[mt][1]);
                *(float2*)&gsm[(r0 + 8) * 68 + col] = make_float2(acc[mt][2], acc[mt][3]);
            }
            __syncthreads();
        }

        float* hOut = g_thbuf[(s + 1) & 1] + (size_t)dir * BB * 128;
#pragma unroll
        for (int u = 0; u < 2; u++) {
            int idx = tid + u * 256;
            int b = idx >> 4, jj = idx & 15;
            const float* xr = xp + ((size_t)t * BB + b) * 512 + j0 + jj;
            float gi = xr[0], gf = xr[128], gg2 = xr[256], go = xr[384];
            if (s > 0) {
                gi  += gsm[b * 68 + jj];
                gf  += gsm[b * 68 + 16 + jj];
                gg2 += gsm[b * 68 + 32 + jj];
                go  += gsm[b * 68 + 48 + jj];
            }
            float cn = sigf(gf) * creg[u] + sigf(gi) * tanhfast(gg2);
            float hn = sigf(go) * tanhfast(cn);
            creg[u] = cn;
            hOut[(size_t)b * 128 + j0 + jj] = hn;
            g_tag_out[((size_t)b * NSEQ + t) * 256 + dir * 128 + j0 + jj] = tanhfast(hn);
        }

        if (s < NSEQ - 1) {
            __syncthreads();
            if (tid == 0) {
                __threadfence();
                atomicAdd(bar, 1);
                int target = 8 * (s + 1);
                while (*(volatile int*)bar < target) { }
                __threadfence();
            }
            __syncthreads();
        }
    }

    __syncthreads();
    if (tid == 0) {
        int old = atomicAdd(&g_tdone2[dir * 32], 1);
        if (old == 7) {
            g_tbar2[dir * 32] = 0;
            __threadfence();
            g_tdone2[dir * 32] = 0;
        }
    }
}

// ---------------- SPP ----------------
__global__ void __launch_bounds__(256) spp_kernel(int which) {
    int b = blockIdx.x;
    int tid = threadIdx.x;
    __shared__ float qs[64][33];
    __shared__ float ks[64][33];
    __shared__ float segs[64][8];

    float acc[16];
#pragma unroll
    for (int i = 0; i < 16; i++) acc[i] = 0.0f;
    int n = tid >> 2;
    int mBase = (tid & 3) * 16;

    for (int d0 = 0; d0 < 256; d0 += 32) {
        __syncthreads();
        for (int idx = tid; idx < 64 * 32; idx += 256) {
            int r = idx >> 5, cc = idx & 31;
            size_t gi = ((size_t)(b * 64 + r)) * 256 + d0 + cc;
            qs[r][cc] = g_q[gi];
            ks[r][cc] = g_k[gi];
        }
        __syncthreads();
#pragma unroll 4
        for (int dd = 0; dd < 32; dd++) {
            float qv = qs[n][dd];
#pragma unroll
            for (int mm = 0; mm < 16; mm++)
                acc[mm] += qv * ks[mBase + mm][dd];
        }
    }
    float s8a = -3.4e38f, s8b = -3.4e38f;
#pragma unroll
    for (int mm = 0; mm < 8; mm++)  s8a = fmaxf(s8a, acc[mm]);
#pragma unroll
    for (int mm = 8; mm < 16; mm++) s8b = fmaxf(s8b, acc[mm]);
    segs[n][(tid & 3) * 2 + 0] = s8a * 0.0625f;
    segs[n][(tid & 3) * 2 + 1] = s8b * 0.0625f;
    __syncthreads();

    if (tid < 64) {
        float e[8];
#pragma unroll
        for (int i = 0; i < 8; i++) e[i] = segs[tid][i];
        float q4[4], h2[2];
#pragma unroll
        for (int i = 0; i < 4; i++) q4[i] = fmaxf(e[2 * i], e[2 * i + 1]);
        h2[0] = fmaxf(q4[0], q4[1]);
        h2[1] = fmaxf(q4[2], q4[3]);
        float a1 = fmaxf(h2[0], h2[1]);
        float* o = (which ? g_roleFt : g_sentFt) + (size_t)(b * 64 + tid) * 15;
        o[0] = a1;
        o[1] = h2[0]; o[2] = h2[1];
#pragma unroll
        for (int i = 0; i < 4; i++) o[3 + i] = q4[i];
#pragma unroll
        for (int i = 0; i < 8; i++) o[7 + i] = e[i];
    }
}

// ---------------- GCN pre ----------------
__global__ void __launch_bounds__(256) gcn_pre() {
    int b = blockIdx.x;
    int tid = threadIdx.x;
    __shared__ float cosm[64][65];
    __shared__ float xs[64][33];
    __shared__ float inv[64];

    if (tid < 64) {
        const float* xr = g_tag_out + (size_t)(b * 64 + tid) * 256;
        float s = 0.0f;
        for (int d = 0; d < 256; d++) { float v = xr[d]; s += v * v; }
        inv[tid] = 1.0f / (sqrtf(s) + 1e-8f);
    }

    float acc[16];
#pragma unroll
    for (int i = 0; i < 16; i++) acc[i] = 0.0f;
    int n = tid >> 2;
    int mBase = (tid & 3) * 16;

    for (int d0 = 0; d0 < 256; d0 += 32) {
        __syncthreads();
        for (int idx = tid; idx < 64 * 32; idx += 256) {
            int r = idx >> 5, cc = idx & 31;
            xs[r][cc] = g_tag_out[((size_t)(b * 64 + r)) * 256 + d0 + cc];
        }
        __syncthreads();
#pragma unroll 4
        for (int dd = 0; dd < 32; dd++) {
            float xv = xs[n][dd];
#pragma unroll
            for (int mm = 0; mm < 16; mm++)
                acc[mm] += xv * xs[mBase + mm][dd];
        }
    }
#pragma unroll
    for (int mm = 0; mm < 16; mm++)
        cosm[n][mBase + mm] = acc[mm] * inv[n] * inv[mBase + mm];

    int ddBase = (tid & 3) * 8;
    for (int d0 = 0; d0 < 256; d0 += 32) {
        __syncthreads();
        for (int idx = tid; idx < 64 * 32; idx += 256) {
            int r = idx >> 5, cc = idx & 31;
            xs[r][cc] = g_tag_out[((size_t)(b * 64 + r)) * 256 + d0 + cc];
        }
        __syncthreads();
        float r8[8];
#pragma unroll
        for (int i = 0; i < 8; i++) r8[i] = 0.0f;
        for (int m = 0; m < 64; m++) {
            float cv = cosm[n][m];
#pragma unroll
            for (int i = 0; i < 8; i++) r8[i] += cv * xs[m][ddBase + i];
        }
#pragma unroll
        for (int i = 0; i < 8; i++) {
            float v = (r8[i] + 2.0f * xs[n][ddBase + i]) * (1.0f / 66.0f);
            g_agg[(size_t)(b * 64 + n) * 256 + d0 + ddBase + i] = v;
        }
    }
}

// ---------------- classifier + log_softmax ----------------
__global__ void __launch_bounds__(256) cls_kernel(
    const float* __restrict__ W, const float* __restrict__ bias,
    float* __restrict__ out)
{
    __shared__ float Wsh[8][288];
    __shared__ float bsh[8];
    __shared__ float ftile[256][33];

    int tid = threadIdx.x;
    for (int i = tid; i < 8 * 286; i += 256) Wsh[i / 286][i % 286] = W[i];
    if (tid < 8) bsh[tid] = bias[tid];
    __syncthreads();

    int p0 = blockIdx.x * 256;
    int p = p0 + tid;
    float z[8];
#pragma unroll
    for (int c = 0; c < 8; c++) z[c] = bsh[c];

    for (int d0 = 0; d0 < 256; d0 += 32) {
        __syncthreads();
        for (int idx = tid; idx < 256 * 32; idx += 256) {
            int r = idx >> 5, cc = idx & 31;
            ftile[r][cc] = g_tag_out[(size_t)(p0 + r) * 256 + d0 + cc];
        }
        __syncthreads();
#pragma unroll 4
        for (int dd = 0; dd < 32; dd++) {
            float f = ftile[tid][dd];
#pragma unroll
            for (int c = 0; c < 8; c++) z[c] += f * Wsh[c][d0 + dd];
        }
    }
#pragma unroll
    for (int d = 0; d < 15; d++) {
        float f = g_sentFt[(size_t)p * 15 + d];
#pragma unroll
        for (int c = 0; c < 8; c++) z[c] += f * Wsh[c][256 + d];
    }
#pragma unroll
    for (int d = 0; d < 15; d++) {
        float f = g_roleFt[(size_t)p * 15 + d];
#pragma unroll
        for (int c = 0; c < 8; c++) z[c] += f * Wsh[c][271 + d];
    }
    float m = z[0];
#pragma unroll
    for (int c = 1; c < 8; c++) m = fmaxf(m, z[c]);
    float se = 0.0f;
#pragma unroll
    for (int c = 0; c < 8; c++) se += expf(z[c] - m);
    float lse = m + logf(se);
#pragma unroll
    for (int c = 0; c < 8; c++) out[(size_t)p * 8 + c] = z[c] - lse;
}

// ============================================================
extern "C" void kernel_launch(void* const* d_in, const int* in_sizes, int n_in,
                              void* d_out, int out_size)
{
    (void)in_sizes; (void)n_in; (void)out_size;
    const float* documents = (const float*)d_in[0];
    const float* sw_ih_f = (const float*)d_in[1];
    const float* sw_hh_f = (const float*)d_in[2];
    const float* sb_f    = (const float*)d_in[3];
    const float* sw_ih_b = (const float*)d_in[4];
    const float* sw_hh_b = (const float*)d_in[5];
    const float* sb_b    = (const float*)d_in[6];
    const float* sf_Wq   = (const float*)d_in[7];
    const float* sf_bq   = (const float*)d_in[8];
    const float* sf_Wk   = (const float*)d_in[9];
    const float* sf_bk   = (const float*)d_in[10];
    const float* rf_Wq   = (const float*)d_in[11];
    const float* rf_bq   = (const float*)d_in[12];
    const float* rf_Wk   = (const float*)d_in[13];
    const float* rf_bk   = (const float*)d_in[14];
    const float* tw_ih_f = (const float*)d_in[15];
    const float* tw_hh_f = (const float*)d_in[16];
    const float* tb_f    = (const float*)d_in[17];
    const float* tw_ih_b = (const float*)d_in[18];
    const float* tw_hh_b = (const float*)d_in[19];
    const float* tb_b    = (const float*)d_in[20];
    const float* sage_W  = (const float*)d_in[21];
    const float* sage_b  = (const float*)d_in[22];
    const float* cls_W   = (const float*)d_in[23];
    const float* cls_b   = (const float*)d_in[24];
    float* out = (float*)d_out;

    cudaFuncSetAttribute(lstm_sent5, cudaFuncAttributeMaxDynamicSharedMemorySize, S5_SMEM);
    cudaFuncSetAttribute(tag_persistent_tc, cudaFuncAttributeMaxDynamicSharedMemorySize, TG2_SMEM);

    // 1) sentence BiLSTM input projection: tensor cores, 3xTF32
    gemm_inproj_tc<<<dim3(800, 8), 256>>>(documents, sw_ih_f, sw_ih_b, sb_f, sb_b);
    // 2) sentence recurrence: persistent tensor-core kernel, 512 threads
    lstm_sent5<<<128, 512, S5_SMEM>>>(sw_hh_f, sw_hh_b);
    // 3) tag BiLSTM input projection
    gemm_dual<1><<<dim3(16, 8), 256>>>(nullptr, 2048, 256, 512,
                                       tw_ih_f, tw_ih_b, tb_f, tb_b, nullptr);
    // 4) tag recurrence: persistent tensor-core kernel
    tag_persistent_tc<<<16, 256, TG2_SMEM>>>(tw_hh_f, tw_hh_b);
    // 5) SPP on sentpres -> sentFt
    gemm_dual<2><<<dim3(16, 4), 256>>>(nullptr, 2048, 256, 256,
                                       sf_Wq, sf_Wk, sf_bq, sf_bk, nullptr);
    spp_kernel<<<32, 256>>>(0);
    // 6) SPP on tag_out -> roleFt
    gemm_dual<3><<<dim3(16, 4), 256>>>(nullptr, 2048, 256, 256,
                                       rf_Wq, rf_Wk, rf_bq, rf_bk, nullptr);
    spp_kernel<<<32, 256>>>(1);
    // 7) GCN
    gcn_pre<<<32, 256>>>();
    gemm_dual<4><<<dim3(16, 2), 256>>>(nullptr, 2048, 256, 256,
                                       sage_W, sage_W, sage_b, sage_b, out + 16384);
    // 8) classifier + log_softmax
    cls_kernel<<<8, 256>>>(cls_W, cls_b, out);
}